// round 1
// baseline (speedup 1.0000x reference)
#include <cuda_runtime.h>
#include <math.h>

#define S_LEN 2048
#define HID   2048
#define NHEAD 16
#define HD    128
#define MROWS 4096          // B * S
#define SCALE 0.08838834764831845f   // 1/sqrt(128)

// ---------------------------------------------------------------------------
// Global scratch (device statics; no allocation in kernel_launch)
// ---------------------------------------------------------------------------
__device__ float g_Q[MROWS * HID];
__device__ float g_K[MROWS * HID];
__device__ float g_V[MROWS * HID];
__device__ float g_Ctx[MROWS * HID];

// ---------------------------------------------------------------------------
// SGEMM: C[M,N] = A[M,K] * B[N,K]^T   (both operands K-major => "NT" gemm)
// Block tile 128x128, K-tile 8, 256 threads, 8x8 per-thread microtile.
// M,N,K must be multiples of 128/128/8 (true here: 4096/2048/2048).
// ---------------------------------------------------------------------------
__global__ __launch_bounds__(256, 2)
void sgemm_nt(const float* __restrict__ A, const float* __restrict__ B,
              float* __restrict__ C, int M, int N, int K)
{
    __shared__ float As[8][128];
    __shared__ float Bs[8][128];

    const int tid = threadIdx.x;
    const int tx  = tid & 15;      // 0..15 -> N direction
    const int ty  = tid >> 4;      // 0..15 -> M direction
    const int lr  = tid >> 1;      // 0..127 row within tile for loading
    const int lc  = (tid & 1) << 2;// 0 or 4 (k offset for float4)

    const float* Ab = A + (size_t)blockIdx.y * 128 * K;
    const float* Bb = B + (size_t)blockIdx.x * 128 * K;

    float acc[8][8];
#pragma unroll
    for (int i = 0; i < 8; i++)
#pragma unroll
        for (int j = 0; j < 8; j++) acc[i][j] = 0.f;

    for (int k0 = 0; k0 < K; k0 += 8) {
        float4 av = *(const float4*)(Ab + (size_t)lr * K + k0 + lc);
        float4 bv = *(const float4*)(Bb + (size_t)lr * K + k0 + lc);
        __syncthreads();   // previous iteration's reads done
        As[lc + 0][lr] = av.x; As[lc + 1][lr] = av.y;
        As[lc + 2][lr] = av.z; As[lc + 3][lr] = av.w;
        Bs[lc + 0][lr] = bv.x; Bs[lc + 1][lr] = bv.y;
        Bs[lc + 2][lr] = bv.z; Bs[lc + 3][lr] = bv.w;
        __syncthreads();

#pragma unroll
        for (int kk = 0; kk < 8; kk++) {
            float a[8], b[8];
            *(float4*)&a[0] = *(const float4*)&As[kk][ty * 8];
            *(float4*)&a[4] = *(const float4*)&As[kk][ty * 8 + 4];
            *(float4*)&b[0] = *(const float4*)&Bs[kk][tx * 8];
            *(float4*)&b[4] = *(const float4*)&Bs[kk][tx * 8 + 4];
#pragma unroll
            for (int i = 0; i < 8; i++)
#pragma unroll
                for (int j = 0; j < 8; j++)
                    acc[i][j] += a[i] * b[j];
        }
    }

    float* Cb = C + (size_t)(blockIdx.y * 128 + ty * 8) * N + blockIdx.x * 128 + tx * 8;
#pragma unroll
    for (int i = 0; i < 8; i++) {
        float4 r0 = make_float4(acc[i][0], acc[i][1], acc[i][2], acc[i][3]);
        float4 r1 = make_float4(acc[i][4], acc[i][5], acc[i][6], acc[i][7]);
        *(float4*)(Cb + (size_t)i * N)     = r0;
        *(float4*)(Cb + (size_t)i * N + 4) = r1;
    }
}

// ---------------------------------------------------------------------------
// RoPE applied in-place to g_Q, g_K.
// grid = MROWS blocks, 256 threads. Each (b,s) row: 16 heads x 64 pairs.
// ---------------------------------------------------------------------------
__global__ void rope_kernel()
{
    const int row = blockIdx.x;           // b*S + s
    const int s   = row & (S_LEN - 1);
    for (int t = threadIdx.x; t < NHEAD * 64; t += 256) {
        const int h = t >> 6;
        const int i = t & 63;
        float inv = powf(10000.0f, -((float)(2 * i)) / 128.0f);
        float ang = (float)s * inv;
        float sn, cs;
        sincosf(ang, &sn, &cs);
        const int idx = row * HID + h * HD + i;
        float q1 = g_Q[idx], q2 = g_Q[idx + 64];
        g_Q[idx]      = q1 * cs - q2 * sn;
        g_Q[idx + 64] = q1 * sn + q2 * cs;
        float k1 = g_K[idx], k2 = g_K[idx + 64];
        g_K[idx]      = k1 * cs - k2 * sn;
        g_K[idx + 64] = k1 * sn + k2 * cs;
    }
}

// ---------------------------------------------------------------------------
// Flash attention, fp32, non-causal. Bq = Bk = 64, D = 128.
// grid = (S/64 = 32, B*NHEAD = 32), 256 threads, 117248 B dynamic smem.
// Smem layout (floats):
//   Qs   [64][129]  @ 0
//   Ks   [64][129]  @ 8256
//   Vs   [64][132]  @ 16512
//   Ss   [64][65]   @ 24960
//   rmax [64]       @ 29120
//   rsum [64]       @ 29184
//   alp  [64]       @ 29248       -> total 29312 floats
// ---------------------------------------------------------------------------
#define FLASH_SMEM (29312 * 4)

__global__ __launch_bounds__(256, 1)
void flash_kernel()
{
    extern __shared__ float sm[];
    float* Qs   = sm;
    float* Ks   = sm + 8256;
    float* Vs   = sm + 16512;
    float* Ss   = sm + 24960;
    float* rmax = sm + 29120;
    float* rsum = sm + 29184;
    float* alp  = sm + 29248;

    const int tid = threadIdx.x;
    const int tx  = tid & 15;
    const int ty  = tid >> 4;
    const int q0  = blockIdx.x * 64;
    const int b   = blockIdx.y >> 4;
    const int h   = blockIdx.y & 15;
    const int base = (b * S_LEN) * HID + h * HD;   // + s*HID + d

    // Load Q tile (stays resident)
    for (int idx = tid; idx < 64 * 128; idx += 256) {
        const int i = idx >> 7, d = idx & 127;
        Qs[i * 129 + d] = g_Q[base + (q0 + i) * HID + d];
    }
    if (tid < 64) { rmax[tid] = -1e30f; rsum[tid] = 0.f; }

    float o[4][8];
#pragma unroll
    for (int r = 0; r < 4; r++)
#pragma unroll
        for (int c = 0; c < 8; c++) o[r][c] = 0.f;

    for (int kt = 0; kt < S_LEN; kt += 64) {
        __syncthreads();   // previous tile's Ss/Vs consumers done
        for (int idx = tid; idx < 64 * 128; idx += 256) {
            const int i = idx >> 7, d = idx & 127;
            const int g = base + (kt + i) * HID + d;
            Ks[i * 129 + d] = g_K[g];
            Vs[i * 132 + d] = g_V[g];
        }
        __syncthreads();

        // S = Q K^T  (4x4 microtile per thread)
        float s[4][4];
#pragma unroll
        for (int r = 0; r < 4; r++)
#pragma unroll
            for (int c = 0; c < 4; c++) s[r][c] = 0.f;

        const float* qp = Qs + ty * 4 * 129;
        const float* kp = Ks + tx * 4 * 129;
#pragma unroll 4
        for (int d = 0; d < 128; d++) {
            const float a0 = qp[d], a1 = qp[129 + d], a2 = qp[258 + d], a3 = qp[387 + d];
            const float b0 = kp[d], b1 = kp[129 + d], b2 = kp[258 + d], b3 = kp[387 + d];
            s[0][0] += a0 * b0; s[0][1] += a0 * b1; s[0][2] += a0 * b2; s[0][3] += a0 * b3;
            s[1][0] += a1 * b0; s[1][1] += a1 * b1; s[1][2] += a1 * b2; s[1][3] += a1 * b3;
            s[2][0] += a2 * b0; s[2][1] += a2 * b1; s[2][2] += a2 * b2; s[2][3] += a2 * b3;
            s[3][0] += a3 * b0; s[3][1] += a3 * b1; s[3][2] += a3 * b2; s[3][3] += a3 * b3;
        }
#pragma unroll
        for (int r = 0; r < 4; r++)
#pragma unroll
            for (int c = 0; c < 4; c++)
                Ss[(ty * 4 + r) * 65 + tx * 4 + c] = s[r][c] * SCALE;
        __syncthreads();

        // Online softmax row update (one thread per row)
        if (tid < 64) {
            float* sr = Ss + tid * 65;
            float mold = rmax[tid];
            float mnew = mold;
#pragma unroll 8
            for (int j = 0; j < 64; j++) mnew = fmaxf(mnew, sr[j]);
            const float a = __expf(mold - mnew);
            float p = 0.f;
#pragma unroll 8
            for (int j = 0; j < 64; j++) {
                const float e = __expf(sr[j] - mnew);
                sr[j] = e;
                p += e;
            }
            rsum[tid] = rsum[tid] * a + p;
            rmax[tid] = mnew;
            alp[tid]  = a;
        }
        __syncthreads();

        // O = O*alpha + P V   (4x8 microtile per thread)
        float ar[4];
#pragma unroll
        for (int r = 0; r < 4; r++) ar[r] = alp[ty * 4 + r];
#pragma unroll
        for (int r = 0; r < 4; r++)
#pragma unroll
            for (int c = 0; c < 8; c++) o[r][c] *= ar[r];

        const float* pp = Ss + ty * 4 * 65;
#pragma unroll 2
        for (int kk = 0; kk < 64; kk++) {
            const float p0 = pp[kk], p1 = pp[65 + kk], p2 = pp[130 + kk], p3 = pp[195 + kk];
            const float4 v0 = *(const float4*)&Vs[kk * 132 + tx * 8];
            const float4 v1 = *(const float4*)&Vs[kk * 132 + tx * 8 + 4];
            o[0][0] += p0 * v0.x; o[0][1] += p0 * v0.y; o[0][2] += p0 * v0.z; o[0][3] += p0 * v0.w;
            o[0][4] += p0 * v1.x; o[0][5] += p0 * v1.y; o[0][6] += p0 * v1.z; o[0][7] += p0 * v1.w;
            o[1][0] += p1 * v0.x; o[1][1] += p1 * v0.y; o[1][2] += p1 * v0.z; o[1][3] += p1 * v0.w;
            o[1][4] += p1 * v1.x; o[1][5] += p1 * v1.y; o[1][6] += p1 * v1.z; o[1][7] += p1 * v1.w;
            o[2][0] += p2 * v0.x; o[2][1] += p2 * v0.y; o[2][2] += p2 * v0.z; o[2][3] += p2 * v0.w;
            o[2][4] += p2 * v1.x; o[2][5] += p2 * v1.y; o[2][6] += p2 * v1.z; o[2][7] += p2 * v1.w;
            o[3][0] += p3 * v0.x; o[3][1] += p3 * v0.y; o[3][2] += p3 * v0.z; o[3][3] += p3 * v0.w;
            o[3][4] += p3 * v1.x; o[3][5] += p3 * v1.y; o[3][6] += p3 * v1.z; o[3][7] += p3 * v1.w;
        }
    }
    __syncthreads();

    float inv[4];
#pragma unroll
    for (int r = 0; r < 4; r++) inv[r] = 1.0f / rsum[ty * 4 + r];
#pragma unroll
    for (int r = 0; r < 4; r++) {
        const int row = q0 + ty * 4 + r;
        float* op = g_Ctx + base + row * HID + tx * 8;
        float4 w0 = make_float4(o[r][0] * inv[r], o[r][1] * inv[r],
                                o[r][2] * inv[r], o[r][3] * inv[r]);
        float4 w1 = make_float4(o[r][4] * inv[r], o[r][5] * inv[r],
                                o[r][6] * inv[r], o[r][7] * inv[r]);
        *(float4*)op       = w0;
        *(float4*)(op + 4) = w1;
    }
}

// ---------------------------------------------------------------------------
// Launch
// ---------------------------------------------------------------------------
extern "C" void kernel_launch(void* const* d_in, const int* in_sizes, int n_in,
                              void* d_out, int out_size)
{
    const float* x  = (const float*)d_in[0];
    const float* Wq = (const float*)d_in[1];
    const float* Wk = (const float*)d_in[2];
    const float* Wv = (const float*)d_in[3];
    const float* Wo = (const float*)d_in[4];
    float* out = (float*)d_out;

    float *pQ, *pK, *pV, *pC;
    cudaGetSymbolAddress((void**)&pQ, g_Q);
    cudaGetSymbolAddress((void**)&pK, g_K);
    cudaGetSymbolAddress((void**)&pV, g_V);
    cudaGetSymbolAddress((void**)&pC, g_Ctx);

    dim3 gg(HID / 128, MROWS / 128);   // (16, 32)

    sgemm_nt<<<gg, 256>>>(x, Wq, pQ, MROWS, HID, HID);
    sgemm_nt<<<gg, 256>>>(x, Wk, pK, MROWS, HID, HID);
    sgemm_nt<<<gg, 256>>>(x, Wv, pV, MROWS, HID, HID);

    rope_kernel<<<MROWS, 256>>>();

    cudaFuncSetAttribute(flash_kernel,
                         cudaFuncAttributeMaxDynamicSharedMemorySize, FLASH_SMEM);
    flash_kernel<<<dim3(S_LEN / 64, 2 * NHEAD), 256, FLASH_SMEM>>>();

    sgemm_nt<<<gg, 256>>>(pC, Wo, out, MROWS, HID, HID);
}

// round 2
// speedup vs baseline: 1.4851x; 1.4851x over previous
#include <cuda_runtime.h>
#include <math.h>

#define S_LEN 2048
#define HID   2048
#define NHEAD 16
#define HD    128
#define MROWS 4096          // B * S
#define SCALE 0.08838834764831845f   // 1/sqrt(128)

// ---------------------------------------------------------------------------
// Global scratch (device statics; no allocation in kernel_launch)
// ---------------------------------------------------------------------------
__device__ float g_Q[MROWS * HID];
__device__ float g_K[MROWS * HID];
__device__ float g_V[MROWS * HID];
__device__ float g_Ctx[MROWS * HID];

// ---------------------------------------------------------------------------
// TF32 tensor-core GEMM: C[M,N] = A[M,K] * B[N,K]^T  (both K-major, "NT")
// CTA tile 128x128, K-tile 16, 256 threads (8 warps), warp tile 64x32.
// mma.sync.m16n8k8 tf32. M%128==0, N%128==0, K%16==0.
// ---------------------------------------------------------------------------
__device__ __forceinline__ uint4 cvt4_tf32(float4 v)
{
    uint4 r;
    asm("cvt.rna.tf32.f32 %0, %1;" : "=r"(r.x) : "f"(v.x));
    asm("cvt.rna.tf32.f32 %0, %1;" : "=r"(r.y) : "f"(v.y));
    asm("cvt.rna.tf32.f32 %0, %1;" : "=r"(r.z) : "f"(v.z));
    asm("cvt.rna.tf32.f32 %0, %1;" : "=r"(r.w) : "f"(v.w));
    return r;
}

__device__ __forceinline__ void mma_tf32(float* c, const unsigned* a, const unsigned* b)
{
    asm volatile(
        "mma.sync.aligned.m16n8k8.row.col.f32.tf32.tf32.f32 "
        "{%0,%1,%2,%3}, {%4,%5,%6,%7}, {%8,%9}, {%0,%1,%2,%3};\n"
        : "+f"(c[0]), "+f"(c[1]), "+f"(c[2]), "+f"(c[3])
        : "r"(a[0]), "r"(a[1]), "r"(a[2]), "r"(a[3]),
          "r"(b[0]), "r"(b[1]));
}

#define SMS 20   // smem row stride (16 k + 4 pad) -> conflict-free fragment LDS

__global__ __launch_bounds__(256, 2)
void gemm_tf32_nt(const float* __restrict__ A, const float* __restrict__ B,
                  float* __restrict__ C, int M, int N, int K)
{
    __shared__ unsigned As[128][SMS];
    __shared__ unsigned Bs[128][SMS];

    const int tid  = threadIdx.x;
    const int lane = tid & 31;
    const int warp = tid >> 5;
    const int g    = lane >> 2;      // 0..7
    const int t    = lane & 3;       // 0..3
    const int wm   = (warp & 1) * 64;   // M offset of warp tile
    const int wn   = (warp >> 1) * 32;  // N offset of warp tile

    const int lr = tid >> 2;          // 0..63 (load row)
    const int lk = (tid & 3) * 4;     // 0,4,8,12 (load k quad)

    const float* Ab = A + (size_t)(blockIdx.y * 128 + lr) * K + lk;
    const float* Bb = B + (size_t)(blockIdx.x * 128 + lr) * K + lk;
    const size_t strdA = (size_t)64 * K;

    float c[4][4][4];
#pragma unroll
    for (int i = 0; i < 4; i++)
#pragma unroll
        for (int j = 0; j < 4; j++)
#pragma unroll
            for (int q = 0; q < 4; q++) c[i][j][q] = 0.f;

    float4 a0v = *(const float4*)(Ab);
    float4 a1v = *(const float4*)(Ab + strdA);
    float4 b0v = *(const float4*)(Bb);
    float4 b1v = *(const float4*)(Bb + strdA);

    for (int k0 = 0; k0 < K; k0 += 16) {
        __syncthreads();
        *(uint4*)&As[lr     ][lk] = cvt4_tf32(a0v);
        *(uint4*)&As[lr + 64][lk] = cvt4_tf32(a1v);
        *(uint4*)&Bs[lr     ][lk] = cvt4_tf32(b0v);
        *(uint4*)&Bs[lr + 64][lk] = cvt4_tf32(b1v);
        __syncthreads();

        if (k0 + 16 < K) {                       // prefetch next stage
            a0v = *(const float4*)(Ab + k0 + 16);
            a1v = *(const float4*)(Ab + k0 + 16 + strdA);
            b0v = *(const float4*)(Bb + k0 + 16);
            b1v = *(const float4*)(Bb + k0 + 16 + strdA);
        }

#pragma unroll
        for (int sub = 0; sub < 2; sub++) {
            const int ks = sub * 8 + t;
            unsigned af[4][4], bf[4][2];
#pragma unroll
            for (int mt = 0; mt < 4; mt++) {
                const int m = wm + mt * 16 + g;
                af[mt][0] = As[m    ][ks];
                af[mt][1] = As[m + 8][ks];
                af[mt][2] = As[m    ][ks + 4];
                af[mt][3] = As[m + 8][ks + 4];
            }
#pragma unroll
            for (int nt = 0; nt < 4; nt++) {
                const int n = wn + nt * 8 + g;
                bf[nt][0] = Bs[n][ks];
                bf[nt][1] = Bs[n][ks + 4];
            }
#pragma unroll
            for (int mt = 0; mt < 4; mt++)
#pragma unroll
                for (int nt = 0; nt < 4; nt++)
                    mma_tf32(c[mt][nt], af[mt], bf[nt]);
        }
    }

    // Epilogue: c0,c1 at (row, col..col+1), c2,c3 at (row+8, col..col+1)
#pragma unroll
    for (int mt = 0; mt < 4; mt++) {
        const size_t row = (size_t)blockIdx.y * 128 + wm + mt * 16 + g;
#pragma unroll
        for (int nt = 0; nt < 4; nt++) {
            const size_t col = (size_t)blockIdx.x * 128 + wn + nt * 8 + 2 * t;
            float2 lo = make_float2(c[mt][nt][0], c[mt][nt][1]);
            float2 hi = make_float2(c[mt][nt][2], c[mt][nt][3]);
            *(float2*)(C + row * N + col)       = lo;
            *(float2*)(C + (row + 8) * N + col) = hi;
        }
    }
}

// ---------------------------------------------------------------------------
// RoPE applied in-place to g_Q, g_K.
// ---------------------------------------------------------------------------
__global__ void rope_kernel()
{
    const int row = blockIdx.x;           // b*S + s
    const int s   = row & (S_LEN - 1);
    for (int t = threadIdx.x; t < NHEAD * 64; t += 256) {
        const int h = t >> 6;
        const int i = t & 63;
        float inv = powf(10000.0f, -((float)(2 * i)) / 128.0f);
        float ang = (float)s * inv;
        float sn, cs;
        sincosf(ang, &sn, &cs);
        const int idx = row * HID + h * HD + i;
        float q1 = g_Q[idx], q2 = g_Q[idx + 64];
        g_Q[idx]      = q1 * cs - q2 * sn;
        g_Q[idx + 64] = q1 * sn + q2 * cs;
        float k1 = g_K[idx], k2 = g_K[idx + 64];
        g_K[idx]      = k1 * cs - k2 * sn;
        g_K[idx + 64] = k1 * sn + k2 * cs;
    }
}

// ---------------------------------------------------------------------------
// Flash attention, fp32, non-causal. Bq = Bk = 64, D = 128. (unchanged)
// ---------------------------------------------------------------------------
#define FLASH_SMEM (29312 * 4)

__global__ __launch_bounds__(256, 1)
void flash_kernel()
{
    extern __shared__ float sm[];
    float* Qs   = sm;
    float* Ks   = sm + 8256;
    float* Vs   = sm + 16512;
    float* Ss   = sm + 24960;
    float* rmax = sm + 29120;
    float* rsum = sm + 29184;
    float* alp  = sm + 29248;

    const int tid = threadIdx.x;
    const int tx  = tid & 15;
    const int ty  = tid >> 4;
    const int q0  = blockIdx.x * 64;
    const int b   = blockIdx.y >> 4;
    const int h   = blockIdx.y & 15;
    const int base = (b * S_LEN) * HID + h * HD;

    for (int idx = tid; idx < 64 * 128; idx += 256) {
        const int i = idx >> 7, d = idx & 127;
        Qs[i * 129 + d] = g_Q[base + (q0 + i) * HID + d];
    }
    if (tid < 64) { rmax[tid] = -1e30f; rsum[tid] = 0.f; }

    float o[4][8];
#pragma unroll
    for (int r = 0; r < 4; r++)
#pragma unroll
        for (int c = 0; c < 8; c++) o[r][c] = 0.f;

    for (int kt = 0; kt < S_LEN; kt += 64) {
        __syncthreads();
        for (int idx = tid; idx < 64 * 128; idx += 256) {
            const int i = idx >> 7, d = idx & 127;
            const int g = base + (kt + i) * HID + d;
            Ks[i * 129 + d] = g_K[g];
            Vs[i * 132 + d] = g_V[g];
        }
        __syncthreads();

        float s[4][4];
#pragma unroll
        for (int r = 0; r < 4; r++)
#pragma unroll
            for (int c = 0; c < 4; c++) s[r][c] = 0.f;

        const float* qp = Qs + ty * 4 * 129;
        const float* kp = Ks + tx * 4 * 129;
#pragma unroll 4
        for (int d = 0; d < 128; d++) {
            const float a0 = qp[d], a1 = qp[129 + d], a2 = qp[258 + d], a3 = qp[387 + d];
            const float b0 = kp[d], b1 = kp[129 + d], b2 = kp[258 + d], b3 = kp[387 + d];
            s[0][0] += a0 * b0; s[0][1] += a0 * b1; s[0][2] += a0 * b2; s[0][3] += a0 * b3;
            s[1][0] += a1 * b0; s[1][1] += a1 * b1; s[1][2] += a1 * b2; s[1][3] += a1 * b3;
            s[2][0] += a2 * b0; s[2][1] += a2 * b1; s[2][2] += a2 * b2; s[2][3] += a2 * b3;
            s[3][0] += a3 * b0; s[3][1] += a3 * b1; s[3][2] += a3 * b2; s[3][3] += a3 * b3;
        }
#pragma unroll
        for (int r = 0; r < 4; r++)
#pragma unroll
            for (int c = 0; c < 4; c++)
                Ss[(ty * 4 + r) * 65 + tx * 4 + c] = s[r][c] * SCALE;
        __syncthreads();

        if (tid < 64) {
            float* sr = Ss + tid * 65;
            float mold = rmax[tid];
            float mnew = mold;
#pragma unroll 8
            for (int j = 0; j < 64; j++) mnew = fmaxf(mnew, sr[j]);
            const float a = __expf(mold - mnew);
            float p = 0.f;
#pragma unroll 8
            for (int j = 0; j < 64; j++) {
                const float e = __expf(sr[j] - mnew);
                sr[j] = e;
                p += e;
            }
            rsum[tid] = rsum[tid] * a + p;
            rmax[tid] = mnew;
            alp[tid]  = a;
        }
        __syncthreads();

        float ar[4];
#pragma unroll
        for (int r = 0; r < 4; r++) ar[r] = alp[ty * 4 + r];
#pragma unroll
        for (int r = 0; r < 4; r++)
#pragma unroll
            for (int c = 0; c < 8; c++) o[r][c] *= ar[r];

        const float* pp = Ss + ty * 4 * 65;
#pragma unroll 2
        for (int kk = 0; kk < 64; kk++) {
            const float p0 = pp[kk], p1 = pp[65 + kk], p2 = pp[130 + kk], p3 = pp[195 + kk];
            const float4 v0 = *(const float4*)&Vs[kk * 132 + tx * 8];
            const float4 v1 = *(const float4*)&Vs[kk * 132 + tx * 8 + 4];
            o[0][0] += p0 * v0.x; o[0][1] += p0 * v0.y; o[0][2] += p0 * v0.z; o[0][3] += p0 * v0.w;
            o[0][4] += p0 * v1.x; o[0][5] += p0 * v1.y; o[0][6] += p0 * v1.z; o[0][7] += p0 * v1.w;
            o[1][0] += p1 * v0.x; o[1][1] += p1 * v0.y; o[1][2] += p1 * v0.z; o[1][3] += p1 * v0.w;
            o[1][4] += p1 * v1.x; o[1][5] += p1 * v1.y; o[1][6] += p1 * v1.z; o[1][7] += p1 * v1.w;
            o[2][0] += p2 * v0.x; o[2][1] += p2 * v0.y; o[2][2] += p2 * v0.z; o[2][3] += p2 * v0.w;
            o[2][4] += p2 * v1.x; o[2][5] += p2 * v1.y; o[2][6] += p2 * v1.z; o[2][7] += p2 * v1.w;
            o[3][0] += p3 * v0.x; o[3][1] += p3 * v0.y; o[3][2] += p3 * v0.z; o[3][3] += p3 * v0.w;
            o[3][4] += p3 * v1.x; o[3][5] += p3 * v1.y; o[3][6] += p3 * v1.z; o[3][7] += p3 * v1.w;
        }
    }
    __syncthreads();

    float inv[4];
#pragma unroll
    for (int r = 0; r < 4; r++) inv[r] = 1.0f / rsum[ty * 4 + r];
#pragma unroll
    for (int r = 0; r < 4; r++) {
        const int row = q0 + ty * 4 + r;
        float* op = g_Ctx + base + row * HID + tx * 8;
        float4 w0 = make_float4(o[r][0] * inv[r], o[r][1] * inv[r],
                                o[r][2] * inv[r], o[r][3] * inv[r]);
        float4 w1 = make_float4(o[r][4] * inv[r], o[r][5] * inv[r],
                                o[r][6] * inv[r], o[r][7] * inv[r]);
        *(float4*)op       = w0;
        *(float4*)(op + 4) = w1;
    }
}

// ---------------------------------------------------------------------------
// Launch
// ---------------------------------------------------------------------------
extern "C" void kernel_launch(void* const* d_in, const int* in_sizes, int n_in,
                              void* d_out, int out_size)
{
    const float* x  = (const float*)d_in[0];
    const float* Wq = (const float*)d_in[1];
    const float* Wk = (const float*)d_in[2];
    const float* Wv = (const float*)d_in[3];
    const float* Wo = (const float*)d_in[4];
    float* out = (float*)d_out;

    float *pQ, *pK, *pV, *pC;
    cudaGetSymbolAddress((void**)&pQ, g_Q);
    cudaGetSymbolAddress((void**)&pK, g_K);
    cudaGetSymbolAddress((void**)&pV, g_V);
    cudaGetSymbolAddress((void**)&pC, g_Ctx);

    dim3 gg(HID / 128, MROWS / 128);   // (16, 32)

    gemm_tf32_nt<<<gg, 256>>>(x, Wq, pQ, MROWS, HID, HID);
    gemm_tf32_nt<<<gg, 256>>>(x, Wk, pK, MROWS, HID, HID);
    gemm_tf32_nt<<<gg, 256>>>(x, Wv, pV, MROWS, HID, HID);

    rope_kernel<<<MROWS, 256>>>();

    cudaFuncSetAttribute(flash_kernel,
                         cudaFuncAttributeMaxDynamicSharedMemorySize, FLASH_SMEM);
    flash_kernel<<<dim3(S_LEN / 64, 2 * NHEAD), 256, FLASH_SMEM>>>();

    gemm_tf32_nt<<<gg, 256>>>(pC, Wo, out, MROWS, HID, HID);
}

// round 3
// speedup vs baseline: 3.2876x; 2.2138x over previous
#include <cuda_runtime.h>
#include <math.h>

#define S_LEN 2048
#define HID   2048
#define NHEAD 16
#define HD    128
#define MROWS 4096          // B * S
#define SCALE 0.08838834764831845f   // 1/sqrt(128)

// ---------------------------------------------------------------------------
// Global scratch
// ---------------------------------------------------------------------------
__device__ float g_Q[MROWS * HID];
__device__ float g_K[MROWS * HID];
__device__ float g_V[MROWS * HID];
__device__ float g_Ctx[MROWS * HID];

// ---------------------------------------------------------------------------
// Shared helpers
// ---------------------------------------------------------------------------
__device__ __forceinline__ uint4 cvt4_tf32(float4 v)
{
    uint4 r;
    asm("cvt.rna.tf32.f32 %0, %1;" : "=r"(r.x) : "f"(v.x));
    asm("cvt.rna.tf32.f32 %0, %1;" : "=r"(r.y) : "f"(v.y));
    asm("cvt.rna.tf32.f32 %0, %1;" : "=r"(r.z) : "f"(v.z));
    asm("cvt.rna.tf32.f32 %0, %1;" : "=r"(r.w) : "f"(v.w));
    return r;
}

__device__ __forceinline__ unsigned cvt1_tf32(float v)
{
    unsigned r;
    asm("cvt.rna.tf32.f32 %0, %1;" : "=r"(r) : "f"(v));
    return r;
}

__device__ __forceinline__ void mma_tf32(float* c, const unsigned* a, const unsigned* b)
{
    asm volatile(
        "mma.sync.aligned.m16n8k8.row.col.f32.tf32.tf32.f32 "
        "{%0,%1,%2,%3}, {%4,%5,%6,%7}, {%8,%9}, {%0,%1,%2,%3};\n"
        : "+f"(c[0]), "+f"(c[1]), "+f"(c[2]), "+f"(c[3])
        : "r"(a[0]), "r"(a[1]), "r"(a[2]), "r"(a[3]),
          "r"(b[0]), "r"(b[1]));
}

// ---------------------------------------------------------------------------
// TF32 tensor-core GEMM: C[M,N] = A[M,K] * B[N,K]^T  (unchanged from R2)
// ---------------------------------------------------------------------------
#define SMS 20

__global__ __launch_bounds__(256, 2)
void gemm_tf32_nt(const float* __restrict__ A, const float* __restrict__ B,
                  float* __restrict__ C, int M, int N, int K)
{
    __shared__ unsigned As[128][SMS];
    __shared__ unsigned Bs[128][SMS];

    const int tid  = threadIdx.x;
    const int lane = tid & 31;
    const int warp = tid >> 5;
    const int g    = lane >> 2;
    const int t    = lane & 3;
    const int wm   = (warp & 1) * 64;
    const int wn   = (warp >> 1) * 32;

    const int lr = tid >> 2;
    const int lk = (tid & 3) * 4;

    const float* Ab = A + (size_t)(blockIdx.y * 128 + lr) * K + lk;
    const float* Bb = B + (size_t)(blockIdx.x * 128 + lr) * K + lk;
    const size_t strdA = (size_t)64 * K;

    float c[4][4][4];
#pragma unroll
    for (int i = 0; i < 4; i++)
#pragma unroll
        for (int j = 0; j < 4; j++)
#pragma unroll
            for (int q = 0; q < 4; q++) c[i][j][q] = 0.f;

    float4 a0v = *(const float4*)(Ab);
    float4 a1v = *(const float4*)(Ab + strdA);
    float4 b0v = *(const float4*)(Bb);
    float4 b1v = *(const float4*)(Bb + strdA);

    for (int k0 = 0; k0 < K; k0 += 16) {
        __syncthreads();
        *(uint4*)&As[lr     ][lk] = cvt4_tf32(a0v);
        *(uint4*)&As[lr + 64][lk] = cvt4_tf32(a1v);
        *(uint4*)&Bs[lr     ][lk] = cvt4_tf32(b0v);
        *(uint4*)&Bs[lr + 64][lk] = cvt4_tf32(b1v);
        __syncthreads();

        if (k0 + 16 < K) {
            a0v = *(const float4*)(Ab + k0 + 16);
            a1v = *(const float4*)(Ab + k0 + 16 + strdA);
            b0v = *(const float4*)(Bb + k0 + 16);
            b1v = *(const float4*)(Bb + k0 + 16 + strdA);
        }

#pragma unroll
        for (int sub = 0; sub < 2; sub++) {
            const int ks = sub * 8 + t;
            unsigned af[4][4], bf[4][2];
#pragma unroll
            for (int mt = 0; mt < 4; mt++) {
                const int m = wm + mt * 16 + g;
                af[mt][0] = As[m    ][ks];
                af[mt][1] = As[m + 8][ks];
                af[mt][2] = As[m    ][ks + 4];
                af[mt][3] = As[m + 8][ks + 4];
            }
#pragma unroll
            for (int nt = 0; nt < 4; nt++) {
                const int n = wn + nt * 8 + g;
                bf[nt][0] = Bs[n][ks];
                bf[nt][1] = Bs[n][ks + 4];
            }
#pragma unroll
            for (int mt = 0; mt < 4; mt++)
#pragma unroll
                for (int nt = 0; nt < 4; nt++)
                    mma_tf32(c[mt][nt], af[mt], bf[nt]);
        }
    }

#pragma unroll
    for (int mt = 0; mt < 4; mt++) {
        const size_t row = (size_t)blockIdx.y * 128 + wm + mt * 16 + g;
#pragma unroll
        for (int nt = 0; nt < 4; nt++) {
            const size_t col = (size_t)blockIdx.x * 128 + wn + nt * 8 + 2 * t;
            float2 lo = make_float2(c[mt][nt][0], c[mt][nt][1]);
            float2 hi = make_float2(c[mt][nt][2], c[mt][nt][3]);
            *(float2*)(C + row * N + col)       = lo;
            *(float2*)(C + (row + 8) * N + col) = hi;
        }
    }
}

// ---------------------------------------------------------------------------
// RoPE (unchanged)
// ---------------------------------------------------------------------------
__global__ void rope_kernel()
{
    const int row = blockIdx.x;
    const int s   = row & (S_LEN - 1);
    for (int t = threadIdx.x; t < NHEAD * 64; t += 256) {
        const int h = t >> 6;
        const int i = t & 63;
        float inv = powf(10000.0f, -((float)(2 * i)) / 128.0f);
        float ang = (float)s * inv;
        float sn, cs;
        sincosf(ang, &sn, &cs);
        const int idx = row * HID + h * HD + i;
        float q1 = g_Q[idx], q2 = g_Q[idx + 64];
        g_Q[idx]      = q1 * cs - q2 * sn;
        g_Q[idx + 64] = q1 * sn + q2 * cs;
        float k1 = g_K[idx], k2 = g_K[idx + 64];
        g_K[idx]      = k1 * cs - k2 * sn;
        g_K[idx + 64] = k1 * sn + k2 * cs;
    }
}

// ---------------------------------------------------------------------------
// TF32 flash attention. Bq = Bk = 64, D = 128, 256 threads (8 warps).
// S-phase: S[q][k] = Q Kt  (warp tile 32x16 of 64x64)
// PV-phase: O^T[d][q] += V^T P^T (warp tile 32x32 of 128x64) -> V needs no
//           transpose: A-frag reads Vs[k][d] (stride 136 == 8 mod 32,
//           conflict-free); P rows (tf32) are the col-major B-frag directly.
// Smem (floats): Qs 64x132 @0, Ks 64x132 @8448, Vs 64x136 @16896,
//                Ss 64x68 @25600, rmax@29952 rsum@30016 alp@30080 -> 30144
// ---------------------------------------------------------------------------
#define QST 132
#define KST 132
#define VST 136
#define SST 68
#define FLASH_SMEM (30144 * 4)

__global__ __launch_bounds__(256, 1)
void flash_tf32()
{
    extern __shared__ float sm[];
    float* Qs   = sm;
    float* Ks   = sm + 8448;
    float* Vs   = sm + 16896;
    float* Ss   = sm + 25600;
    float* rmax = sm + 29952;
    float* rsum = sm + 30016;
    float* alp  = sm + 30080;
    unsigned* Qu = (unsigned*)Qs;
    unsigned* Ku = (unsigned*)Ks;
    unsigned* Vu = (unsigned*)Vs;
    unsigned* Su = (unsigned*)Ss;

    const int tid  = threadIdx.x;
    const int lane = tid & 31;
    const int warp = tid >> 5;
    const int g    = lane >> 2;
    const int t    = lane & 3;
    const int q0   = blockIdx.x * 64;
    const int b    = blockIdx.y >> 4;
    const int h    = blockIdx.y & 15;
    const size_t base = (size_t)(b * S_LEN) * HID + (size_t)h * HD;

    const int wm_s = (warp & 1) * 32;    // S-phase: q offset
    const int wn_s = (warp >> 1) * 16;   // S-phase: k offset
    const int wm_p = (warp & 3) * 32;    // PV: d offset
    const int wn_p = (warp >> 2) * 32;   // PV: q offset

    // Load Q tile once (tf32)
#pragma unroll
    for (int i = 0; i < 8; i++) {
        const int r = warp * 8 + i;
        float4 v = *(const float4*)&g_Q[base + (size_t)(q0 + r) * HID + lane * 4];
        *(uint4*)&Qu[r * QST + lane * 4] = cvt4_tf32(v);
    }
    if (tid < 64) { rmax[tid] = -1e30f; rsum[tid] = 0.f; }

    float o[2][4][4];
#pragma unroll
    for (int mt = 0; mt < 2; mt++)
#pragma unroll
        for (int nt = 0; nt < 4; nt++)
#pragma unroll
            for (int j = 0; j < 4; j++) o[mt][nt][j] = 0.f;

    for (int kt = 0; kt < S_LEN; kt += 64) {
        __syncthreads();   // prev tile's Vs/Ss consumers done
#pragma unroll
        for (int i = 0; i < 8; i++) {
            const int r = warp * 8 + i;
            const size_t go = base + (size_t)(kt + r) * HID + lane * 4;
            *(uint4*)&Ku[r * KST + lane * 4] = cvt4_tf32(*(const float4*)&g_K[go]);
            *(uint4*)&Vu[r * VST + lane * 4] = cvt4_tf32(*(const float4*)&g_V[go]);
        }
        __syncthreads();

        // ---- S = Q K^T ----
        float s[2][2][4];
#pragma unroll
        for (int mt = 0; mt < 2; mt++)
#pragma unroll
            for (int nt = 0; nt < 2; nt++)
#pragma unroll
                for (int j = 0; j < 4; j++) s[mt][nt][j] = 0.f;

#pragma unroll
        for (int kk = 0; kk < 16; kk++) {
            const int ks = kk * 8 + t;
            unsigned af[2][4], bf[2][2];
#pragma unroll
            for (int mt = 0; mt < 2; mt++) {
                const int m = wm_s + mt * 16 + g;
                af[mt][0] = Qu[m * QST + ks];
                af[mt][1] = Qu[(m + 8) * QST + ks];
                af[mt][2] = Qu[m * QST + ks + 4];
                af[mt][3] = Qu[(m + 8) * QST + ks + 4];
            }
#pragma unroll
            for (int nt = 0; nt < 2; nt++) {
                const int n = wn_s + nt * 8 + g;
                bf[nt][0] = Ku[n * KST + ks];
                bf[nt][1] = Ku[n * KST + ks + 4];
            }
#pragma unroll
            for (int mt = 0; mt < 2; mt++)
#pragma unroll
                for (int nt = 0; nt < 2; nt++)
                    mma_tf32(s[mt][nt], af[mt], bf[nt]);
        }
#pragma unroll
        for (int mt = 0; mt < 2; mt++) {
            const int row = wm_s + mt * 16 + g;
#pragma unroll
            for (int nt = 0; nt < 2; nt++) {
                const int col = wn_s + nt * 8 + 2 * t;
                *(float2*)&Ss[row * SST + col] =
                    make_float2(s[mt][nt][0] * SCALE, s[mt][nt][1] * SCALE);
                *(float2*)&Ss[(row + 8) * SST + col] =
                    make_float2(s[mt][nt][2] * SCALE, s[mt][nt][3] * SCALE);
            }
        }
        __syncthreads();

        // ---- online softmax: 4 threads per row ----
        {
            const int row = tid >> 2;
            const int t4  = tid & 3;
            float* sr = Ss + row * SST + t4 * 16;
            const float mold = rmax[row];
            float mx = mold;
#pragma unroll
            for (int j = 0; j < 16; j++) mx = fmaxf(mx, sr[j]);
            mx = fmaxf(mx, __shfl_xor_sync(0xffffffffu, mx, 1));
            mx = fmaxf(mx, __shfl_xor_sync(0xffffffffu, mx, 2));
            float p = 0.f;
            unsigned* su = (unsigned*)sr;
#pragma unroll
            for (int j = 0; j < 16; j++) {
                const float e = __expf(sr[j] - mx);
                p += e;
                su[j] = cvt1_tf32(e);      // P stored as tf32 bits
            }
            p += __shfl_xor_sync(0xffffffffu, p, 1);
            p += __shfl_xor_sync(0xffffffffu, p, 2);
            if (t4 == 0) {
                const float a = __expf(mold - mx);
                rsum[row] = rsum[row] * a + p;
                rmax[row] = mx;
                alp[row]  = a;
            }
        }
        __syncthreads();

        // ---- alpha rescale + O^T += V^T P^T ----
        float alo[4], ahi[4];
#pragma unroll
        for (int nt = 0; nt < 4; nt++) {
            const int q = wn_p + nt * 8 + 2 * t;
            alo[nt] = alp[q];
            ahi[nt] = alp[q + 1];
        }
#pragma unroll
        for (int mt = 0; mt < 2; mt++)
#pragma unroll
            for (int nt = 0; nt < 4; nt++) {
                o[mt][nt][0] *= alo[nt];
                o[mt][nt][1] *= ahi[nt];
                o[mt][nt][2] *= alo[nt];
                o[mt][nt][3] *= ahi[nt];
            }

#pragma unroll
        for (int kk = 0; kk < 8; kk++) {
            const int ks = kk * 8;
            unsigned af[2][4], bf[4][2];
#pragma unroll
            for (int mt = 0; mt < 2; mt++) {
                const int m = wm_p + mt * 16 + g;
                af[mt][0] = Vu[(ks + t) * VST + m];
                af[mt][1] = Vu[(ks + t) * VST + m + 8];
                af[mt][2] = Vu[(ks + t + 4) * VST + m];
                af[mt][3] = Vu[(ks + t + 4) * VST + m + 8];
            }
#pragma unroll
            for (int nt = 0; nt < 4; nt++) {
                const int n = wn_p + nt * 8 + g;
                bf[nt][0] = Su[n * SST + ks + t];
                bf[nt][1] = Su[n * SST + ks + t + 4];
            }
#pragma unroll
            for (int mt = 0; mt < 2; mt++)
#pragma unroll
                for (int nt = 0; nt < 4; nt++)
                    mma_tf32(o[mt][nt], af[mt], bf[nt]);
        }
    }
    __syncthreads();

    // ---- epilogue: O[q][d] = O^T * (1/rsum[q]) ----
    float ilo[4], ihi[4];
#pragma unroll
    for (int nt = 0; nt < 4; nt++) {
        const int q = wn_p + nt * 8 + 2 * t;
        ilo[nt] = 1.0f / rsum[q];
        ihi[nt] = 1.0f / rsum[q + 1];
    }
#pragma unroll
    for (int mt = 0; mt < 2; mt++) {
        const int d = wm_p + mt * 16 + g;
#pragma unroll
        for (int nt = 0; nt < 4; nt++) {
            const int q = wn_p + nt * 8 + 2 * t;
            g_Ctx[base + (size_t)(q0 + q)     * HID + d]     = o[mt][nt][0] * ilo[nt];
            g_Ctx[base + (size_t)(q0 + q + 1) * HID + d]     = o[mt][nt][1] * ihi[nt];
            g_Ctx[base + (size_t)(q0 + q)     * HID + d + 8] = o[mt][nt][2] * ilo[nt];
            g_Ctx[base + (size_t)(q0 + q + 1) * HID + d + 8] = o[mt][nt][3] * ihi[nt];
        }
    }
}

// ---------------------------------------------------------------------------
// Launch
// ---------------------------------------------------------------------------
extern "C" void kernel_launch(void* const* d_in, const int* in_sizes, int n_in,
                              void* d_out, int out_size)
{
    const float* x  = (const float*)d_in[0];
    const float* Wq = (const float*)d_in[1];
    const float* Wk = (const float*)d_in[2];
    const float* Wv = (const float*)d_in[3];
    const float* Wo = (const float*)d_in[4];
    float* out = (float*)d_out;

    float *pQ, *pK, *pV, *pC;
    cudaGetSymbolAddress((void**)&pQ, g_Q);
    cudaGetSymbolAddress((void**)&pK, g_K);
    cudaGetSymbolAddress((void**)&pV, g_V);
    cudaGetSymbolAddress((void**)&pC, g_Ctx);

    dim3 gg(HID / 128, MROWS / 128);   // (16, 32)

    gemm_tf32_nt<<<gg, 256>>>(x, Wq, pQ, MROWS, HID, HID);
    gemm_tf32_nt<<<gg, 256>>>(x, Wk, pK, MROWS, HID, HID);
    gemm_tf32_nt<<<gg, 256>>>(x, Wv, pV, MROWS, HID, HID);

    rope_kernel<<<MROWS, 256>>>();

    cudaFuncSetAttribute(flash_tf32,
                         cudaFuncAttributeMaxDynamicSharedMemorySize, FLASH_SMEM);
    flash_tf32<<<dim3(S_LEN / 64, 2 * NHEAD), 256, FLASH_SMEM>>>();

    gemm_tf32_nt<<<gg, 256>>>(pC, Wo, out, MROWS, HID, HID);
}

// round 4
// speedup vs baseline: 3.4839x; 1.0597x over previous
#include <cuda_runtime.h>
#include <math.h>

#define S_LEN 2048
#define HID   2048
#define NHEAD 16
#define HD    128
#define MROWS 4096          // B * S
#define SCALE 0.08838834764831845f   // 1/sqrt(128)

// ---------------------------------------------------------------------------
// Global scratch
// ---------------------------------------------------------------------------
__device__ float g_Q[MROWS * HID];
__device__ float g_K[MROWS * HID];
__device__ float g_V[MROWS * HID];
__device__ float g_Ctx[MROWS * HID];
__device__ float g_xr[MROWS * HID];          // x rounded to tf32
__device__ float g_Wr[4 * HID * HID];        // Wq,Wk,Wv,Wo rounded to tf32

// ---------------------------------------------------------------------------
// Helpers
// ---------------------------------------------------------------------------
__device__ __forceinline__ uint4 cvt4_tf32(float4 v)
{
    uint4 r;
    asm("cvt.rna.tf32.f32 %0, %1;" : "=r"(r.x) : "f"(v.x));
    asm("cvt.rna.tf32.f32 %0, %1;" : "=r"(r.y) : "f"(v.y));
    asm("cvt.rna.tf32.f32 %0, %1;" : "=r"(r.z) : "f"(v.z));
    asm("cvt.rna.tf32.f32 %0, %1;" : "=r"(r.w) : "f"(v.w));
    return r;
}

__device__ __forceinline__ unsigned cvt1_tf32(float v)
{
    unsigned r;
    asm("cvt.rna.tf32.f32 %0, %1;" : "=r"(r) : "f"(v));
    return r;
}

__device__ __forceinline__ void mma_tf32(float* c, const unsigned* a, const unsigned* b)
{
    asm volatile(
        "mma.sync.aligned.m16n8k8.row.col.f32.tf32.tf32.f32 "
        "{%0,%1,%2,%3}, {%4,%5,%6,%7}, {%8,%9}, {%0,%1,%2,%3};\n"
        : "+f"(c[0]), "+f"(c[1]), "+f"(c[2]), "+f"(c[3])
        : "r"(a[0]), "r"(a[1]), "r"(a[2]), "r"(a[3]),
          "r"(b[0]), "r"(b[1]));
}

__device__ __forceinline__ void cp_async16(unsigned saddr, const void* gaddr)
{
    asm volatile("cp.async.cg.shared.global [%0], [%1], 16;\n"
                 :: "r"(saddr), "l"(gaddr));
}
__device__ __forceinline__ void cp_commit()
{
    asm volatile("cp.async.commit_group;\n" ::: "memory");
}
__device__ __forceinline__ void cp_wait2()
{
    asm volatile("cp.async.wait_group 2;\n" ::: "memory");
}

// ---------------------------------------------------------------------------
// Pre-round: dst = tf32_rna(src), vectorized
// ---------------------------------------------------------------------------
__global__ void round_tf32_kernel(const float4* __restrict__ src,
                                  float4* __restrict__ dst, int n4)
{
    for (int i = blockIdx.x * blockDim.x + threadIdx.x; i < n4;
         i += gridDim.x * blockDim.x) {
        uint4 u = cvt4_tf32(src[i]);
        dst[i] = *(float4*)&u;
    }
}

// ---------------------------------------------------------------------------
// Pipelined TF32 GEMM: C[M,N] = A[M,K]*B[N,K]^T. Inputs MUST already be
// tf32-representable (mma truncation then exact). CTA 128x128, K-tile 16,
// 4-stage cp.async, 256 threads, warp tile 64x32.
// Smem: 4 stages x (A 128x20 + B 128x20) words = 81920 B.
// ---------------------------------------------------------------------------
#define GSTG   4
#define GS_MAT 2560              // words per matrix per stage (128*20)
#define GS_STG (2 * GS_MAT)      // words per stage
#define GEMM_SMEM (GSTG * GS_STG * 4)

__global__ __launch_bounds__(256, 2)
void gemm_tf32_pipe(const float* __restrict__ A, const float* __restrict__ B,
                    float* __restrict__ C, int M, int N, int K)
{
    extern __shared__ unsigned sh[];

    const int tid  = threadIdx.x;
    const int lane = tid & 31;
    const int warp = tid >> 5;
    const int g    = lane >> 2;
    const int t    = lane & 3;
    const int wm   = (warp & 1) * 64;
    const int wn   = (warp >> 1) * 32;

    const int lr = tid >> 2;          // 0..63
    const int lk = (tid & 3) * 4;     // 0,4,8,12

    const float* Ag = A + (size_t)(blockIdx.y * 128 + lr) * K + lk;
    const float* Bg = B + (size_t)(blockIdx.x * 128 + lr) * K + lk;
    const size_t strd = (size_t)64 * K;

    const unsigned shbase = (unsigned)__cvta_generic_to_shared(sh);
    const unsigned sA0 = shbase + (lr * 20 + lk) * 4;
    const unsigned sA1 = shbase + ((lr + 64) * 20 + lk) * 4;

    const int ntiles = K / 16;

    float c[4][4][4];
#pragma unroll
    for (int i = 0; i < 4; i++)
#pragma unroll
        for (int j = 0; j < 4; j++)
#pragma unroll
            for (int q = 0; q < 4; q++) c[i][j][q] = 0.f;

    // prologue: stages 0..2
#pragma unroll
    for (int s = 0; s < GSTG - 1; s++) {
        const unsigned so = s * GS_STG * 4;
        const int k0 = s * 16;
        cp_async16(sA0 + so, Ag + k0);
        cp_async16(sA1 + so, Ag + k0 + strd);
        cp_async16(sA0 + so + GS_MAT * 4, Bg + k0);
        cp_async16(sA1 + so + GS_MAT * 4, Bg + k0 + strd);
        cp_commit();
    }

    for (int i = 0; i < ntiles; i++) {
        cp_wait2();
        __syncthreads();

        if (i + GSTG - 1 < ntiles) {
            const int s = (i + GSTG - 1) & (GSTG - 1);
            const unsigned so = s * GS_STG * 4;
            const int k0 = (i + GSTG - 1) * 16;
            cp_async16(sA0 + so, Ag + k0);
            cp_async16(sA1 + so, Ag + k0 + strd);
            cp_async16(sA0 + so + GS_MAT * 4, Bg + k0);
            cp_async16(sA1 + so + GS_MAT * 4, Bg + k0 + strd);
        }
        cp_commit();

        const unsigned* As = sh + (i & (GSTG - 1)) * GS_STG;
        const unsigned* Bs = As + GS_MAT;

#pragma unroll
        for (int sub = 0; sub < 2; sub++) {
            const int ks = sub * 8 + t;
            unsigned af[4][4], bf[4][2];
#pragma unroll
            for (int mt = 0; mt < 4; mt++) {
                const int m = wm + mt * 16 + g;
                af[mt][0] = As[m * 20 + ks];
                af[mt][1] = As[(m + 8) * 20 + ks];
                af[mt][2] = As[m * 20 + ks + 4];
                af[mt][3] = As[(m + 8) * 20 + ks + 4];
            }
#pragma unroll
            for (int nt = 0; nt < 4; nt++) {
                const int n = wn + nt * 8 + g;
                bf[nt][0] = Bs[n * 20 + ks];
                bf[nt][1] = Bs[n * 20 + ks + 4];
            }
#pragma unroll
            for (int mt = 0; mt < 4; mt++)
#pragma unroll
                for (int nt = 0; nt < 4; nt++)
                    mma_tf32(c[mt][nt], af[mt], bf[nt]);
        }
        __syncthreads();
    }

#pragma unroll
    for (int mt = 0; mt < 4; mt++) {
        const size_t row = (size_t)blockIdx.y * 128 + wm + mt * 16 + g;
#pragma unroll
        for (int nt = 0; nt < 4; nt++) {
            const size_t col = (size_t)blockIdx.x * 128 + wn + nt * 8 + 2 * t;
            *(float2*)(C + row * N + col) =
                make_float2(c[mt][nt][0], c[mt][nt][1]);
            *(float2*)(C + (row + 8) * N + col) =
                make_float2(c[mt][nt][2], c[mt][nt][3]);
        }
    }
}

// ---------------------------------------------------------------------------
// RoPE (unchanged)
// ---------------------------------------------------------------------------
__global__ void rope_kernel()
{
    const int row = blockIdx.x;
    const int s   = row & (S_LEN - 1);
    for (int t = threadIdx.x; t < NHEAD * 64; t += 256) {
        const int h = t >> 6;
        const int i = t & 63;
        float inv = powf(10000.0f, -((float)(2 * i)) / 128.0f);
        float ang = (float)s * inv;
        float sn, cs;
        sincosf(ang, &sn, &cs);
        const int idx = row * HID + h * HD + i;
        float q1 = g_Q[idx], q2 = g_Q[idx + 64];
        g_Q[idx]      = q1 * cs - q2 * sn;
        g_Q[idx + 64] = q1 * sn + q2 * cs;
        float k1 = g_K[idx], k2 = g_K[idx + 64];
        g_K[idx]      = k1 * cs - k2 * sn;
        g_K[idx + 64] = k1 * sn + k2 * cs;
    }
}

// ---------------------------------------------------------------------------
// TF32 flash attention (unchanged except Ctx written tf32-rounded)
// ---------------------------------------------------------------------------
#define QST 132
#define KST 132
#define VST 136
#define SST 68
#define FLASH_SMEM (30144 * 4)

__global__ __launch_bounds__(256, 1)
void flash_tf32()
{
    extern __shared__ float sm[];
    float* Qs   = sm;
    float* Ks   = sm + 8448;
    float* Vs   = sm + 16896;
    float* Ss   = sm + 25600;
    float* rmax = sm + 29952;
    float* rsum = sm + 30016;
    float* alp  = sm + 30080;
    unsigned* Qu = (unsigned*)Qs;
    unsigned* Ku = (unsigned*)Ks;
    unsigned* Vu = (unsigned*)Vs;
    unsigned* Su = (unsigned*)Ss;

    const int tid  = threadIdx.x;
    const int lane = tid & 31;
    const int warp = tid >> 5;
    const int g    = lane >> 2;
    const int t    = lane & 3;
    const int q0   = blockIdx.x * 64;
    const int b    = blockIdx.y >> 4;
    const int h    = blockIdx.y & 15;
    const size_t base = (size_t)(b * S_LEN) * HID + (size_t)h * HD;

    const int wm_s = (warp & 1) * 32;
    const int wn_s = (warp >> 1) * 16;
    const int wm_p = (warp & 3) * 32;
    const int wn_p = (warp >> 2) * 32;

#pragma unroll
    for (int i = 0; i < 8; i++) {
        const int r = warp * 8 + i;
        float4 v = *(const float4*)&g_Q[base + (size_t)(q0 + r) * HID + lane * 4];
        *(uint4*)&Qu[r * QST + lane * 4] = cvt4_tf32(v);
    }
    if (tid < 64) { rmax[tid] = -1e30f; rsum[tid] = 0.f; }

    float o[2][4][4];
#pragma unroll
    for (int mt = 0; mt < 2; mt++)
#pragma unroll
        for (int nt = 0; nt < 4; nt++)
#pragma unroll
            for (int j = 0; j < 4; j++) o[mt][nt][j] = 0.f;

    for (int kt = 0; kt < S_LEN; kt += 64) {
        __syncthreads();
#pragma unroll
        for (int i = 0; i < 8; i++) {
            const int r = warp * 8 + i;
            const size_t go = base + (size_t)(kt + r) * HID + lane * 4;
            *(uint4*)&Ku[r * KST + lane * 4] = cvt4_tf32(*(const float4*)&g_K[go]);
            *(uint4*)&Vu[r * VST + lane * 4] = cvt4_tf32(*(const float4*)&g_V[go]);
        }
        __syncthreads();

        float s[2][2][4];
#pragma unroll
        for (int mt = 0; mt < 2; mt++)
#pragma unroll
            for (int nt = 0; nt < 2; nt++)
#pragma unroll
                for (int j = 0; j < 4; j++) s[mt][nt][j] = 0.f;

#pragma unroll
        for (int kk = 0; kk < 16; kk++) {
            const int ks = kk * 8 + t;
            unsigned af[2][4], bf[2][2];
#pragma unroll
            for (int mt = 0; mt < 2; mt++) {
                const int m = wm_s + mt * 16 + g;
                af[mt][0] = Qu[m * QST + ks];
                af[mt][1] = Qu[(m + 8) * QST + ks];
                af[mt][2] = Qu[m * QST + ks + 4];
                af[mt][3] = Qu[(m + 8) * QST + ks + 4];
            }
#pragma unroll
            for (int nt = 0; nt < 2; nt++) {
                const int n = wn_s + nt * 8 + g;
                bf[nt][0] = Ku[n * KST + ks];
                bf[nt][1] = Ku[n * KST + ks + 4];
            }
#pragma unroll
            for (int mt = 0; mt < 2; mt++)
#pragma unroll
                for (int nt = 0; nt < 2; nt++)
                    mma_tf32(s[mt][nt], af[mt], bf[nt]);
        }
#pragma unroll
        for (int mt = 0; mt < 2; mt++) {
            const int row = wm_s + mt * 16 + g;
#pragma unroll
            for (int nt = 0; nt < 2; nt++) {
                const int col = wn_s + nt * 8 + 2 * t;
                *(float2*)&Ss[row * SST + col] =
                    make_float2(s[mt][nt][0] * SCALE, s[mt][nt][1] * SCALE);
                *(float2*)&Ss[(row + 8) * SST + col] =
                    make_float2(s[mt][nt][2] * SCALE, s[mt][nt][3] * SCALE);
            }
        }
        __syncthreads();

        {
            const int row = tid >> 2;
            const int t4  = tid & 3;
            float* sr = Ss + row * SST + t4 * 16;
            const float mold = rmax[row];
            float mx = mold;
#pragma unroll
            for (int j = 0; j < 16; j++) mx = fmaxf(mx, sr[j]);
            mx = fmaxf(mx, __shfl_xor_sync(0xffffffffu, mx, 1));
            mx = fmaxf(mx, __shfl_xor_sync(0xffffffffu, mx, 2));
            float p = 0.f;
            unsigned* su = (unsigned*)sr;
#pragma unroll
            for (int j = 0; j < 16; j++) {
                const float e = __expf(sr[j] - mx);
                p += e;
                su[j] = cvt1_tf32(e);
            }
            p += __shfl_xor_sync(0xffffffffu, p, 1);
            p += __shfl_xor_sync(0xffffffffu, p, 2);
            if (t4 == 0) {
                const float a = __expf(mold - mx);
                rsum[row] = rsum[row] * a + p;
                rmax[row] = mx;
                alp[row]  = a;
            }
        }
        __syncthreads();

        float alo[4], ahi[4];
#pragma unroll
        for (int nt = 0; nt < 4; nt++) {
            const int q = wn_p + nt * 8 + 2 * t;
            alo[nt] = alp[q];
            ahi[nt] = alp[q + 1];
        }
#pragma unroll
        for (int mt = 0; mt < 2; mt++)
#pragma unroll
            for (int nt = 0; nt < 4; nt++) {
                o[mt][nt][0] *= alo[nt];
                o[mt][nt][1] *= ahi[nt];
                o[mt][nt][2] *= alo[nt];
                o[mt][nt][3] *= ahi[nt];
            }

#pragma unroll
        for (int kk = 0; kk < 8; kk++) {
            const int ks = kk * 8;
            unsigned af[2][4], bf[4][2];
#pragma unroll
            for (int mt = 0; mt < 2; mt++) {
                const int m = wm_p + mt * 16 + g;
                af[mt][0] = Vu[(ks + t) * VST + m];
                af[mt][1] = Vu[(ks + t) * VST + m + 8];
                af[mt][2] = Vu[(ks + t + 4) * VST + m];
                af[mt][3] = Vu[(ks + t + 4) * VST + m + 8];
            }
#pragma unroll
            for (int nt = 0; nt < 4; nt++) {
                const int n = wn_p + nt * 8 + g;
                bf[nt][0] = Su[n * SST + ks + t];
                bf[nt][1] = Su[n * SST + ks + t + 4];
            }
#pragma unroll
            for (int mt = 0; mt < 2; mt++)
#pragma unroll
                for (int nt = 0; nt < 4; nt++)
                    mma_tf32(o[mt][nt], af[mt], bf[nt]);
        }
    }
    __syncthreads();

    float ilo[4], ihi[4];
#pragma unroll
    for (int nt = 0; nt < 4; nt++) {
        const int q = wn_p + nt * 8 + 2 * t;
        ilo[nt] = 1.0f / rsum[q];
        ihi[nt] = 1.0f / rsum[q + 1];
    }
    unsigned* Cu = (unsigned*)g_Ctx;
#pragma unroll
    for (int mt = 0; mt < 2; mt++) {
        const int d = wm_p + mt * 16 + g;
#pragma unroll
        for (int nt = 0; nt < 4; nt++) {
            const int q = wn_p + nt * 8 + 2 * t;
            Cu[base + (size_t)(q0 + q)     * HID + d]     = cvt1_tf32(o[mt][nt][0] * ilo[nt]);
            Cu[base + (size_t)(q0 + q + 1) * HID + d]     = cvt1_tf32(o[mt][nt][1] * ihi[nt]);
            Cu[base + (size_t)(q0 + q)     * HID + d + 8] = cvt1_tf32(o[mt][nt][2] * ilo[nt]);
            Cu[base + (size_t)(q0 + q + 1) * HID + d + 8] = cvt1_tf32(o[mt][nt][3] * ihi[nt]);
        }
    }
}

// ---------------------------------------------------------------------------
// Launch
// ---------------------------------------------------------------------------
extern "C" void kernel_launch(void* const* d_in, const int* in_sizes, int n_in,
                              void* d_out, int out_size)
{
    const float* x  = (const float*)d_in[0];
    const float* Wq = (const float*)d_in[1];
    const float* Wk = (const float*)d_in[2];
    const float* Wv = (const float*)d_in[3];
    const float* Wo = (const float*)d_in[4];
    float* out = (float*)d_out;

    float *pQ, *pK, *pV, *pC, *pXr, *pWr;
    cudaGetSymbolAddress((void**)&pQ,  g_Q);
    cudaGetSymbolAddress((void**)&pK,  g_K);
    cudaGetSymbolAddress((void**)&pV,  g_V);
    cudaGetSymbolAddress((void**)&pC,  g_Ctx);
    cudaGetSymbolAddress((void**)&pXr, g_xr);
    cudaGetSymbolAddress((void**)&pWr, g_Wr);

    const int WSZ = HID * HID;   // 4M elements per weight

    // Pre-round inputs to tf32 (exactness: mma truncation of rounded = rounded)
    round_tf32_kernel<<<1024, 256>>>((const float4*)x,  (float4*)pXr, MROWS * HID / 4);
    round_tf32_kernel<<<512, 256>>>((const float4*)Wq, (float4*)(pWr + 0 * WSZ), WSZ / 4);
    round_tf32_kernel<<<512, 256>>>((const float4*)Wk, (float4*)(pWr + 1 * WSZ), WSZ / 4);
    round_tf32_kernel<<<512, 256>>>((const float4*)Wv, (float4*)(pWr + 2 * WSZ), WSZ / 4);
    round_tf32_kernel<<<512, 256>>>((const float4*)Wo, (float4*)(pWr + 3 * WSZ), WSZ / 4);

    dim3 gg(HID / 128, MROWS / 128);   // (16, 32)

    cudaFuncSetAttribute(gemm_tf32_pipe,
                         cudaFuncAttributeMaxDynamicSharedMemorySize, GEMM_SMEM);

    gemm_tf32_pipe<<<gg, 256, GEMM_SMEM>>>(pXr, pWr + 0 * WSZ, pQ, MROWS, HID, HID);
    gemm_tf32_pipe<<<gg, 256, GEMM_SMEM>>>(pXr, pWr + 1 * WSZ, pK, MROWS, HID, HID);
    gemm_tf32_pipe<<<gg, 256, GEMM_SMEM>>>(pXr, pWr + 2 * WSZ, pV, MROWS, HID, HID);

    rope_kernel<<<MROWS, 256>>>();

    cudaFuncSetAttribute(flash_tf32,
                         cudaFuncAttributeMaxDynamicSharedMemorySize, FLASH_SMEM);
    flash_tf32<<<dim3(S_LEN / 64, 2 * NHEAD), 256, FLASH_SMEM>>>();

    gemm_tf32_pipe<<<gg, 256, GEMM_SMEM>>>(pC, pWr + 3 * WSZ, out, MROWS, HID, HID);
}

// round 6
// speedup vs baseline: 3.8201x; 1.0965x over previous
#include <cuda_runtime.h>
#include <math.h>

#define S_LEN 2048
#define HID   2048
#define NHEAD 16
#define HD    128
#define MROWS 4096
#define SCALE 0.08838834764831845f

// ---------------------------------------------------------------------------
// Global scratch
// ---------------------------------------------------------------------------
__device__ float g_Q[MROWS * HID];
__device__ float g_K[MROWS * HID];
__device__ float g_V[MROWS * HID];
__device__ float g_Ctx[MROWS * HID];
__device__ float g_xr[MROWS * HID];
__device__ float g_Wr[4 * HID * HID];

// ---------------------------------------------------------------------------
// Helpers
// ---------------------------------------------------------------------------
__device__ __forceinline__ uint4 cvt4_tf32(float4 v)
{
    uint4 r;
    asm("cvt.rna.tf32.f32 %0, %1;" : "=r"(r.x) : "f"(v.x));
    asm("cvt.rna.tf32.f32 %0, %1;" : "=r"(r.y) : "f"(v.y));
    asm("cvt.rna.tf32.f32 %0, %1;" : "=r"(r.z) : "f"(v.z));
    asm("cvt.rna.tf32.f32 %0, %1;" : "=r"(r.w) : "f"(v.w));
    return r;
}
__device__ __forceinline__ unsigned cvt1_tf32(float v)
{
    unsigned r;
    asm("cvt.rna.tf32.f32 %0, %1;" : "=r"(r) : "f"(v));
    return r;
}
__device__ __forceinline__ void mma_tf32(float* c, const unsigned* a, const unsigned* b)
{
    asm volatile(
        "mma.sync.aligned.m16n8k8.row.col.f32.tf32.tf32.f32 "
        "{%0,%1,%2,%3}, {%4,%5,%6,%7}, {%8,%9}, {%0,%1,%2,%3};\n"
        : "+f"(c[0]), "+f"(c[1]), "+f"(c[2]), "+f"(c[3])
        : "r"(a[0]), "r"(a[1]), "r"(a[2]), "r"(a[3]),
          "r"(b[0]), "r"(b[1]));
}
__device__ __forceinline__ void cp_async16(unsigned saddr, const void* gaddr)
{
    asm volatile("cp.async.cg.shared.global [%0], [%1], 16;\n"
                 :: "r"(saddr), "l"(gaddr));
}
__device__ __forceinline__ void cp_commit()
{
    asm volatile("cp.async.commit_group;\n" ::: "memory");
}

// ---------------------------------------------------------------------------
// Pre-round to tf32 (exactness: mma truncation of an rna-rounded value = id)
// ---------------------------------------------------------------------------
__global__ void round_tf32_kernel(const float4* __restrict__ src,
                                  float4* __restrict__ dst, int n4)
{
    for (int i = blockIdx.x * blockDim.x + threadIdx.x; i < n4;
         i += gridDim.x * blockDim.x) {
        uint4 u = cvt4_tf32(src[i]);
        dst[i] = *(float4*)&u;
    }
}

// ---------------------------------------------------------------------------
// Pipelined TF32 GEMM: C[M,N] = A[M,K]*B[N,K]^T, tf32-representable inputs.
// CTA 128x128, K-tile 16, 4-stage cp.async, 256 threads, warp tile 64x32.
// ONE __syncthreads per tile; explicit sub0/sub1 fragment double-buffer.
// ---------------------------------------------------------------------------
#define GSTG   4
#define GS_MAT 2560              // words per matrix per stage (128*20)
#define GS_STG (2 * GS_MAT)
#define GEMM_SMEM (GSTG * GS_STG * 4)

__global__ __launch_bounds__(256, 2)
void gemm_tf32_pipe(const float* __restrict__ A, const float* __restrict__ B,
                    float* __restrict__ C, int M, int N, int K)
{
    extern __shared__ unsigned sh[];

    const int tid  = threadIdx.x;
    const int lane = tid & 31;
    const int warp = tid >> 5;
    const int g    = lane >> 2;
    const int t    = lane & 3;
    const int wm   = (warp & 1) * 64;
    const int wn   = (warp >> 1) * 32;

    const int lr = tid >> 2;          // 0..63
    const int lk = (tid & 3) * 4;     // 0,4,8,12

    const float* Ag = A + (size_t)(blockIdx.y * 128 + lr) * K + lk;
    const float* Bg = B + (size_t)(blockIdx.x * 128 + lr) * K + lk;
    const size_t strd = (size_t)64 * K;

    const unsigned shbase = (unsigned)__cvta_generic_to_shared(sh);
    const unsigned sA0 = shbase + (lr * 20 + lk) * 4;
    const unsigned sA1 = shbase + ((lr + 64) * 20 + lk) * 4;

    const int ntiles = K / 16;

    float c[4][4][4];
#pragma unroll
    for (int i = 0; i < 4; i++)
#pragma unroll
        for (int j = 0; j < 4; j++)
#pragma unroll
            for (int q = 0; q < 4; q++) c[i][j][q] = 0.f;

    // prologue: stages 0..2
#pragma unroll
    for (int s = 0; s < GSTG - 1; s++) {
        const unsigned so = s * GS_STG * 4;
        const int k0 = s * 16;
        cp_async16(sA0 + so, Ag + k0);
        cp_async16(sA1 + so, Ag + k0 + strd);
        cp_async16(sA0 + so + GS_MAT * 4, Bg + k0);
        cp_async16(sA1 + so + GS_MAT * 4, Bg + k0 + strd);
        cp_commit();
    }

    for (int i = 0; i < ntiles; i++) {
        asm volatile("cp.async.wait_group 2;\n" ::: "memory");
        __syncthreads();    // also orders: compute(i-1) done before stage
                            // (i-1)%4 is overwritten by the cp.async below

        const unsigned* As = sh + (i & (GSTG - 1)) * GS_STG;
        const unsigned* Bs = As + GS_MAT;

        unsigned af[2][4][4], bf[2][4][2];

        // sub0 fragments (ks = t)
#pragma unroll
        for (int mt = 0; mt < 4; mt++) {
            const int m = wm + mt * 16 + g;
            af[0][mt][0] = As[m * 20 + t];
            af[0][mt][1] = As[(m + 8) * 20 + t];
            af[0][mt][2] = As[m * 20 + t + 4];
            af[0][mt][3] = As[(m + 8) * 20 + t + 4];
        }
#pragma unroll
        for (int nt = 0; nt < 4; nt++) {
            const int n = wn + nt * 8 + g;
            bf[0][nt][0] = Bs[n * 20 + t];
            bf[0][nt][1] = Bs[n * 20 + t + 4];
        }

        // issue copies for tile i+3
        if (i + GSTG - 1 < ntiles) {
            const int s = (i + GSTG - 1) & (GSTG - 1);
            const unsigned so = s * GS_STG * 4;
            const int k0 = (i + GSTG - 1) * 16;
            cp_async16(sA0 + so, Ag + k0);
            cp_async16(sA1 + so, Ag + k0 + strd);
            cp_async16(sA0 + so + GS_MAT * 4, Bg + k0);
            cp_async16(sA1 + so + GS_MAT * 4, Bg + k0 + strd);
        }
        cp_commit();

        // sub1 fragments (ks = 8 + t) — overlap with sub0 MMAs below
#pragma unroll
        for (int mt = 0; mt < 4; mt++) {
            const int m = wm + mt * 16 + g;
            af[1][mt][0] = As[m * 20 + 8 + t];
            af[1][mt][1] = As[(m + 8) * 20 + 8 + t];
            af[1][mt][2] = As[m * 20 + 8 + t + 4];
            af[1][mt][3] = As[(m + 8) * 20 + 8 + t + 4];
        }
#pragma unroll
        for (int nt = 0; nt < 4; nt++) {
            const int n = wn + nt * 8 + g;
            bf[1][nt][0] = Bs[n * 20 + 8 + t];
            bf[1][nt][1] = Bs[n * 20 + 8 + t + 4];
        }

#pragma unroll
        for (int mt = 0; mt < 4; mt++)
#pragma unroll
            for (int nt = 0; nt < 4; nt++)
                mma_tf32(c[mt][nt], af[0][mt], bf[0][nt]);
#pragma unroll
        for (int mt = 0; mt < 4; mt++)
#pragma unroll
            for (int nt = 0; nt < 4; nt++)
                mma_tf32(c[mt][nt], af[1][mt], bf[1][nt]);
    }

#pragma unroll
    for (int mt = 0; mt < 4; mt++) {
        const size_t row = (size_t)blockIdx.y * 128 + wm + mt * 16 + g;
#pragma unroll
        for (int nt = 0; nt < 4; nt++) {
            const size_t col = (size_t)blockIdx.x * 128 + wn + nt * 8 + 2 * t;
            *(float2*)(C + row * N + col) =
                make_float2(c[mt][nt][0], c[mt][nt][1]);
            *(float2*)(C + (row + 8) * N + col) =
                make_float2(c[mt][nt][2], c[mt][nt][3]);
        }
    }
}

// ---------------------------------------------------------------------------
// RoPE (unchanged)
// ---------------------------------------------------------------------------
__global__ void rope_kernel()
{
    const int row = blockIdx.x;
    const int s   = row & (S_LEN - 1);
    for (int t = threadIdx.x; t < NHEAD * 64; t += 256) {
        const int h = t >> 6;
        const int i = t & 63;
        float inv = powf(10000.0f, -((float)(2 * i)) / 128.0f);
        float ang = (float)s * inv;
        float sn, cs;
        sincosf(ang, &sn, &cs);
        const int idx = row * HID + h * HD + i;
        float q1 = g_Q[idx], q2 = g_Q[idx + 64];
        g_Q[idx]      = q1 * cs - q2 * sn;
        g_Q[idx + 64] = q1 * sn + q2 * cs;
        float k1 = g_K[idx], k2 = g_K[idx + 64];
        g_K[idx]      = k1 * cs - k2 * sn;
        g_K[idx + 64] = k1 * sn + k2 * cs;
    }
}

// ---------------------------------------------------------------------------
// TF32 flash attention (unchanged from R4; writes Ctx tf32-rounded)
// ---------------------------------------------------------------------------
#define QST 132
#define KST 132
#define VST 136
#define SST 68
#define FLASH_SMEM (30144 * 4)

__global__ __launch_bounds__(256, 1)
void flash_tf32()
{
    extern __shared__ float sm[];
    float* Qs   = sm;
    float* Ks   = sm + 8448;
    float* Vs   = sm + 16896;
    float* Ss   = sm + 25600;
    float* rmax = sm + 29952;
    float* rsum = sm + 30016;
    float* alp  = sm + 30080;
    unsigned* Qu = (unsigned*)Qs;
    unsigned* Ku = (unsigned*)Ks;
    unsigned* Vu = (unsigned*)Vs;
    unsigned* Su = (unsigned*)Ss;

    const int tid  = threadIdx.x;
    const int lane = tid & 31;
    const int warp = tid >> 5;
    const int g    = lane >> 2;
    const int t    = lane & 3;
    const int q0   = blockIdx.x * 64;
    const int b    = blockIdx.y >> 4;
    const int h    = blockIdx.y & 15;
    const size_t base = (size_t)(b * S_LEN) * HID + (size_t)h * HD;

    const int wm_s = (warp & 1) * 32;
    const int wn_s = (warp >> 1) * 16;
    const int wm_p = (warp & 3) * 32;
    const int wn_p = (warp >> 2) * 32;

#pragma unroll
    for (int i = 0; i < 8; i++) {
        const int r = warp * 8 + i;
        float4 v = *(const float4*)&g_Q[base + (size_t)(q0 + r) * HID + lane * 4];
        *(uint4*)&Qu[r * QST + lane * 4] = cvt4_tf32(v);
    }
    if (tid < 64) { rmax[tid] = -1e30f; rsum[tid] = 0.f; }

    float o[2][4][4];
#pragma unroll
    for (int mt = 0; mt < 2; mt++)
#pragma unroll
        for (int nt = 0; nt < 4; nt++)
#pragma unroll
            for (int j = 0; j < 4; j++) o[mt][nt][j] = 0.f;

    for (int kt = 0; kt < S_LEN; kt += 64) {
        __syncthreads();
#pragma unroll
        for (int i = 0; i < 8; i++) {
            const int r = warp * 8 + i;
            const size_t go = base + (size_t)(kt + r) * HID + lane * 4;
            *(uint4*)&Ku[r * KST + lane * 4] = cvt4_tf32(*(const float4*)&g_K[go]);
            *(uint4*)&Vu[r * VST + lane * 4] = cvt4_tf32(*(const float4*)&g_V[go]);
        }
        __syncthreads();

        float s[2][2][4];
#pragma unroll
        for (int mt = 0; mt < 2; mt++)
#pragma unroll
            for (int nt = 0; nt < 2; nt++)
#pragma unroll
                for (int j = 0; j < 4; j++) s[mt][nt][j] = 0.f;

#pragma unroll
        for (int kk = 0; kk < 16; kk++) {
            const int ks = kk * 8 + t;
            unsigned af[2][4], bf[2][2];
#pragma unroll
            for (int mt = 0; mt < 2; mt++) {
                const int m = wm_s + mt * 16 + g;
                af[mt][0] = Qu[m * QST + ks];
                af[mt][1] = Qu[(m + 8) * QST + ks];
                af[mt][2] = Qu[m * QST + ks + 4];
                af[mt][3] = Qu[(m + 8) * QST + ks + 4];
            }
#pragma unroll
            for (int nt = 0; nt < 2; nt++) {
                const int n = wn_s + nt * 8 + g;
                bf[nt][0] = Ku[n * KST + ks];
                bf[nt][1] = Ku[n * KST + ks + 4];
            }
#pragma unroll
            for (int mt = 0; mt < 2; mt++)
#pragma unroll
                for (int nt = 0; nt < 2; nt++)
                    mma_tf32(s[mt][nt], af[mt], bf[nt]);
        }
#pragma unroll
        for (int mt = 0; mt < 2; mt++) {
            const int row = wm_s + mt * 16 + g;
#pragma unroll
            for (int nt = 0; nt < 2; nt++) {
                const int col = wn_s + nt * 8 + 2 * t;
                *(float2*)&Ss[row * SST + col] =
                    make_float2(s[mt][nt][0] * SCALE, s[mt][nt][1] * SCALE);
                *(float2*)&Ss[(row + 8) * SST + col] =
                    make_float2(s[mt][nt][2] * SCALE, s[mt][nt][3] * SCALE);
            }
        }
        __syncthreads();

        {
            const int row = tid >> 2;
            const int t4  = tid & 3;
            float* sr = Ss + row * SST + t4 * 16;
            const float mold = rmax[row];
            float mx = mold;
#pragma unroll
            for (int j = 0; j < 16; j++) mx = fmaxf(mx, sr[j]);
            mx = fmaxf(mx, __shfl_xor_sync(0xffffffffu, mx, 1));
            mx = fmaxf(mx, __shfl_xor_sync(0xffffffffu, mx, 2));
            float p = 0.f;
            unsigned* su = (unsigned*)sr;
#pragma unroll
            for (int j = 0; j < 16; j++) {
                const float e = __expf(sr[j] - mx);
                p += e;
                su[j] = cvt1_tf32(e);
            }
            p += __shfl_xor_sync(0xffffffffu, p, 1);
            p += __shfl_xor_sync(0xffffffffu, p, 2);
            if (t4 == 0) {
                const float a = __expf(mold - mx);
                rsum[row] = rsum[row] * a + p;
                rmax[row] = mx;
                alp[row]  = a;
            }
        }
        __syncthreads();

        float alo[4], ahi[4];
#pragma unroll
        for (int nt = 0; nt < 4; nt++) {
            const int q = wn_p + nt * 8 + 2 * t;
            alo[nt] = alp[q];
            ahi[nt] = alp[q + 1];
        }
#pragma unroll
        for (int mt = 0; mt < 2; mt++)
#pragma unroll
            for (int nt = 0; nt < 4; nt++) {
                o[mt][nt][0] *= alo[nt];
                o[mt][nt][1] *= ahi[nt];
                o[mt][nt][2] *= alo[nt];
                o[mt][nt][3] *= ahi[nt];
            }

#pragma unroll
        for (int kk = 0; kk < 8; kk++) {
            const int ks = kk * 8;
            unsigned af[2][4], bf[4][2];
#pragma unroll
            for (int mt = 0; mt < 2; mt++) {
                const int m = wm_p + mt * 16 + g;
                af[mt][0] = Vu[(ks + t) * VST + m];
                af[mt][1] = Vu[(ks + t) * VST + m + 8];
                af[mt][2] = Vu[(ks + t + 4) * VST + m];
                af[mt][3] = Vu[(ks + t + 4) * VST + m + 8];
            }
#pragma unroll
            for (int nt = 0; nt < 4; nt++) {
                const int n = wn_p + nt * 8 + g;
                bf[nt][0] = Su[n * SST + ks + t];
                bf[nt][1] = Su[n * SST + ks + t + 4];
            }
#pragma unroll
            for (int mt = 0; mt < 2; mt++)
#pragma unroll
                for (int nt = 0; nt < 4; nt++)
                    mma_tf32(o[mt][nt], af[mt], bf[nt]);
        }
    }
    __syncthreads();

    float ilo[4], ihi[4];
#pragma unroll
    for (int nt = 0; nt < 4; nt++) {
        const int q = wn_p + nt * 8 + 2 * t;
        ilo[nt] = 1.0f / rsum[q];
        ihi[nt] = 1.0f / rsum[q + 1];
    }
    unsigned* Cu = (unsigned*)g_Ctx;
#pragma unroll
    for (int mt = 0; mt < 2; mt++) {
        const int d = wm_p + mt * 16 + g;
#pragma unroll
        for (int nt = 0; nt < 4; nt++) {
            const int q = wn_p + nt * 8 + 2 * t;
            Cu[base + (size_t)(q0 + q)     * HID + d]     = cvt1_tf32(o[mt][nt][0] * ilo[nt]);
            Cu[base + (size_t)(q0 + q + 1) * HID + d]     = cvt1_tf32(o[mt][nt][1] * ihi[nt]);
            Cu[base + (size_t)(q0 + q)     * HID + d + 8] = cvt1_tf32(o[mt][nt][2] * ilo[nt]);
            Cu[base + (size_t)(q0 + q + 1) * HID + d + 8] = cvt1_tf32(o[mt][nt][3] * ihi[nt]);
        }
    }
}

// ---------------------------------------------------------------------------
// Launch
// ---------------------------------------------------------------------------
extern "C" void kernel_launch(void* const* d_in, const int* in_sizes, int n_in,
                              void* d_out, int out_size)
{
    const float* x  = (const float*)d_in[0];
    const float* Wq = (const float*)d_in[1];
    const float* Wk = (const float*)d_in[2];
    const float* Wv = (const float*)d_in[3];
    const float* Wo = (const float*)d_in[4];
    float* out = (float*)d_out;

    float *pQ, *pK, *pV, *pC, *pXr, *pWr;
    cudaGetSymbolAddress((void**)&pQ,  g_Q);
    cudaGetSymbolAddress((void**)&pK,  g_K);
    cudaGetSymbolAddress((void**)&pV,  g_V);
    cudaGetSymbolAddress((void**)&pC,  g_Ctx);
    cudaGetSymbolAddress((void**)&pXr, g_xr);
    cudaGetSymbolAddress((void**)&pWr, g_Wr);

    const int WSZ = HID * HID;

    round_tf32_kernel<<<1024, 256>>>((const float4*)x,  (float4*)pXr, MROWS * HID / 4);
    round_tf32_kernel<<<512, 256>>>((const float4*)Wq, (float4*)(pWr + 0 * WSZ), WSZ / 4);
    round_tf32_kernel<<<512, 256>>>((const float4*)Wk, (float4*)(pWr + 1 * WSZ), WSZ / 4);
    round_tf32_kernel<<<512, 256>>>((const float4*)Wv, (float4*)(pWr + 2 * WSZ), WSZ / 4);
    round_tf32_kernel<<<512, 256>>>((const float4*)Wo, (float4*)(pWr + 3 * WSZ), WSZ / 4);

    dim3 gg(HID / 128, MROWS / 128);   // (16, 32)

    cudaFuncSetAttribute(gemm_tf32_pipe,
                         cudaFuncAttributeMaxDynamicSharedMemorySize, GEMM_SMEM);

    gemm_tf32_pipe<<<gg, 256, GEMM_SMEM>>>(pXr, pWr + 0 * WSZ, pQ, MROWS, HID, HID);
    gemm_tf32_pipe<<<gg, 256, GEMM_SMEM>>>(pXr, pWr + 1 * WSZ, pK, MROWS, HID, HID);
    gemm_tf32_pipe<<<gg, 256, GEMM_SMEM>>>(pXr, pWr + 2 * WSZ, pV, MROWS, HID, HID);

    rope_kernel<<<MROWS, 256>>>();

    cudaFuncSetAttribute(flash_tf32,
                         cudaFuncAttributeMaxDynamicSharedMemorySize, FLASH_SMEM);
    flash_tf32<<<dim3(S_LEN / 64, 2 * NHEAD), 256, FLASH_SMEM>>>();

    gemm_tf32_pipe<<<gg, 256, GEMM_SMEM>>>(pC, pWr + 3 * WSZ, out, MROWS, HID, HID);
}

// round 7
// speedup vs baseline: 3.8807x; 1.0159x over previous
#include <cuda_runtime.h>
#include <math.h>

#define S_LEN 2048
#define HID   2048
#define NHEAD 16
#define HD    128
#define MROWS 4096
#define SCALE 0.08838834764831845f

// ---------------------------------------------------------------------------
// Global scratch
// ---------------------------------------------------------------------------
__device__ float g_Q[MROWS * HID];
__device__ float g_K[MROWS * HID];
__device__ float g_V[MROWS * HID];
__device__ float g_Ctx[MROWS * HID];
__device__ float g_xr[MROWS * HID];
__device__ float g_Wr[4 * HID * HID];   // Wq,Wk,Wv contiguous (6144x2048) + Wo

// ---------------------------------------------------------------------------
// Helpers
// ---------------------------------------------------------------------------
__device__ __forceinline__ uint4 cvt4_tf32(float4 v)
{
    uint4 r;
    asm("cvt.rna.tf32.f32 %0, %1;" : "=r"(r.x) : "f"(v.x));
    asm("cvt.rna.tf32.f32 %0, %1;" : "=r"(r.y) : "f"(v.y));
    asm("cvt.rna.tf32.f32 %0, %1;" : "=r"(r.z) : "f"(v.z));
    asm("cvt.rna.tf32.f32 %0, %1;" : "=r"(r.w) : "f"(v.w));
    return r;
}
__device__ __forceinline__ unsigned cvt1_tf32(float v)
{
    unsigned r;
    asm("cvt.rna.tf32.f32 %0, %1;" : "=r"(r) : "f"(v));
    return r;
}
__device__ __forceinline__ void mma_tf32(float* c, const unsigned* a, const unsigned* b)
{
    asm volatile(
        "mma.sync.aligned.m16n8k8.row.col.f32.tf32.tf32.f32 "
        "{%0,%1,%2,%3}, {%4,%5,%6,%7}, {%8,%9}, {%0,%1,%2,%3};\n"
        : "+f"(c[0]), "+f"(c[1]), "+f"(c[2]), "+f"(c[3])
        : "r"(a[0]), "r"(a[1]), "r"(a[2]), "r"(a[3]),
          "r"(b[0]), "r"(b[1]));
}
__device__ __forceinline__ void cp_async16(unsigned saddr, const void* gaddr)
{
    asm volatile("cp.async.cg.shared.global [%0], [%1], 16;\n"
                 :: "r"(saddr), "l"(gaddr));
}
__device__ __forceinline__ void cp_commit()
{
    asm volatile("cp.async.commit_group;\n" ::: "memory");
}

// ---------------------------------------------------------------------------
// Pre-round to tf32
// ---------------------------------------------------------------------------
__global__ void round_tf32_kernel(const float4* __restrict__ src,
                                  float4* __restrict__ dst, int n4)
{
    for (int i = blockIdx.x * blockDim.x + threadIdx.x; i < n4;
         i += gridDim.x * blockDim.x) {
        uint4 u = cvt4_tf32(src[i]);
        dst[i] = *(float4*)&u;
    }
}

// ---------------------------------------------------------------------------
// Pipelined TF32 GEMM. C = A[M,K] * B[*,K]^T, tf32-representable inputs.
// CTA 128x128, K-tile 16, 4-stage cp.async, 256 threads, warp tile 64x32.
// QKV=true: B has 48*128 rows (Wq;Wk;Wv stacked); output column block
// (blockIdx.x & 15) routed to C0/C1/C2 by blockIdx.x >> 4, stride Nout.
// QKV=false: plain C0[M,Nout], col block = blockIdx.x.
// ---------------------------------------------------------------------------
#define GSTG   4
#define GS_MAT 2560              // words per matrix per stage (128*20)
#define GS_STG (2 * GS_MAT)
#define GEMM_SMEM (GSTG * GS_STG * 4)

template<bool QKV>
__global__ __launch_bounds__(256, 2)
void gemm_tf32_pipe(const float* __restrict__ A, const float* __restrict__ B,
                    float* __restrict__ C0, float* __restrict__ C1,
                    float* __restrict__ C2, int M, int Nout, int K)
{
    extern __shared__ unsigned sh[];

    const int tid  = threadIdx.x;
    const int lane = tid & 31;
    const int warp = tid >> 5;
    const int g    = lane >> 2;
    const int t    = lane & 3;
    const int wm   = (warp & 1) * 64;
    const int wn   = (warp >> 1) * 32;

    const int lr = tid >> 2;          // 0..63
    const int lk = (tid & 3) * 4;     // 0,4,8,12

    const float* Ag = A + (size_t)(blockIdx.y * 128 + lr) * K + lk;
    const float* Bg = B + (size_t)(blockIdx.x * 128 + lr) * K + lk;
    const size_t strd = (size_t)64 * K;

    const unsigned shbase = (unsigned)__cvta_generic_to_shared(sh);
    const unsigned sA0 = shbase + (lr * 20 + lk) * 4;
    const unsigned sA1 = shbase + ((lr + 64) * 20 + lk) * 4;

    const int ntiles = K / 16;

    float c[4][4][4];
#pragma unroll
    for (int i = 0; i < 4; i++)
#pragma unroll
        for (int j = 0; j < 4; j++)
#pragma unroll
            for (int q = 0; q < 4; q++) c[i][j][q] = 0.f;

#pragma unroll
    for (int s = 0; s < GSTG - 1; s++) {
        const unsigned so = s * GS_STG * 4;
        const int k0 = s * 16;
        cp_async16(sA0 + so, Ag + k0);
        cp_async16(sA1 + so, Ag + k0 + strd);
        cp_async16(sA0 + so + GS_MAT * 4, Bg + k0);
        cp_async16(sA1 + so + GS_MAT * 4, Bg + k0 + strd);
        cp_commit();
    }

    for (int i = 0; i < ntiles; i++) {
        asm volatile("cp.async.wait_group 2;\n" ::: "memory");
        __syncthreads();

        const unsigned* As = sh + (i & (GSTG - 1)) * GS_STG;
        const unsigned* Bs = As + GS_MAT;

        unsigned af[2][4][4], bf[2][4][2];

#pragma unroll
        for (int mt = 0; mt < 4; mt++) {
            const int m = wm + mt * 16 + g;
            af[0][mt][0] = As[m * 20 + t];
            af[0][mt][1] = As[(m + 8) * 20 + t];
            af[0][mt][2] = As[m * 20 + t + 4];
            af[0][mt][3] = As[(m + 8) * 20 + t + 4];
        }
#pragma unroll
        for (int nt = 0; nt < 4; nt++) {
            const int n = wn + nt * 8 + g;
            bf[0][nt][0] = Bs[n * 20 + t];
            bf[0][nt][1] = Bs[n * 20 + t + 4];
        }

        if (i + GSTG - 1 < ntiles) {
            const int s = (i + GSTG - 1) & (GSTG - 1);
            const unsigned so = s * GS_STG * 4;
            const int k0 = (i + GSTG - 1) * 16;
            cp_async16(sA0 + so, Ag + k0);
            cp_async16(sA1 + so, Ag + k0 + strd);
            cp_async16(sA0 + so + GS_MAT * 4, Bg + k0);
            cp_async16(sA1 + so + GS_MAT * 4, Bg + k0 + strd);
        }
        cp_commit();

#pragma unroll
        for (int mt = 0; mt < 4; mt++) {
            const int m = wm + mt * 16 + g;
            af[1][mt][0] = As[m * 20 + 8 + t];
            af[1][mt][1] = As[(m + 8) * 20 + 8 + t];
            af[1][mt][2] = As[m * 20 + 8 + t + 4];
            af[1][mt][3] = As[(m + 8) * 20 + 8 + t + 4];
        }
#pragma unroll
        for (int nt = 0; nt < 4; nt++) {
            const int n = wn + nt * 8 + g;
            bf[1][nt][0] = Bs[n * 20 + 8 + t];
            bf[1][nt][1] = Bs[n * 20 + 8 + t + 4];
        }

#pragma unroll
        for (int mt = 0; mt < 4; mt++)
#pragma unroll
            for (int nt = 0; nt < 4; nt++)
                mma_tf32(c[mt][nt], af[0][mt], bf[0][nt]);
#pragma unroll
        for (int mt = 0; mt < 4; mt++)
#pragma unroll
            for (int nt = 0; nt < 4; nt++)
                mma_tf32(c[mt][nt], af[1][mt], bf[1][nt]);
    }

    // epilogue: route output
    float* Cb;
    size_t colbase;
    if (QKV) {
        const int seg = blockIdx.x >> 4;
        Cb = (seg == 0) ? C0 : (seg == 1) ? C1 : C2;
        colbase = (size_t)(blockIdx.x & 15) * 128;
    } else {
        Cb = C0;
        colbase = (size_t)blockIdx.x * 128;
    }

#pragma unroll
    for (int mt = 0; mt < 4; mt++) {
        const size_t row = (size_t)blockIdx.y * 128 + wm + mt * 16 + g;
#pragma unroll
        for (int nt = 0; nt < 4; nt++) {
            const size_t col = colbase + wn + nt * 8 + 2 * t;
            *(float2*)(Cb + row * Nout + col) =
                make_float2(c[mt][nt][0], c[mt][nt][1]);
            *(float2*)(Cb + (row + 8) * Nout + col) =
                make_float2(c[mt][nt][2], c[mt][nt][3]);
        }
    }
}

// ---------------------------------------------------------------------------
// RoPE (unchanged)
// ---------------------------------------------------------------------------
__global__ void rope_kernel()
{
    const int row = blockIdx.x;
    const int s   = row & (S_LEN - 1);
    for (int t = threadIdx.x; t < NHEAD * 64; t += 256) {
        const int h = t >> 6;
        const int i = t & 63;
        float inv = powf(10000.0f, -((float)(2 * i)) / 128.0f);
        float ang = (float)s * inv;
        float sn, cs;
        sincosf(ang, &sn, &cs);
        const int idx = row * HID + h * HD + i;
        float q1 = g_Q[idx], q2 = g_Q[idx + 64];
        g_Q[idx]      = q1 * cs - q2 * sn;
        g_Q[idx + 64] = q1 * sn + q2 * cs;
        float k1 = g_K[idx], k2 = g_K[idx + 64];
        g_K[idx]      = k1 * cs - k2 * sn;
        g_K[idx + 64] = k1 * sn + k2 * cs;
    }
}

// ---------------------------------------------------------------------------
// TF32 flash attention (unchanged; writes Ctx tf32-rounded)
// ---------------------------------------------------------------------------
#define QST 132
#define KST 132
#define VST 136
#define SST 68
#define FLASH_SMEM (30144 * 4)

__global__ __launch_bounds__(256, 1)
void flash_tf32()
{
    extern __shared__ float sm[];
    float* Qs   = sm;
    float* Ks   = sm + 8448;
    float* Vs   = sm + 16896;
    float* Ss   = sm + 25600;
    float* rmax = sm + 29952;
    float* rsum = sm + 30016;
    float* alp  = sm + 30080;
    unsigned* Qu = (unsigned*)Qs;
    unsigned* Ku = (unsigned*)Ks;
    unsigned* Vu = (unsigned*)Vs;
    unsigned* Su = (unsigned*)Ss;

    const int tid  = threadIdx.x;
    const int lane = tid & 31;
    const int warp = tid >> 5;
    const int g    = lane >> 2;
    const int t    = lane & 3;
    const int q0   = blockIdx.x * 64;
    const int b    = blockIdx.y >> 4;
    const int h    = blockIdx.y & 15;
    const size_t base = (size_t)(b * S_LEN) * HID + (size_t)h * HD;

    const int wm_s = (warp & 1) * 32;
    const int wn_s = (warp >> 1) * 16;
    const int wm_p = (warp & 3) * 32;
    const int wn_p = (warp >> 2) * 32;

#pragma unroll
    for (int i = 0; i < 8; i++) {
        const int r = warp * 8 + i;
        float4 v = *(const float4*)&g_Q[base + (size_t)(q0 + r) * HID + lane * 4];
        *(uint4*)&Qu[r * QST + lane * 4] = cvt4_tf32(v);
    }
    if (tid < 64) { rmax[tid] = -1e30f; rsum[tid] = 0.f; }

    float o[2][4][4];
#pragma unroll
    for (int mt = 0; mt < 2; mt++)
#pragma unroll
        for (int nt = 0; nt < 4; nt++)
#pragma unroll
            for (int j = 0; j < 4; j++) o[mt][nt][j] = 0.f;

    for (int kt = 0; kt < S_LEN; kt += 64) {
        __syncthreads();
#pragma unroll
        for (int i = 0; i < 8; i++) {
            const int r = warp * 8 + i;
            const size_t go = base + (size_t)(kt + r) * HID + lane * 4;
            *(uint4*)&Ku[r * KST + lane * 4] = cvt4_tf32(*(const float4*)&g_K[go]);
            *(uint4*)&Vu[r * VST + lane * 4] = cvt4_tf32(*(const float4*)&g_V[go]);
        }
        __syncthreads();

        float s[2][2][4];
#pragma unroll
        for (int mt = 0; mt < 2; mt++)
#pragma unroll
            for (int nt = 0; nt < 2; nt++)
#pragma unroll
                for (int j = 0; j < 4; j++) s[mt][nt][j] = 0.f;

#pragma unroll
        for (int kk = 0; kk < 16; kk++) {
            const int ks = kk * 8 + t;
            unsigned af[2][4], bf[2][2];
#pragma unroll
            for (int mt = 0; mt < 2; mt++) {
                const int m = wm_s + mt * 16 + g;
                af[mt][0] = Qu[m * QST + ks];
                af[mt][1] = Qu[(m + 8) * QST + ks];
                af[mt][2] = Qu[m * QST + ks + 4];
                af[mt][3] = Qu[(m + 8) * QST + ks + 4];
            }
#pragma unroll
            for (int nt = 0; nt < 2; nt++) {
                const int n = wn_s + nt * 8 + g;
                bf[nt][0] = Ku[n * KST + ks];
                bf[nt][1] = Ku[n * KST + ks + 4];
            }
#pragma unroll
            for (int mt = 0; mt < 2; mt++)
#pragma unroll
                for (int nt = 0; nt < 2; nt++)
                    mma_tf32(s[mt][nt], af[mt], bf[nt]);
        }
#pragma unroll
        for (int mt = 0; mt < 2; mt++) {
            const int row = wm_s + mt * 16 + g;
#pragma unroll
            for (int nt = 0; nt < 2; nt++) {
                const int col = wn_s + nt * 8 + 2 * t;
                *(float2*)&Ss[row * SST + col] =
                    make_float2(s[mt][nt][0] * SCALE, s[mt][nt][1] * SCALE);
                *(float2*)&Ss[(row + 8) * SST + col] =
                    make_float2(s[mt][nt][2] * SCALE, s[mt][nt][3] * SCALE);
            }
        }
        __syncthreads();

        {
            const int row = tid >> 2;
            const int t4  = tid & 3;
            float* sr = Ss + row * SST + t4 * 16;
            const float mold = rmax[row];
            float mx = mold;
#pragma unroll
            for (int j = 0; j < 16; j++) mx = fmaxf(mx, sr[j]);
            mx = fmaxf(mx, __shfl_xor_sync(0xffffffffu, mx, 1));
            mx = fmaxf(mx, __shfl_xor_sync(0xffffffffu, mx, 2));
            float p = 0.f;
            unsigned* su = (unsigned*)sr;
#pragma unroll
            for (int j = 0; j < 16; j++) {
                const float e = __expf(sr[j] - mx);
                p += e;
                su[j] = cvt1_tf32(e);
            }
            p += __shfl_xor_sync(0xffffffffu, p, 1);
            p += __shfl_xor_sync(0xffffffffu, p, 2);
            if (t4 == 0) {
                const float a = __expf(mold - mx);
                rsum[row] = rsum[row] * a + p;
                rmax[row] = mx;
                alp[row]  = a;
            }
        }
        __syncthreads();

        float alo[4], ahi[4];
#pragma unroll
        for (int nt = 0; nt < 4; nt++) {
            const int q = wn_p + nt * 8 + 2 * t;
            alo[nt] = alp[q];
            ahi[nt] = alp[q + 1];
        }
#pragma unroll
        for (int mt = 0; mt < 2; mt++)
#pragma unroll
            for (int nt = 0; nt < 4; nt++) {
                o[mt][nt][0] *= alo[nt];
                o[mt][nt][1] *= ahi[nt];
                o[mt][nt][2] *= alo[nt];
                o[mt][nt][3] *= ahi[nt];
            }

#pragma unroll
        for (int kk = 0; kk < 8; kk++) {
            const int ks = kk * 8;
            unsigned af[2][4], bf[4][2];
#pragma unroll
            for (int mt = 0; mt < 2; mt++) {
                const int m = wm_p + mt * 16 + g;
                af[mt][0] = Vu[(ks + t) * VST + m];
                af[mt][1] = Vu[(ks + t) * VST + m + 8];
                af[mt][2] = Vu[(ks + t + 4) * VST + m];
                af[mt][3] = Vu[(ks + t + 4) * VST + m + 8];
            }
#pragma unroll
            for (int nt = 0; nt < 4; nt++) {
                const int n = wn_p + nt * 8 + g;
                bf[nt][0] = Su[n * SST + ks + t];
                bf[nt][1] = Su[n * SST + ks + t + 4];
            }
#pragma unroll
            for (int mt = 0; mt < 2; mt++)
#pragma unroll
                for (int nt = 0; nt < 4; nt++)
                    mma_tf32(o[mt][nt], af[mt], bf[nt]);
        }
    }
    __syncthreads();

    float ilo[4], ihi[4];
#pragma unroll
    for (int nt = 0; nt < 4; nt++) {
        const int q = wn_p + nt * 8 + 2 * t;
        ilo[nt] = 1.0f / rsum[q];
        ihi[nt] = 1.0f / rsum[q + 1];
    }
    unsigned* Cu = (unsigned*)g_Ctx;
#pragma unroll
    for (int mt = 0; mt < 2; mt++) {
        const int d = wm_p + mt * 16 + g;
#pragma unroll
        for (int nt = 0; nt < 4; nt++) {
            const int q = wn_p + nt * 8 + 2 * t;
            Cu[base + (size_t)(q0 + q)     * HID + d]     = cvt1_tf32(o[mt][nt][0] * ilo[nt]);
            Cu[base + (size_t)(q0 + q + 1) * HID + d]     = cvt1_tf32(o[mt][nt][1] * ihi[nt]);
            Cu[base + (size_t)(q0 + q)     * HID + d + 8] = cvt1_tf32(o[mt][nt][2] * ilo[nt]);
            Cu[base + (size_t)(q0 + q + 1) * HID + d + 8] = cvt1_tf32(o[mt][nt][3] * ihi[nt]);
        }
    }
}

// ---------------------------------------------------------------------------
// Launch
// ---------------------------------------------------------------------------
extern "C" void kernel_launch(void* const* d_in, const int* in_sizes, int n_in,
                              void* d_out, int out_size)
{
    const float* x  = (const float*)d_in[0];
    const float* Wq = (const float*)d_in[1];
    const float* Wk = (const float*)d_in[2];
    const float* Wv = (const float*)d_in[3];
    const float* Wo = (const float*)d_in[4];
    float* out = (float*)d_out;

    float *pQ, *pK, *pV, *pC, *pXr, *pWr;
    cudaGetSymbolAddress((void**)&pQ,  g_Q);
    cudaGetSymbolAddress((void**)&pK,  g_K);
    cudaGetSymbolAddress((void**)&pV,  g_V);
    cudaGetSymbolAddress((void**)&pC,  g_Ctx);
    cudaGetSymbolAddress((void**)&pXr, g_xr);
    cudaGetSymbolAddress((void**)&pWr, g_Wr);

    const int WSZ = HID * HID;

    round_tf32_kernel<<<1024, 256>>>((const float4*)x,  (float4*)pXr, MROWS * HID / 4);
    round_tf32_kernel<<<512, 256>>>((const float4*)Wq, (float4*)(pWr + 0 * WSZ), WSZ / 4);
    round_tf32_kernel<<<512, 256>>>((const float4*)Wk, (float4*)(pWr + 1 * WSZ), WSZ / 4);
    round_tf32_kernel<<<512, 256>>>((const float4*)Wv, (float4*)(pWr + 2 * WSZ), WSZ / 4);
    round_tf32_kernel<<<512, 256>>>((const float4*)Wo, (float4*)(pWr + 3 * WSZ), WSZ / 4);

    cudaFuncSetAttribute(gemm_tf32_pipe<true>,
                         cudaFuncAttributeMaxDynamicSharedMemorySize, GEMM_SMEM);
    cudaFuncSetAttribute(gemm_tf32_pipe<false>,
                         cudaFuncAttributeMaxDynamicSharedMemorySize, GEMM_SMEM);

    // Fused QKV projection: B = [Wq;Wk;Wv] (6144 x 2048), one launch
    gemm_tf32_pipe<true><<<dim3(48, MROWS / 128), 256, GEMM_SMEM>>>(
        pXr, pWr, pQ, pK, pV, MROWS, HID, HID);

    rope_kernel<<<MROWS, 256>>>();

    cudaFuncSetAttribute(flash_tf32,
                         cudaFuncAttributeMaxDynamicSharedMemorySize, FLASH_SMEM);
    flash_tf32<<<dim3(S_LEN / 64, 2 * NHEAD), 256, FLASH_SMEM>>>();

    gemm_tf32_pipe<false><<<dim3(16, MROWS / 128), 256, GEMM_SMEM>>>(
        pC, pWr + 3 * WSZ, out, out, out, MROWS, HID, HID);
}

// round 8
// speedup vs baseline: 4.1929x; 1.0805x over previous
#include <cuda_runtime.h>
#include <math.h>

#define S_LEN 2048
#define HID   2048
#define NHEAD 16
#define HD    128
#define MROWS 4096
#define SCALE 0.08838834764831845f

// ---------------------------------------------------------------------------
// Global scratch
// ---------------------------------------------------------------------------
__device__ float g_Q[MROWS * HID];
__device__ float g_K[MROWS * HID];
__device__ float g_V[MROWS * HID];
__device__ float g_Ctx[MROWS * HID];
__device__ float g_xr[MROWS * HID];
__device__ float g_Wr[4 * HID * HID];   // Wq,Wk,Wv contiguous (6144x2048) + Wo

// ---------------------------------------------------------------------------
// Helpers
// ---------------------------------------------------------------------------
__device__ __forceinline__ uint4 cvt4_tf32(float4 v)
{
    uint4 r;
    asm("cvt.rna.tf32.f32 %0, %1;" : "=r"(r.x) : "f"(v.x));
    asm("cvt.rna.tf32.f32 %0, %1;" : "=r"(r.y) : "f"(v.y));
    asm("cvt.rna.tf32.f32 %0, %1;" : "=r"(r.z) : "f"(v.z));
    asm("cvt.rna.tf32.f32 %0, %1;" : "=r"(r.w) : "f"(v.w));
    return r;
}
__device__ __forceinline__ unsigned cvt1_tf32(float v)
{
    unsigned r;
    asm("cvt.rna.tf32.f32 %0, %1;" : "=r"(r) : "f"(v));
    return r;
}
__device__ __forceinline__ void mma_tf32(float* c, const unsigned* a, const unsigned* b)
{
    asm volatile(
        "mma.sync.aligned.m16n8k8.row.col.f32.tf32.tf32.f32 "
        "{%0,%1,%2,%3}, {%4,%5,%6,%7}, {%8,%9}, {%0,%1,%2,%3};\n"
        : "+f"(c[0]), "+f"(c[1]), "+f"(c[2]), "+f"(c[3])
        : "r"(a[0]), "r"(a[1]), "r"(a[2]), "r"(a[3]),
          "r"(b[0]), "r"(b[1]));
}
__device__ __forceinline__ void cp_async16(unsigned saddr, const void* gaddr)
{
    asm volatile("cp.async.cg.shared.global [%0], [%1], 16;\n"
                 :: "r"(saddr), "l"(gaddr));
}
__device__ __forceinline__ void cp_commit()
{
    asm volatile("cp.async.commit_group;\n" ::: "memory");
}
__device__ __forceinline__ void cp_wait1()
{
    asm volatile("cp.async.wait_group 1;\n" ::: "memory");
}

// ---------------------------------------------------------------------------
// Pre-round to tf32
// ---------------------------------------------------------------------------
__global__ void round_tf32_kernel(const float4* __restrict__ src,
                                  float4* __restrict__ dst, int n4)
{
    for (int i = blockIdx.x * blockDim.x + threadIdx.x; i < n4;
         i += gridDim.x * blockDim.x) {
        uint4 u = cvt4_tf32(src[i]);
        dst[i] = *(float4*)&u;
    }
}

// ---------------------------------------------------------------------------
// Pipelined TF32 GEMM. C = A[M,K] * B[*,K]^T, tf32-representable inputs.
// CTA 128x128, K-tile 32, 3-stage cp.async, 256 threads, warp tile 64x32.
// Smem row stride 36 words (144B) -> fragment LDS bank = lane id (no conflict).
// QKV=true: B rows = [Wq;Wk;Wv]; col block (bx&15) routed by bx>>4.
// ---------------------------------------------------------------------------
#define G2STG  3
#define G2MATW 4608              // words per matrix per stage (128*36)
#define G2STGW 9216
#define GEMM_SMEM (G2STG * G2STGW * 4)   // 110592 B

#define ISSUE_STAGE(st, k0) do {                                              \
    const unsigned so_ = shb + (unsigned)(st) * (G2STGW * 4);                 \
    _Pragma("unroll")                                                         \
    for (int j_ = 0; j_ < 4; j_++) {                                          \
        const int c_ = tid + 256 * j_, r_ = c_ >> 3, kq_ = c_ & 7;            \
        cp_async16(so_ + r_ * 144 + kq_ * 16,                                 \
                   Abase + (size_t)r_ * K + (k0) + kq_ * 4);                  \
        cp_async16(so_ + G2MATW * 4 + r_ * 144 + kq_ * 16,                    \
                   Bbase + (size_t)r_ * K + (k0) + kq_ * 4);                  \
    } } while (0)

template<bool QKV>
__global__ __launch_bounds__(256, 2)
void gemm_tf32_pipe(const float* __restrict__ A, const float* __restrict__ B,
                    float* __restrict__ C0, float* __restrict__ C1,
                    float* __restrict__ C2, int M, int Nout, int K)
{
    extern __shared__ unsigned sh[];

    const int tid  = threadIdx.x;
    const int lane = tid & 31;
    const int warp = tid >> 5;
    const int g    = lane >> 2;
    const int t    = lane & 3;
    const int wm   = (warp & 1) * 64;
    const int wn   = (warp >> 1) * 32;

    const float* Abase = A + (size_t)blockIdx.y * 128 * K;
    const float* Bbase = B + (size_t)blockIdx.x * 128 * K;
    const unsigned shb = (unsigned)__cvta_generic_to_shared(sh);

    const int ntiles = K / 32;

    float c[4][4][4];
#pragma unroll
    for (int i = 0; i < 4; i++)
#pragma unroll
        for (int j = 0; j < 4; j++)
#pragma unroll
            for (int q = 0; q < 4; q++) c[i][j][q] = 0.f;

    ISSUE_STAGE(0, 0);  cp_commit();
    ISSUE_STAGE(1, 32); cp_commit();

    for (int i = 0; i < ntiles; i++) {
        cp_wait1();
        __syncthreads();   // stage i visible to all; prior compute done

        const unsigned* As = sh + (i % 3) * G2STGW;
        const unsigned* Bs = As + G2MATW;

        unsigned af[2][4][4], bf[2][4][2];

        // sub0 fragments (ks = t)
#pragma unroll
        for (int mt = 0; mt < 4; mt++) {
            const int m = wm + mt * 16 + g;
            af[0][mt][0] = As[m * 36 + t];
            af[0][mt][1] = As[(m + 8) * 36 + t];
            af[0][mt][2] = As[m * 36 + t + 4];
            af[0][mt][3] = As[(m + 8) * 36 + t + 4];
        }
#pragma unroll
        for (int nt = 0; nt < 4; nt++) {
            const int n = wn + nt * 8 + g;
            bf[0][nt][0] = Bs[n * 36 + t];
            bf[0][nt][1] = Bs[n * 36 + t + 4];
        }

        if (i + 2 < ntiles) ISSUE_STAGE((i + 2) % 3, (i + 2) * 32);
        cp_commit();

#pragma unroll
        for (int sub = 0; sub < 4; sub++) {
            const int cur = sub & 1;
            if (sub < 3) {
                const int nxt = cur ^ 1;
                const int ks = (sub + 1) * 8 + t;
#pragma unroll
                for (int mt = 0; mt < 4; mt++) {
                    const int m = wm + mt * 16 + g;
                    af[nxt][mt][0] = As[m * 36 + ks];
                    af[nxt][mt][1] = As[(m + 8) * 36 + ks];
                    af[nxt][mt][2] = As[m * 36 + ks + 4];
                    af[nxt][mt][3] = As[(m + 8) * 36 + ks + 4];
                }
#pragma unroll
                for (int nt = 0; nt < 4; nt++) {
                    const int n = wn + nt * 8 + g;
                    bf[nxt][nt][0] = Bs[n * 36 + ks];
                    bf[nxt][nt][1] = Bs[n * 36 + ks + 4];
                }
            }
#pragma unroll
            for (int mt = 0; mt < 4; mt++)
#pragma unroll
                for (int nt = 0; nt < 4; nt++)
                    mma_tf32(c[mt][nt], af[cur][mt], bf[cur][nt]);
        }
    }

    float* Cb;
    size_t colbase;
    if (QKV) {
        const int seg = blockIdx.x >> 4;
        Cb = (seg == 0) ? C0 : (seg == 1) ? C1 : C2;
        colbase = (size_t)(blockIdx.x & 15) * 128;
    } else {
        Cb = C0;
        colbase = (size_t)blockIdx.x * 128;
    }

#pragma unroll
    for (int mt = 0; mt < 4; mt++) {
        const size_t row = (size_t)blockIdx.y * 128 + wm + mt * 16 + g;
#pragma unroll
        for (int nt = 0; nt < 4; nt++) {
            const size_t col = colbase + wn + nt * 8 + 2 * t;
            *(float2*)(Cb + row * Nout + col) =
                make_float2(c[mt][nt][0], c[mt][nt][1]);
            *(float2*)(Cb + (row + 8) * Nout + col) =
                make_float2(c[mt][nt][2], c[mt][nt][3]);
        }
    }
}

// ---------------------------------------------------------------------------
// RoPE: writes Q,K tf32-rounded (same value flash used to compute at load),
// and rounds V in-place. Bit-identical to previous round-at-load scheme.
// ---------------------------------------------------------------------------
__global__ void rope_kernel()
{
    const int row = blockIdx.x;
    const int s   = row & (S_LEN - 1);
    unsigned* Qu = (unsigned*)g_Q;
    unsigned* Ku = (unsigned*)g_K;
    unsigned* Vu = (unsigned*)g_V;
    for (int t = threadIdx.x; t < NHEAD * 64; t += 256) {
        const int h = t >> 6;
        const int i = t & 63;
        float inv = powf(10000.0f, -((float)(2 * i)) / 128.0f);
        float ang = (float)s * inv;
        float sn, cs;
        sincosf(ang, &sn, &cs);
        const int idx = row * HID + h * HD + i;
        float q1 = g_Q[idx], q2 = g_Q[idx + 64];
        Qu[idx]      = cvt1_tf32(q1 * cs - q2 * sn);
        Qu[idx + 64] = cvt1_tf32(q1 * sn + q2 * cs);
        float k1 = g_K[idx], k2 = g_K[idx + 64];
        Ku[idx]      = cvt1_tf32(k1 * cs - k2 * sn);
        Ku[idx + 64] = cvt1_tf32(k1 * sn + k2 * cs);
    }
    for (int t = threadIdx.x; t < HID; t += 256) {
        const int i = row * HID + t;
        Vu[i] = cvt1_tf32(g_V[i]);
    }
}

// ---------------------------------------------------------------------------
// TF32 flash attention. Bq = Bk = 64, D = 128, 256 threads (8 warps).
// Q/K/V pre-rounded to tf32 -> no cvt in loop; K/V double-buffered cp.async.
// Smem (floats): Qs 64x132 @0, K stages 64x132 @8448/@16896,
//   V stages 64x136 @25344/@34048, Ss 64x68 @42752,
//   rmax@47104 rsum@47168 alp@47232 -> 47296 words (189184 B)
// ---------------------------------------------------------------------------
#define QST 132
#define KST 132
#define VST 136
#define SST 68
#define FK0 8448
#define FV0 25344
#define FSS 42752
#define FLASH_SMEM (47296 * 4)

__global__ __launch_bounds__(256, 1)
void flash_tf32()
{
    extern __shared__ float sm[];
    float* Ss   = sm + FSS;
    float* rmax = sm + 47104;
    float* rsum = sm + 47168;
    float* alp  = sm + 47232;
    unsigned* Qu = (unsigned*)sm;
    unsigned* Su = (unsigned*)Ss;

    const int tid  = threadIdx.x;
    const int lane = tid & 31;
    const int warp = tid >> 5;
    const int g    = lane >> 2;
    const int t    = lane & 3;
    const int q0   = blockIdx.x * 64;
    const int b    = blockIdx.y >> 4;
    const int h    = blockIdx.y & 15;
    const size_t base = (size_t)(b * S_LEN) * HID + (size_t)h * HD;
    const unsigned shb = (unsigned)__cvta_generic_to_shared(sm);

    const int wm_s = (warp & 1) * 32;
    const int wn_s = (warp >> 1) * 16;
    const int wm_p = (warp & 3) * 32;
    const int wn_p = (warp >> 2) * 32;

    // prologue: Q + K/V stage 0 (group 0), K/V stage 1 (group 1)
#pragma unroll
    for (int j = 0; j < 8; j++) {
        const int c = tid + 256 * j, r = c >> 5, cq = c & 31;
        cp_async16(shb + r * (QST * 4) + cq * 16,
                   &g_Q[base + (size_t)(q0 + r) * HID + cq * 4]);
        const size_t go = base + (size_t)r * HID + cq * 4;
        cp_async16(shb + FK0 * 4 + r * (KST * 4) + cq * 16, &g_K[go]);
        cp_async16(shb + FV0 * 4 + r * (VST * 4) + cq * 16, &g_V[go]);
    }
    cp_commit();
#pragma unroll
    for (int j = 0; j < 8; j++) {
        const int c = tid + 256 * j, r = c >> 5, cq = c & 31;
        const size_t go = base + (size_t)(64 + r) * HID + cq * 4;
        cp_async16(shb + (FK0 + KST * 64) * 4 + r * (KST * 4) + cq * 16, &g_K[go]);
        cp_async16(shb + (FV0 + VST * 64) * 4 + r * (VST * 4) + cq * 16, &g_V[go]);
    }
    cp_commit();

    if (tid < 64) { rmax[tid] = -1e30f; rsum[tid] = 0.f; }

    float o[2][4][4];
#pragma unroll
    for (int mt = 0; mt < 2; mt++)
#pragma unroll
        for (int nt = 0; nt < 4; nt++)
#pragma unroll
            for (int j = 0; j < 4; j++) o[mt][nt][j] = 0.f;

    for (int it = 0; it < S_LEN / 64; it++) {
        const int s = it & 1;
        cp_wait1();
        __syncthreads();

        const unsigned* Ku = (unsigned*)(sm + FK0 + s * (KST * 64));
        const unsigned* Vu = (unsigned*)(sm + FV0 + s * (VST * 64));

        // ---- S = Q K^T ----
        float sacc[2][2][4];
#pragma unroll
        for (int mt = 0; mt < 2; mt++)
#pragma unroll
            for (int nt = 0; nt < 2; nt++)
#pragma unroll
                for (int j = 0; j < 4; j++) sacc[mt][nt][j] = 0.f;

#pragma unroll
        for (int kk = 0; kk < 16; kk++) {
            const int ks = kk * 8 + t;
            unsigned af[2][4], bf[2][2];
#pragma unroll
            for (int mt = 0; mt < 2; mt++) {
                const int m = wm_s + mt * 16 + g;
                af[mt][0] = Qu[m * QST + ks];
                af[mt][1] = Qu[(m + 8) * QST + ks];
                af[mt][2] = Qu[m * QST + ks + 4];
                af[mt][3] = Qu[(m + 8) * QST + ks + 4];
            }
#pragma unroll
            for (int nt = 0; nt < 2; nt++) {
                const int n = wn_s + nt * 8 + g;
                bf[nt][0] = Ku[n * KST + ks];
                bf[nt][1] = Ku[n * KST + ks + 4];
            }
#pragma unroll
            for (int mt = 0; mt < 2; mt++)
#pragma unroll
                for (int nt = 0; nt < 2; nt++)
                    mma_tf32(sacc[mt][nt], af[mt], bf[nt]);
        }
#pragma unroll
        for (int mt = 0; mt < 2; mt++) {
            const int row = wm_s + mt * 16 + g;
#pragma unroll
            for (int nt = 0; nt < 2; nt++) {
                const int col = wn_s + nt * 8 + 2 * t;
                *(float2*)&Ss[row * SST + col] =
                    make_float2(sacc[mt][nt][0] * SCALE, sacc[mt][nt][1] * SCALE);
                *(float2*)&Ss[(row + 8) * SST + col] =
                    make_float2(sacc[mt][nt][2] * SCALE, sacc[mt][nt][3] * SCALE);
            }
        }
        __syncthreads();

        // ---- online softmax: 4 threads per row ----
        {
            const int row = tid >> 2;
            const int t4  = tid & 3;
            float* sr = Ss + row * SST + t4 * 16;
            const float mold = rmax[row];
            float mx = mold;
#pragma unroll
            for (int j = 0; j < 16; j++) mx = fmaxf(mx, sr[j]);
            mx = fmaxf(mx, __shfl_xor_sync(0xffffffffu, mx, 1));
            mx = fmaxf(mx, __shfl_xor_sync(0xffffffffu, mx, 2));
            float p = 0.f;
            unsigned* su = (unsigned*)sr;
#pragma unroll
            for (int j = 0; j < 16; j++) {
                const float e = __expf(sr[j] - mx);
                p += e;
                su[j] = cvt1_tf32(e);
            }
            p += __shfl_xor_sync(0xffffffffu, p, 1);
            p += __shfl_xor_sync(0xffffffffu, p, 2);
            if (t4 == 0) {
                const float a = __expf(mold - mx);
                rsum[row] = rsum[row] * a + p;
                rmax[row] = mx;
                alp[row]  = a;
            }
        }
        __syncthreads();

        // ---- alpha rescale + O^T += V^T P^T ----
        float alo[4], ahi[4];
#pragma unroll
        for (int nt = 0; nt < 4; nt++) {
            const int q = wn_p + nt * 8 + 2 * t;
            alo[nt] = alp[q];
            ahi[nt] = alp[q + 1];
        }
#pragma unroll
        for (int mt = 0; mt < 2; mt++)
#pragma unroll
            for (int nt = 0; nt < 4; nt++) {
                o[mt][nt][0] *= alo[nt];
                o[mt][nt][1] *= ahi[nt];
                o[mt][nt][2] *= alo[nt];
                o[mt][nt][3] *= ahi[nt];
            }

#pragma unroll
        for (int kk = 0; kk < 8; kk++) {
            const int ks = kk * 8;
            unsigned af[2][4], bf[4][2];
#pragma unroll
            for (int mt = 0; mt < 2; mt++) {
                const int m = wm_p + mt * 16 + g;
                af[mt][0] = Vu[(ks + t) * VST + m];
                af[mt][1] = Vu[(ks + t) * VST + m + 8];
                af[mt][2] = Vu[(ks + t + 4) * VST + m];
                af[mt][3] = Vu[(ks + t + 4) * VST + m + 8];
            }
#pragma unroll
            for (int nt = 0; nt < 4; nt++) {
                const int n = wn_p + nt * 8 + g;
                bf[nt][0] = Su[n * SST + ks + t];
                bf[nt][1] = Su[n * SST + ks + t + 4];
            }
#pragma unroll
            for (int mt = 0; mt < 2; mt++)
#pragma unroll
                for (int nt = 0; nt < 4; nt++)
                    mma_tf32(o[mt][nt], af[mt], bf[nt]);
        }
        __syncthreads();   // all warps done reading stage s

        if (it + 2 < S_LEN / 64) {
            const int kt2 = (it + 2) * 64;
#pragma unroll
            for (int j = 0; j < 8; j++) {
                const int c = tid + 256 * j, r = c >> 5, cq = c & 31;
                const size_t go = base + (size_t)(kt2 + r) * HID + cq * 4;
                cp_async16(shb + (FK0 + s * (KST * 64)) * 4 + r * (KST * 4) + cq * 16, &g_K[go]);
                cp_async16(shb + (FV0 + s * (VST * 64)) * 4 + r * (VST * 4) + cq * 16, &g_V[go]);
            }
        }
        cp_commit();
    }
    __syncthreads();

    // ---- epilogue ----
    float ilo[4], ihi[4];
#pragma unroll
    for (int nt = 0; nt < 4; nt++) {
        const int q = wn_p + nt * 8 + 2 * t;
        ilo[nt] = 1.0f / rsum[q];
        ihi[nt] = 1.0f / rsum[q + 1];
    }
    unsigned* Cu = (unsigned*)g_Ctx;
#pragma unroll
    for (int mt = 0; mt < 2; mt++) {
        const int d = wm_p + mt * 16 + g;
#pragma unroll
        for (int nt = 0; nt < 4; nt++) {
            const int q = wn_p + nt * 8 + 2 * t;
            Cu[base + (size_t)(q0 + q)     * HID + d]     = cvt1_tf32(o[mt][nt][0] * ilo[nt]);
            Cu[base + (size_t)(q0 + q + 1) * HID + d]     = cvt1_tf32(o[mt][nt][1] * ihi[nt]);
            Cu[base + (size_t)(q0 + q)     * HID + d + 8] = cvt1_tf32(o[mt][nt][2] * ilo[nt]);
            Cu[base + (size_t)(q0 + q + 1) * HID + d + 8] = cvt1_tf32(o[mt][nt][3] * ihi[nt]);
        }
    }
}

// ---------------------------------------------------------------------------
// Launch
// ---------------------------------------------------------------------------
extern "C" void kernel_launch(void* const* d_in, const int* in_sizes, int n_in,
                              void* d_out, int out_size)
{
    const float* x  = (const float*)d_in[0];
    const float* Wq = (const float*)d_in[1];
    const float* Wk = (const float*)d_in[2];
    const float* Wv = (const float*)d_in[3];
    const float* Wo = (const float*)d_in[4];
    float* out = (float*)d_out;

    float *pQ, *pK, *pV, *pC, *pXr, *pWr;
    cudaGetSymbolAddress((void**)&pQ,  g_Q);
    cudaGetSymbolAddress((void**)&pK,  g_K);
    cudaGetSymbolAddress((void**)&pV,  g_V);
    cudaGetSymbolAddress((void**)&pC,  g_Ctx);
    cudaGetSymbolAddress((void**)&pXr, g_xr);
    cudaGetSymbolAddress((void**)&pWr, g_Wr);

    const int WSZ = HID * HID;

    round_tf32_kernel<<<1024, 256>>>((const float4*)x,  (float4*)pXr, MROWS * HID / 4);
    round_tf32_kernel<<<512, 256>>>((const float4*)Wq, (float4*)(pWr + 0 * WSZ), WSZ / 4);
    round_tf32_kernel<<<512, 256>>>((const float4*)Wk, (float4*)(pWr + 1 * WSZ), WSZ / 4);
    round_tf32_kernel<<<512, 256>>>((const float4*)Wv, (float4*)(pWr + 2 * WSZ), WSZ / 4);
    round_tf32_kernel<<<512, 256>>>((const float4*)Wo, (float4*)(pWr + 3 * WSZ), WSZ / 4);

    cudaFuncSetAttribute(gemm_tf32_pipe<true>,
                         cudaFuncAttributeMaxDynamicSharedMemorySize, GEMM_SMEM);
    cudaFuncSetAttribute(gemm_tf32_pipe<false>,
                         cudaFuncAttributeMaxDynamicSharedMemorySize, GEMM_SMEM);

    // Fused QKV projection: B = [Wq;Wk;Wv] (6144 x 2048), one launch
    gemm_tf32_pipe<true><<<dim3(48, MROWS / 128), 256, GEMM_SMEM>>>(
        pXr, pWr, pQ, pK, pV, MROWS, HID, HID);

    rope_kernel<<<MROWS, 256>>>();

    cudaFuncSetAttribute(flash_tf32,
                         cudaFuncAttributeMaxDynamicSharedMemorySize, FLASH_SMEM);
    flash_tf32<<<dim3(S_LEN / 64, 2 * NHEAD), 256, FLASH_SMEM>>>();

    gemm_tf32_pipe<false><<<dim3(16, MROWS / 128), 256, GEMM_SMEM>>>(
        pC, pWr + 3 * WSZ, out, out, out, MROWS, HID, HID);
}

// round 9
// speedup vs baseline: 6.9225x; 1.6510x over previous
#include <cuda_runtime.h>
#include <cuda_fp16.h>
#include <math.h>

#define S_LEN 2048
#define HID   2048
#define NHEAD 16
#define HD    128
#define MROWS 4096
#define SCALE 0.08838834764831845f

// ---------------------------------------------------------------------------
// Global scratch
// ---------------------------------------------------------------------------
__device__ float  g_Q[MROWS * HID];
__device__ float  g_K[MROWS * HID];
__device__ float  g_V[MROWS * HID];
__device__ __half g_xh[MROWS * HID];
__device__ __half g_Wh[4 * HID * HID];    // Wq,Wk,Wv (6144x2048) + Wo
__device__ __half g_Qh[MROWS * HID];
__device__ __half g_Kh[MROWS * HID];
__device__ __half g_Vth[MROWS * HID];     // V^T per (b,h): [128 d][2048 s]
__device__ __half g_Ctxh[MROWS * HID];

// ---------------------------------------------------------------------------
// Helpers
// ---------------------------------------------------------------------------
__device__ __forceinline__ void mma_f16(float* c, const unsigned* a, const unsigned* b)
{
    asm volatile(
        "mma.sync.aligned.m16n8k16.row.col.f32.f16.f16.f32 "
        "{%0,%1,%2,%3}, {%4,%5,%6,%7}, {%8,%9}, {%0,%1,%2,%3};\n"
        : "+f"(c[0]), "+f"(c[1]), "+f"(c[2]), "+f"(c[3])
        : "r"(a[0]), "r"(a[1]), "r"(a[2]), "r"(a[3]),
          "r"(b[0]), "r"(b[1]));
}
__device__ __forceinline__ void cp_async16(unsigned saddr, const void* gaddr)
{
    asm volatile("cp.async.cg.shared.global [%0], [%1], 16;\n"
                 :: "r"(saddr), "l"(gaddr));
}
__device__ __forceinline__ void cp_commit()
{
    asm volatile("cp.async.commit_group;\n" ::: "memory");
}
__device__ __forceinline__ void cp_wait1()
{
    asm volatile("cp.async.wait_group 1;\n" ::: "memory");
}

// ---------------------------------------------------------------------------
// Pre-convert fp32 -> fp16 (rn)
// ---------------------------------------------------------------------------
__global__ void to_half_kernel(const float4* __restrict__ src,
                               uint2* __restrict__ dst, int n4)
{
    for (int i = blockIdx.x * blockDim.x + threadIdx.x; i < n4;
         i += gridDim.x * blockDim.x) {
        float4 v = src[i];
        __half2 h0 = __floats2half2_rn(v.x, v.y);
        __half2 h1 = __floats2half2_rn(v.z, v.w);
        uint2 u;
        u.x = *(unsigned*)&h0;
        u.y = *(unsigned*)&h1;
        dst[i] = u;
    }
}

// ---------------------------------------------------------------------------
// Pipelined FP16 GEMM. C(fp32) = A[M,K]*B[*,K]^T, A,B fp16 K-major.
// CTA 128x128, K-tile 64 halves (128B/row), 3-stage cp.async, 256 threads,
// warp tile 64x32, 4 x k16 subs per tile. Row stride 72 halves (144B):
// fragment LDS bank = (4g+t+c) mod 32 -> conflict-free.
// ---------------------------------------------------------------------------
#define G3STG  3
#define G3MATW 4608              // words per matrix per stage (128*36)
#define G3STGW 9216
#define GEMM_SMEM (G3STG * G3STGW * 4)   // 110592 B

#define ISSUE_STAGE(st, k0) do {                                              \
    const unsigned so_ = shb + (unsigned)(st) * (G3STGW * 4);                 \
    _Pragma("unroll")                                                         \
    for (int j_ = 0; j_ < 4; j_++) {                                          \
        const int c_ = tid + 256 * j_, r_ = c_ >> 3, kq_ = c_ & 7;            \
        cp_async16(so_ + r_ * 144 + kq_ * 16,                                 \
                   Abase + (size_t)r_ * K + (k0) + kq_ * 8);                  \
        cp_async16(so_ + G3MATW * 4 + r_ * 144 + kq_ * 16,                    \
                   Bbase + (size_t)r_ * K + (k0) + kq_ * 8);                  \
    } } while (0)

template<bool QKV>
__global__ __launch_bounds__(256, 2)
void gemm_f16_pipe(const __half* __restrict__ A, const __half* __restrict__ B,
                   float* __restrict__ C0, float* __restrict__ C1,
                   float* __restrict__ C2, int M, int Nout, int K)
{
    extern __shared__ unsigned sh[];

    const int tid  = threadIdx.x;
    const int lane = tid & 31;
    const int warp = tid >> 5;
    const int g    = lane >> 2;
    const int t    = lane & 3;
    const int wm   = (warp & 1) * 64;
    const int wn   = (warp >> 1) * 32;

    const __half* Abase = A + (size_t)blockIdx.y * 128 * K;
    const __half* Bbase = B + (size_t)blockIdx.x * 128 * K;
    const unsigned shb = (unsigned)__cvta_generic_to_shared(sh);

    const int ntiles = K / 64;   // 32

    float c[4][4][4];
#pragma unroll
    for (int i = 0; i < 4; i++)
#pragma unroll
        for (int j = 0; j < 4; j++)
#pragma unroll
            for (int q = 0; q < 4; q++) c[i][j][q] = 0.f;

    ISSUE_STAGE(0, 0);  cp_commit();
    ISSUE_STAGE(1, 64); cp_commit();

    for (int i = 0; i < ntiles; i++) {
        cp_wait1();
        __syncthreads();

        const unsigned* As = sh + (i % 3) * G3STGW;
        const unsigned* Bs = As + G3MATW;

        unsigned af[2][4][4], bf[2][4][2];

        // sub0 fragments (k16 block 0)
#pragma unroll
        for (int mt = 0; mt < 4; mt++) {
            const int m = wm + mt * 16 + g;
            af[0][mt][0] = As[m * 36 + t];
            af[0][mt][1] = As[(m + 8) * 36 + t];
            af[0][mt][2] = As[m * 36 + t + 4];
            af[0][mt][3] = As[(m + 8) * 36 + t + 4];
        }
#pragma unroll
        for (int nt = 0; nt < 4; nt++) {
            const int n = wn + nt * 8 + g;
            bf[0][nt][0] = Bs[n * 36 + t];
            bf[0][nt][1] = Bs[n * 36 + t + 4];
        }

        if (i + 2 < ntiles) ISSUE_STAGE((i + 2) % 3, (i + 2) * 64);
        cp_commit();

#pragma unroll
        for (int sub = 0; sub < 4; sub++) {
            const int cur = sub & 1;
            if (sub < 3) {
                const int nxt = cur ^ 1;
                const int ks = (sub + 1) * 8 + t;
#pragma unroll
                for (int mt = 0; mt < 4; mt++) {
                    const int m = wm + mt * 16 + g;
                    af[nxt][mt][0] = As[m * 36 + ks];
                    af[nxt][mt][1] = As[(m + 8) * 36 + ks];
                    af[nxt][mt][2] = As[m * 36 + ks + 4];
                    af[nxt][mt][3] = As[(m + 8) * 36 + ks + 4];
                }
#pragma unroll
                for (int nt = 0; nt < 4; nt++) {
                    const int n = wn + nt * 8 + g;
                    bf[nxt][nt][0] = Bs[n * 36 + ks];
                    bf[nxt][nt][1] = Bs[n * 36 + ks + 4];
                }
            }
#pragma unroll
            for (int mt = 0; mt < 4; mt++)
#pragma unroll
                for (int nt = 0; nt < 4; nt++)
                    mma_f16(c[mt][nt], af[cur][mt], bf[cur][nt]);
        }
    }

    float* Cb;
    size_t colbase;
    if (QKV) {
        const int seg = blockIdx.x >> 4;
        Cb = (seg == 0) ? C0 : (seg == 1) ? C1 : C2;
        colbase = (size_t)(blockIdx.x & 15) * 128;
    } else {
        Cb = C0;
        colbase = (size_t)blockIdx.x * 128;
    }

#pragma unroll
    for (int mt = 0; mt < 4; mt++) {
        const size_t row = (size_t)blockIdx.y * 128 + wm + mt * 16 + g;
#pragma unroll
        for (int nt = 0; nt < 4; nt++) {
            const size_t col = colbase + wn + nt * 8 + 2 * t;
            *(float2*)(Cb + row * Nout + col) =
                make_float2(c[mt][nt][0], c[mt][nt][1]);
            *(float2*)(Cb + (row + 8) * Nout + col) =
                make_float2(c[mt][nt][2], c[mt][nt][3]);
        }
    }
}

// ---------------------------------------------------------------------------
// RoPE: reads fp32 Q/K, writes fp16 Q/K
// ---------------------------------------------------------------------------
__global__ void rope_kernel()
{
    const int row = blockIdx.x;
    const int s   = row & (S_LEN - 1);
    for (int t = threadIdx.x; t < NHEAD * 64; t += 256) {
        const int h = t >> 6;
        const int i = t & 63;
        float inv = powf(10000.0f, -((float)(2 * i)) / 128.0f);
        float ang = (float)s * inv;
        float sn, cs;
        sincosf(ang, &sn, &cs);
        const int idx = row * HID + h * HD + i;
        float q1 = g_Q[idx], q2 = g_Q[idx + 64];
        g_Qh[idx]      = __float2half_rn(q1 * cs - q2 * sn);
        g_Qh[idx + 64] = __float2half_rn(q1 * sn + q2 * cs);
        float k1 = g_K[idx], k2 = g_K[idx + 64];
        g_Kh[idx]      = __float2half_rn(k1 * cs - k2 * sn);
        g_Kh[idx + 64] = __float2half_rn(k1 * sn + k2 * cs);
    }
}

// ---------------------------------------------------------------------------
// V transpose: fp32 V[b,s,h,d] -> fp16 g_Vth[(b*16+h)*128+d][s]
// ---------------------------------------------------------------------------
__global__ void vtrans_kernel()
{
    __shared__ __half buf[128][65];
    const int s0 = blockIdx.x * 64;
    const int bh = blockIdx.y;
    const int b  = bh >> 4, h = bh & 15;
    const int tid = threadIdx.x;
#pragma unroll 4
    for (int j = 0; j < 32; j++) {
        const int idx = tid + 256 * j;
        const int s = idx >> 7, d = idx & 127;
        buf[d][s] = __float2half_rn(
            g_V[(size_t)(b * S_LEN + s0 + s) * HID + h * HD + d]);
    }
    __syncthreads();
#pragma unroll 4
    for (int j = 0; j < 32; j++) {
        const int idx = tid + 256 * j;
        const int d = idx >> 6, s = idx & 63;
        g_Vth[((size_t)bh * HD + d) * S_LEN + s0 + s] = buf[d][s];
    }
}

// ---------------------------------------------------------------------------
// FP16 flash attention. Bq = Bk = 64, D = 128, 256 threads (8 warps).
// Smem (words): Q 64x68 @0, K stages 64x68 @4352/@8704,
//   Vt stages 128x36 @13056/@17664, Ss(f32) 64x68 @22272,
//   Ps(fp16) 64x36 @26624, rmax@28928 rsum@28992 alp@29056 -> 29120 words
// ---------------------------------------------------------------------------
#define QWS 68
#define KWS 68
#define VWS 36
#define PWS 36
#define SWS 68
#define WK0 4352
#define WV0 13056
#define WSS 22272
#define WPS 26624
#define FLASH_SMEM (29120 * 4)

__global__ __launch_bounds__(256, 1)
void flash_f16()
{
    extern __shared__ float sm[];
    unsigned* S32 = (unsigned*)sm;
    float* Ss   = sm + WSS;
    float* rmax = sm + 28928;
    float* rsum = sm + 28992;
    float* alp  = sm + 29056;

    const int tid  = threadIdx.x;
    const int lane = tid & 31;
    const int warp = tid >> 5;
    const int g    = lane >> 2;
    const int t    = lane & 3;
    const int q0   = blockIdx.x * 64;
    const int b    = blockIdx.y >> 4;
    const int h    = blockIdx.y & 15;
    const size_t base = (size_t)(b * S_LEN) * HID + (size_t)h * HD;
    const size_t vtb  = (size_t)blockIdx.y * HD * S_LEN;
    const unsigned shb = (unsigned)__cvta_generic_to_shared(sm);

    const int wm_s = (warp & 1) * 32;
    const int wn_s = (warp >> 1) * 16;
    const int wm_p = (warp & 3) * 32;
    const int wn_p = (warp >> 2) * 32;

    // prologue: group0 = Q + K0 + V0, group1 = K1 + V1
#pragma unroll
    for (int j = 0; j < 4; j++) {
        const int c = tid + 256 * j;
        const int r = c >> 4, q = c & 15;
        cp_async16(shb + r * 272 + q * 16,
                   &g_Qh[base + (size_t)(q0 + r) * HID + q * 8]);
        cp_async16(shb + WK0 * 4 + r * 272 + q * 16,
                   &g_Kh[base + (size_t)r * HID + q * 8]);
        const int r2 = c >> 3, q2 = c & 7;
        cp_async16(shb + WV0 * 4 + r2 * 144 + q2 * 16,
                   &g_Vth[vtb + (size_t)r2 * S_LEN + q2 * 8]);
    }
    cp_commit();
#pragma unroll
    for (int j = 0; j < 4; j++) {
        const int c = tid + 256 * j;
        const int r = c >> 4, q = c & 15;
        cp_async16(shb + (WK0 + 4352) * 4 + r * 272 + q * 16,
                   &g_Kh[base + (size_t)(64 + r) * HID + q * 8]);
        const int r2 = c >> 3, q2 = c & 7;
        cp_async16(shb + (WV0 + 4608) * 4 + r2 * 144 + q2 * 16,
                   &g_Vth[vtb + (size_t)r2 * S_LEN + 64 + q2 * 8]);
    }
    cp_commit();

    if (tid < 64) { rmax[tid] = -1e30f; rsum[tid] = 0.f; }

    float o[2][4][4];
#pragma unroll
    for (int mt = 0; mt < 2; mt++)
#pragma unroll
        for (int nt = 0; nt < 4; nt++)
#pragma unroll
            for (int j = 0; j < 4; j++) o[mt][nt][j] = 0.f;

    for (int it = 0; it < S_LEN / 64; it++) {
        const int s = it & 1;
        cp_wait1();
        __syncthreads();

        const unsigned kb = WK0 + s * 4352;
        const unsigned vb = WV0 + s * 4608;

        // ---- S = Q K^T (8 x k16) ----
        float sacc[2][2][4];
#pragma unroll
        for (int mt = 0; mt < 2; mt++)
#pragma unroll
            for (int nt = 0; nt < 2; nt++)
#pragma unroll
                for (int j = 0; j < 4; j++) sacc[mt][nt][j] = 0.f;

#pragma unroll
        for (int kk = 0; kk < 8; kk++) {
            const int ko = kk * 8 + t;
            unsigned af[2][4], bf[2][2];
#pragma unroll
            for (int mt = 0; mt < 2; mt++) {
                const int m = wm_s + mt * 16 + g;
                af[mt][0] = S32[m * QWS + ko];
                af[mt][1] = S32[(m + 8) * QWS + ko];
                af[mt][2] = S32[m * QWS + ko + 4];
                af[mt][3] = S32[(m + 8) * QWS + ko + 4];
            }
#pragma unroll
            for (int nt = 0; nt < 2; nt++) {
                const int n = wn_s + nt * 8 + g;
                bf[nt][0] = S32[kb + n * KWS + ko];
                bf[nt][1] = S32[kb + n * KWS + ko + 4];
            }
#pragma unroll
            for (int mt = 0; mt < 2; mt++)
#pragma unroll
                for (int nt = 0; nt < 2; nt++)
                    mma_f16(sacc[mt][nt], af[mt], bf[nt]);
        }
#pragma unroll
        for (int mt = 0; mt < 2; mt++) {
            const int row = wm_s + mt * 16 + g;
#pragma unroll
            for (int nt = 0; nt < 2; nt++) {
                const int col = wn_s + nt * 8 + 2 * t;
                *(float2*)&Ss[row * SWS + col] =
                    make_float2(sacc[mt][nt][0] * SCALE, sacc[mt][nt][1] * SCALE);
                *(float2*)&Ss[(row + 8) * SWS + col] =
                    make_float2(sacc[mt][nt][2] * SCALE, sacc[mt][nt][3] * SCALE);
            }
        }
        __syncthreads();

        // ---- online softmax (4 threads/row), P written fp16 ----
        {
            const int row = tid >> 2;
            const int t4  = tid & 3;
            float* sr = Ss + row * SWS + t4 * 16;
            const float mold = rmax[row];
            float mx = mold;
#pragma unroll
            for (int j = 0; j < 16; j++) mx = fmaxf(mx, sr[j]);
            mx = fmaxf(mx, __shfl_xor_sync(0xffffffffu, mx, 1));
            mx = fmaxf(mx, __shfl_xor_sync(0xffffffffu, mx, 2));
            float p = 0.f;
            unsigned* pw = S32 + WPS + row * PWS + t4 * 8;
#pragma unroll
            for (int j = 0; j < 8; j++) {
                const float e0 = __expf(sr[2 * j]     - mx);
                const float e1 = __expf(sr[2 * j + 1] - mx);
                p += e0;
                p += e1;
                __half2 hp = __floats2half2_rn(e0, e1);
                pw[j] = *(unsigned*)&hp;
            }
            p += __shfl_xor_sync(0xffffffffu, p, 1);
            p += __shfl_xor_sync(0xffffffffu, p, 2);
            if (t4 == 0) {
                const float a = __expf(mold - mx);
                rsum[row] = rsum[row] * a + p;
                rmax[row] = mx;
                alp[row]  = a;
            }
        }
        __syncthreads();

        // ---- alpha rescale + O^T += V^T P^T (4 x k16) ----
        float alo[4], ahi[4];
#pragma unroll
        for (int nt = 0; nt < 4; nt++) {
            const int q = wn_p + nt * 8 + 2 * t;
            alo[nt] = alp[q];
            ahi[nt] = alp[q + 1];
        }
#pragma unroll
        for (int mt = 0; mt < 2; mt++)
#pragma unroll
            for (int nt = 0; nt < 4; nt++) {
                o[mt][nt][0] *= alo[nt];
                o[mt][nt][1] *= ahi[nt];
                o[mt][nt][2] *= alo[nt];
                o[mt][nt][3] *= ahi[nt];
            }

#pragma unroll
        for (int kk = 0; kk < 4; kk++) {
            const int ko = kk * 8 + t;
            unsigned af[2][4], bf[4][2];
#pragma unroll
            for (int mt = 0; mt < 2; mt++) {
                const int m = wm_p + mt * 16 + g;
                af[mt][0] = S32[vb + m * VWS + ko];
                af[mt][1] = S32[vb + (m + 8) * VWS + ko];
                af[mt][2] = S32[vb + m * VWS + ko + 4];
                af[mt][3] = S32[vb + (m + 8) * VWS + ko + 4];
            }
#pragma unroll
            for (int nt = 0; nt < 4; nt++) {
                const int n = wn_p + nt * 8 + g;
                bf[nt][0] = S32[WPS + n * PWS + ko];
                bf[nt][1] = S32[WPS + n * PWS + ko + 4];
            }
#pragma unroll
            for (int mt = 0; mt < 2; mt++)
#pragma unroll
                for (int nt = 0; nt < 4; nt++)
                    mma_f16(o[mt][nt], af[mt], bf[nt]);
        }
        __syncthreads();   // all warps done reading stage s

        if (it + 2 < S_LEN / 64) {
            const int kt2 = (it + 2) * 64;
#pragma unroll
            for (int j = 0; j < 4; j++) {
                const int c = tid + 256 * j;
                const int r = c >> 4, q = c & 15;
                cp_async16(shb + (WK0 + s * 4352) * 4 + r * 272 + q * 16,
                           &g_Kh[base + (size_t)(kt2 + r) * HID + q * 8]);
                const int r2 = c >> 3, q2 = c & 7;
                cp_async16(shb + (WV0 + s * 4608) * 4 + r2 * 144 + q2 * 16,
                           &g_Vth[vtb + (size_t)r2 * S_LEN + kt2 + q2 * 8]);
            }
        }
        cp_commit();
    }
    __syncthreads();

    // ---- epilogue: Ctx (fp16) = O^T / rsum ----
    float ilo[4], ihi[4];
#pragma unroll
    for (int nt = 0; nt < 4; nt++) {
        const int q = wn_p + nt * 8 + 2 * t;
        ilo[nt] = 1.0f / rsum[q];
        ihi[nt] = 1.0f / rsum[q + 1];
    }
#pragma unroll
    for (int mt = 0; mt < 2; mt++) {
        const int d = wm_p + mt * 16 + g;
#pragma unroll
        for (int nt = 0; nt < 4; nt++) {
            const int q = wn_p + nt * 8 + 2 * t;
            g_Ctxh[base + (size_t)(q0 + q)     * HID + d]     = __float2half_rn(o[mt][nt][0] * ilo[nt]);
            g_Ctxh[base + (size_t)(q0 + q + 1) * HID + d]     = __float2half_rn(o[mt][nt][1] * ihi[nt]);
            g_Ctxh[base + (size_t)(q0 + q)     * HID + d + 8] = __float2half_rn(o[mt][nt][2] * ilo[nt]);
            g_Ctxh[base + (size_t)(q0 + q + 1) * HID + d + 8] = __float2half_rn(o[mt][nt][3] * ihi[nt]);
        }
    }
}

// ---------------------------------------------------------------------------
// Launch
// ---------------------------------------------------------------------------
extern "C" void kernel_launch(void* const* d_in, const int* in_sizes, int n_in,
                              void* d_out, int out_size)
{
    const float* x  = (const float*)d_in[0];
    const float* Wq = (const float*)d_in[1];
    const float* Wk = (const float*)d_in[2];
    const float* Wv = (const float*)d_in[3];
    const float* Wo = (const float*)d_in[4];
    float* out = (float*)d_out;

    float *pQ, *pK, *pV;
    __half *pXh, *pWh, *pCh;
    cudaGetSymbolAddress((void**)&pQ,  g_Q);
    cudaGetSymbolAddress((void**)&pK,  g_K);
    cudaGetSymbolAddress((void**)&pV,  g_V);
    cudaGetSymbolAddress((void**)&pXh, g_xh);
    cudaGetSymbolAddress((void**)&pWh, g_Wh);
    cudaGetSymbolAddress((void**)&pCh, g_Ctxh);

    const int WSZ = HID * HID;

    to_half_kernel<<<1024, 256>>>((const float4*)x,  (uint2*)pXh, MROWS * HID / 4);
    to_half_kernel<<<512, 256>>>((const float4*)Wq, (uint2*)(pWh + 0 * WSZ), WSZ / 4);
    to_half_kernel<<<512, 256>>>((const float4*)Wk, (uint2*)(pWh + 1 * WSZ), WSZ / 4);
    to_half_kernel<<<512, 256>>>((const float4*)Wv, (uint2*)(pWh + 2 * WSZ), WSZ / 4);
    to_half_kernel<<<512, 256>>>((const float4*)Wo, (uint2*)(pWh + 3 * WSZ), WSZ / 4);

    cudaFuncSetAttribute(gemm_f16_pipe<true>,
                         cudaFuncAttributeMaxDynamicSharedMemorySize, GEMM_SMEM);
    cudaFuncSetAttribute(gemm_f16_pipe<false>,
                         cudaFuncAttributeMaxDynamicSharedMemorySize, GEMM_SMEM);

    // Fused QKV projection: B = [Wq;Wk;Wv] (6144 x 2048), one launch
    gemm_f16_pipe<true><<<dim3(48, MROWS / 128), 256, GEMM_SMEM>>>(
        pXh, pWh, pQ, pK, pV, MROWS, HID, HID);

    rope_kernel<<<MROWS, 256>>>();
    vtrans_kernel<<<dim3(S_LEN / 64, 2 * NHEAD), 256>>>();

    cudaFuncSetAttribute(flash_f16,
                         cudaFuncAttributeMaxDynamicSharedMemorySize, FLASH_SMEM);
    flash_f16<<<dim3(S_LEN / 64, 2 * NHEAD), 256, FLASH_SMEM>>>();

    gemm_f16_pipe<false><<<dim3(16, MROWS / 128), 256, GEMM_SMEM>>>(
        pCh, pWh + 3 * WSZ, out, out, out, MROWS, HID, HID);
}

// round 10
// speedup vs baseline: 7.6914x; 1.1111x over previous
#include <cuda_runtime.h>
#include <cuda_fp16.h>
#include <math.h>

#define S_LEN 2048
#define HID   2048
#define NHEAD 16
#define HD    128
#define MROWS 4096
#define SCALE 0.08838834764831845f

// ---------------------------------------------------------------------------
// Global scratch
// ---------------------------------------------------------------------------
__device__ float  g_Q[MROWS * HID];
__device__ float  g_K[MROWS * HID];
__device__ float  g_V[MROWS * HID];
__device__ __half g_xh[MROWS * HID];
__device__ __half g_Wh[4 * HID * HID];    // Wq,Wk,Wv (6144x2048) + Wo
__device__ __half g_Qh[MROWS * HID];
__device__ __half g_Kh[MROWS * HID];
__device__ __half g_Vth[MROWS * HID];     // V^T per (b,h): [128 d][2048 s]
__device__ __half g_Ctxh[MROWS * HID];

// ---------------------------------------------------------------------------
// Helpers
// ---------------------------------------------------------------------------
__device__ __forceinline__ void mma_f16(float* c, const unsigned* a, const unsigned* b)
{
    asm volatile(
        "mma.sync.aligned.m16n8k16.row.col.f32.f16.f16.f32 "
        "{%0,%1,%2,%3}, {%4,%5,%6,%7}, {%8,%9}, {%0,%1,%2,%3};\n"
        : "+f"(c[0]), "+f"(c[1]), "+f"(c[2]), "+f"(c[3])
        : "r"(a[0]), "r"(a[1]), "r"(a[2]), "r"(a[3]),
          "r"(b[0]), "r"(b[1]));
}
__device__ __forceinline__ void cp_async16(unsigned saddr, const void* gaddr)
{
    asm volatile("cp.async.cg.shared.global [%0], [%1], 16;\n"
                 :: "r"(saddr), "l"(gaddr));
}
__device__ __forceinline__ void cp_commit()
{
    asm volatile("cp.async.commit_group;\n" ::: "memory");
}
__device__ __forceinline__ void cp_wait0()
{
    asm volatile("cp.async.wait_group 0;\n" ::: "memory");
}
__device__ __forceinline__ void cp_wait1()
{
    asm volatile("cp.async.wait_group 1;\n" ::: "memory");
}
__device__ __forceinline__ void cp_wait2()
{
    asm volatile("cp.async.wait_group 2;\n" ::: "memory");
}

// ---------------------------------------------------------------------------
// Fused fp32 -> fp16 convert: 6 regions x 1M float4 (x: 2, Wq/Wk/Wv/Wo: 1 each)
// ---------------------------------------------------------------------------
#define REG4 (1024 * 1024)

__global__ void to_half_all(const float4* __restrict__ x,
                            const float4* __restrict__ Wq,
                            const float4* __restrict__ Wk,
                            const float4* __restrict__ Wv,
                            const float4* __restrict__ Wo,
                            uint2* __restrict__ xh, uint2* __restrict__ Wh)
{
    const int region = blockIdx.y;
    const float4* src;
    uint2* dst;
    if (region == 0)      { src = x;        dst = xh; }
    else if (region == 1) { src = x + REG4; dst = xh + REG4; }
    else {
        src = (region == 2) ? Wq : (region == 3) ? Wk : (region == 4) ? Wv : Wo;
        dst = Wh + (size_t)(region - 2) * REG4;
    }
    for (int i = blockIdx.x * blockDim.x + threadIdx.x; i < REG4;
         i += gridDim.x * blockDim.x) {
        float4 v = src[i];
        __half2 h0 = __floats2half2_rn(v.x, v.y);
        __half2 h1 = __floats2half2_rn(v.z, v.w);
        uint2 u;
        u.x = *(unsigned*)&h0;
        u.y = *(unsigned*)&h1;
        dst[i] = u;
    }
}

// ---------------------------------------------------------------------------
// Pipelined FP16 GEMM (unchanged from R9). C(fp32) = A[M,K]*B[*,K]^T.
// ---------------------------------------------------------------------------
#define G3STG  3
#define G3MATW 4608
#define G3STGW 9216
#define GEMM_SMEM (G3STG * G3STGW * 4)   // 110592 B

#define ISSUE_STAGE(st, k0) do {                                              \
    const unsigned so_ = shb + (unsigned)(st) * (G3STGW * 4);                 \
    _Pragma("unroll")                                                         \
    for (int j_ = 0; j_ < 4; j_++) {                                          \
        const int c_ = tid + 256 * j_, r_ = c_ >> 3, kq_ = c_ & 7;            \
        cp_async16(so_ + r_ * 144 + kq_ * 16,                                 \
                   Abase + (size_t)r_ * K + (k0) + kq_ * 8);                  \
        cp_async16(so_ + G3MATW * 4 + r_ * 144 + kq_ * 16,                    \
                   Bbase + (size_t)r_ * K + (k0) + kq_ * 8);                  \
    } } while (0)

template<bool QKV>
__global__ __launch_bounds__(256, 2)
void gemm_f16_pipe(const __half* __restrict__ A, const __half* __restrict__ B,
                   float* __restrict__ C0, float* __restrict__ C1,
                   float* __restrict__ C2, int M, int Nout, int K)
{
    extern __shared__ unsigned sh[];

    const int tid  = threadIdx.x;
    const int lane = tid & 31;
    const int warp = tid >> 5;
    const int g    = lane >> 2;
    const int t    = lane & 3;
    const int wm   = (warp & 1) * 64;
    const int wn   = (warp >> 1) * 32;

    const __half* Abase = A + (size_t)blockIdx.y * 128 * K;
    const __half* Bbase = B + (size_t)blockIdx.x * 128 * K;
    const unsigned shb = (unsigned)__cvta_generic_to_shared(sh);

    const int ntiles = K / 64;

    float c[4][4][4];
#pragma unroll
    for (int i = 0; i < 4; i++)
#pragma unroll
        for (int j = 0; j < 4; j++)
#pragma unroll
            for (int q = 0; q < 4; q++) c[i][j][q] = 0.f;

    ISSUE_STAGE(0, 0);  cp_commit();
    ISSUE_STAGE(1, 64); cp_commit();

    for (int i = 0; i < ntiles; i++) {
        cp_wait1();
        __syncthreads();

        const unsigned* As = sh + (i % 3) * G3STGW;
        const unsigned* Bs = As + G3MATW;

        unsigned af[2][4][4], bf[2][4][2];

#pragma unroll
        for (int mt = 0; mt < 4; mt++) {
            const int m = wm + mt * 16 + g;
            af[0][mt][0] = As[m * 36 + t];
            af[0][mt][1] = As[(m + 8) * 36 + t];
            af[0][mt][2] = As[m * 36 + t + 4];
            af[0][mt][3] = As[(m + 8) * 36 + t + 4];
        }
#pragma unroll
        for (int nt = 0; nt < 4; nt++) {
            const int n = wn + nt * 8 + g;
            bf[0][nt][0] = Bs[n * 36 + t];
            bf[0][nt][1] = Bs[n * 36 + t + 4];
        }

        if (i + 2 < ntiles) ISSUE_STAGE((i + 2) % 3, (i + 2) * 64);
        cp_commit();

#pragma unroll
        for (int sub = 0; sub < 4; sub++) {
            const int cur = sub & 1;
            if (sub < 3) {
                const int nxt = cur ^ 1;
                const int ks = (sub + 1) * 8 + t;
#pragma unroll
                for (int mt = 0; mt < 4; mt++) {
                    const int m = wm + mt * 16 + g;
                    af[nxt][mt][0] = As[m * 36 + ks];
                    af[nxt][mt][1] = As[(m + 8) * 36 + ks];
                    af[nxt][mt][2] = As[m * 36 + ks + 4];
                    af[nxt][mt][3] = As[(m + 8) * 36 + ks + 4];
                }
#pragma unroll
                for (int nt = 0; nt < 4; nt++) {
                    const int n = wn + nt * 8 + g;
                    bf[nxt][nt][0] = Bs[n * 36 + ks];
                    bf[nxt][nt][1] = Bs[n * 36 + ks + 4];
                }
            }
#pragma unroll
            for (int mt = 0; mt < 4; mt++)
#pragma unroll
                for (int nt = 0; nt < 4; nt++)
                    mma_f16(c[mt][nt], af[cur][mt], bf[cur][nt]);
        }
    }

    float* Cb;
    size_t colbase;
    if (QKV) {
        const int seg = blockIdx.x >> 4;
        Cb = (seg == 0) ? C0 : (seg == 1) ? C1 : C2;
        colbase = (size_t)(blockIdx.x & 15) * 128;
    } else {
        Cb = C0;
        colbase = (size_t)blockIdx.x * 128;
    }

#pragma unroll
    for (int mt = 0; mt < 4; mt++) {
        const size_t row = (size_t)blockIdx.y * 128 + wm + mt * 16 + g;
#pragma unroll
        for (int nt = 0; nt < 4; nt++) {
            const size_t col = colbase + wn + nt * 8 + 2 * t;
            *(float2*)(Cb + row * Nout + col) =
                make_float2(c[mt][nt][0], c[mt][nt][1]);
            *(float2*)(Cb + (row + 8) * Nout + col) =
                make_float2(c[mt][nt][2], c[mt][nt][3]);
        }
    }
}

// ---------------------------------------------------------------------------
// RoPE: reads fp32 Q/K, writes fp16 Q/K
// ---------------------------------------------------------------------------
__global__ void rope_kernel()
{
    const int row = blockIdx.x;
    const int s   = row & (S_LEN - 1);
    for (int t = threadIdx.x; t < NHEAD * 64; t += 256) {
        const int h = t >> 6;
        const int i = t & 63;
        float inv = powf(10000.0f, -((float)(2 * i)) / 128.0f);
        float ang = (float)s * inv;
        float sn, cs;
        sincosf(ang, &sn, &cs);
        const int idx = row * HID + h * HD + i;
        float q1 = g_Q[idx], q2 = g_Q[idx + 64];
        g_Qh[idx]      = __float2half_rn(q1 * cs - q2 * sn);
        g_Qh[idx + 64] = __float2half_rn(q1 * sn + q2 * cs);
        float k1 = g_K[idx], k2 = g_K[idx + 64];
        g_Kh[idx]      = __float2half_rn(k1 * cs - k2 * sn);
        g_Kh[idx + 64] = __float2half_rn(k1 * sn + k2 * cs);
    }
}

// ---------------------------------------------------------------------------
// V transpose: fp32 V[b,s,h,d] -> fp16 g_Vth[(b*16+h)*128+d][s]
// ---------------------------------------------------------------------------
__global__ void vtrans_kernel()
{
    __shared__ __half buf[128][65];
    const int s0 = blockIdx.x * 64;
    const int bh = blockIdx.y;
    const int b  = bh >> 4, h = bh & 15;
    const int tid = threadIdx.x;
#pragma unroll 4
    for (int j = 0; j < 32; j++) {
        const int idx = tid + 256 * j;
        const int s = idx >> 7, d = idx & 127;
        buf[d][s] = __float2half_rn(
            g_V[(size_t)(b * S_LEN + s0 + s) * HID + h * HD + d]);
    }
    __syncthreads();
#pragma unroll 4
    for (int j = 0; j < 32; j++) {
        const int idx = tid + 256 * j;
        const int d = idx >> 6, s = idx & 63;
        g_Vth[((size_t)bh * HD + d) * S_LEN + s0 + s] = buf[d][s];
    }
}

// ---------------------------------------------------------------------------
// FP16 flash attention, occupancy 2. Bq = Bk = 64, D = 128, 256 threads.
// K double-buffered, V SINGLE-buffered (V(i+1) load hides under S/softmax(i+1)).
// Smem (words): Q 64x68 @0, K stages @4352/@8704, V 128x36 @13056,
//   Ss @17664, Ps @22016, rmax@24320 rsum@24384 alp@24448 -> 24512 w = 98048 B
// ---------------------------------------------------------------------------
#define QWS 68
#define KWS 68
#define VWS 36
#define PWS 36
#define SWS 68
#define WK0 4352
#define WV0 13056
#define WSS 17664
#define WPS 22016
#define FLASH_SMEM (24512 * 4)

__global__ __launch_bounds__(256, 2)
void flash_f16()
{
    extern __shared__ float sm[];
    unsigned* S32 = (unsigned*)sm;
    float* Ss   = sm + WSS;
    float* rmax = sm + 24320;
    float* rsum = sm + 24384;
    float* alp  = sm + 24448;

    const int tid  = threadIdx.x;
    const int lane = tid & 31;
    const int warp = tid >> 5;
    const int g    = lane >> 2;
    const int t    = lane & 3;
    const int q0   = blockIdx.x * 64;
    const int b    = blockIdx.y >> 4;
    const int h    = blockIdx.y & 15;
    const size_t base = (size_t)(b * S_LEN) * HID + (size_t)h * HD;
    const size_t vtb  = (size_t)blockIdx.y * HD * S_LEN;
    const unsigned shb = (unsigned)__cvta_generic_to_shared(sm);

    const int wm_s = (warp & 1) * 32;
    const int wn_s = (warp >> 1) * 16;
    const int wm_p = (warp & 3) * 32;
    const int wn_p = (warp >> 2) * 32;

    // prologue: P0 = {Q, K0, V0}, P1 = {K1}
#pragma unroll
    for (int j = 0; j < 4; j++) {
        const int c = tid + 256 * j;
        const int r = c >> 4, q = c & 15;
        cp_async16(shb + r * 272 + q * 16,
                   &g_Qh[base + (size_t)(q0 + r) * HID + q * 8]);
        cp_async16(shb + WK0 * 4 + r * 272 + q * 16,
                   &g_Kh[base + (size_t)r * HID + q * 8]);
        const int r2 = c >> 3, q2 = c & 7;
        cp_async16(shb + WV0 * 4 + r2 * 144 + q2 * 16,
                   &g_Vth[vtb + (size_t)r2 * S_LEN + q2 * 8]);
    }
    cp_commit();
#pragma unroll
    for (int j = 0; j < 4; j++) {
        const int c = tid + 256 * j;
        const int r = c >> 4, q = c & 15;
        cp_async16(shb + (WK0 + 4352) * 4 + r * 272 + q * 16,
                   &g_Kh[base + (size_t)(64 + r) * HID + q * 8]);
    }
    cp_commit();

    if (tid < 64) { rmax[tid] = -1e30f; rsum[tid] = 0.f; }

    float o[2][4][4];
#pragma unroll
    for (int mt = 0; mt < 2; mt++)
#pragma unroll
        for (int nt = 0; nt < 4; nt++)
#pragma unroll
            for (int j = 0; j < 4; j++) o[mt][nt][j] = 0.f;

    const int NT = S_LEN / 64;
    for (int it = 0; it < NT; it++) {
        const int s = it & 1;
        if (it == 0) cp_wait1(); else cp_wait2();
        __syncthreads();

        const unsigned kb = WK0 + s * 4352;

        // ---- S = Q K^T (8 x k16) ----
        float sacc[2][2][4];
#pragma unroll
        for (int mt = 0; mt < 2; mt++)
#pragma unroll
            for (int nt = 0; nt < 2; nt++)
#pragma unroll
                for (int j = 0; j < 4; j++) sacc[mt][nt][j] = 0.f;

#pragma unroll
        for (int kk = 0; kk < 8; kk++) {
            const int ko = kk * 8 + t;
            unsigned af[2][4], bf[2][2];
#pragma unroll
            for (int mt = 0; mt < 2; mt++) {
                const int m = wm_s + mt * 16 + g;
                af[mt][0] = S32[m * QWS + ko];
                af[mt][1] = S32[(m + 8) * QWS + ko];
                af[mt][2] = S32[m * QWS + ko + 4];
                af[mt][3] = S32[(m + 8) * QWS + ko + 4];
            }
#pragma unroll
            for (int nt = 0; nt < 2; nt++) {
                const int n = wn_s + nt * 8 + g;
                bf[nt][0] = S32[kb + n * KWS + ko];
                bf[nt][1] = S32[kb + n * KWS + ko + 4];
            }
#pragma unroll
            for (int mt = 0; mt < 2; mt++)
#pragma unroll
                for (int nt = 0; nt < 2; nt++)
                    mma_f16(sacc[mt][nt], af[mt], bf[nt]);
        }
#pragma unroll
        for (int mt = 0; mt < 2; mt++) {
            const int row = wm_s + mt * 16 + g;
#pragma unroll
            for (int nt = 0; nt < 2; nt++) {
                const int col = wn_s + nt * 8 + 2 * t;
                *(float2*)&Ss[row * SWS + col] =
                    make_float2(sacc[mt][nt][0] * SCALE, sacc[mt][nt][1] * SCALE);
                *(float2*)&Ss[(row + 8) * SWS + col] =
                    make_float2(sacc[mt][nt][2] * SCALE, sacc[mt][nt][3] * SCALE);
            }
        }
        __syncthreads();

        // ---- online softmax (4 threads/row), P written fp16 ----
        {
            const int row = tid >> 2;
            const int t4  = tid & 3;
            float* sr = Ss + row * SWS + t4 * 16;
            const float mold = rmax[row];
            float mx = mold;
#pragma unroll
            for (int j = 0; j < 16; j++) mx = fmaxf(mx, sr[j]);
            mx = fmaxf(mx, __shfl_xor_sync(0xffffffffu, mx, 1));
            mx = fmaxf(mx, __shfl_xor_sync(0xffffffffu, mx, 2));
            float p = 0.f;
            unsigned* pw = S32 + WPS + row * PWS + t4 * 8;
#pragma unroll
            for (int j = 0; j < 8; j++) {
                const float e0 = __expf(sr[2 * j]     - mx);
                const float e1 = __expf(sr[2 * j + 1] - mx);
                p += e0;
                p += e1;
                __half2 hp = __floats2half2_rn(e0, e1);
                pw[j] = *(unsigned*)&hp;
            }
            p += __shfl_xor_sync(0xffffffffu, p, 1);
            p += __shfl_xor_sync(0xffffffffu, p, 2);
            if (t4 == 0) {
                const float a = __expf(mold - mx);
                rsum[row] = rsum[row] * a + p;
                rmax[row] = mx;
                alp[row]  = a;
            }
        }
        cp_wait0();        // V(it) (and K(it+1)) arrived
        __syncthreads();

        // ---- alpha rescale + O^T += V^T P^T (4 x k16) ----
        float alo[4], ahi[4];
#pragma unroll
        for (int nt = 0; nt < 4; nt++) {
            const int q = wn_p + nt * 8 + 2 * t;
            alo[nt] = alp[q];
            ahi[nt] = alp[q + 1];
        }
#pragma unroll
        for (int mt = 0; mt < 2; mt++)
#pragma unroll
            for (int nt = 0; nt < 4; nt++) {
                o[mt][nt][0] *= alo[nt];
                o[mt][nt][1] *= ahi[nt];
                o[mt][nt][2] *= alo[nt];
                o[mt][nt][3] *= ahi[nt];
            }

#pragma unroll
        for (int kk = 0; kk < 4; kk++) {
            const int ko = kk * 8 + t;
            unsigned af[2][4], bf[4][2];
#pragma unroll
            for (int mt = 0; mt < 2; mt++) {
                const int m = wm_p + mt * 16 + g;
                af[mt][0] = S32[WV0 + m * VWS + ko];
                af[mt][1] = S32[WV0 + (m + 8) * VWS + ko];
                af[mt][2] = S32[WV0 + m * VWS + ko + 4];
                af[mt][3] = S32[WV0 + (m + 8) * VWS + ko + 4];
            }
#pragma unroll
            for (int nt = 0; nt < 4; nt++) {
                const int n = wn_p + nt * 8 + g;
                bf[nt][0] = S32[WPS + n * PWS + ko];
                bf[nt][1] = S32[WPS + n * PWS + ko + 4];
            }
#pragma unroll
            for (int mt = 0; mt < 2; mt++)
#pragma unroll
                for (int nt = 0; nt < 4; nt++)
                    mma_f16(o[mt][nt], af[mt], bf[nt]);
        }
        __syncthreads();   // all warps done with V(it) and K stage s

        // commit {K(it+2)} then {V(it+1)}
        if (it + 2 < NT) {
            const int kt2 = (it + 2) * 64;
#pragma unroll
            for (int j = 0; j < 4; j++) {
                const int c = tid + 256 * j;
                const int r = c >> 4, q = c & 15;
                cp_async16(shb + (WK0 + s * 4352) * 4 + r * 272 + q * 16,
                           &g_Kh[base + (size_t)(kt2 + r) * HID + q * 8]);
            }
        }
        cp_commit();
        if (it + 1 < NT) {
            const int kt1 = (it + 1) * 64;
#pragma unroll
            for (int j = 0; j < 4; j++) {
                const int c = tid + 256 * j;
                const int r2 = c >> 3, q2 = c & 7;
                cp_async16(shb + WV0 * 4 + r2 * 144 + q2 * 16,
                           &g_Vth[vtb + (size_t)r2 * S_LEN + kt1 + q2 * 8]);
            }
        }
        cp_commit();
    }
    __syncthreads();

    // ---- epilogue: Ctx (fp16) = O^T / rsum ----
    float ilo[4], ihi[4];
#pragma unroll
    for (int nt = 0; nt < 4; nt++) {
        const int q = wn_p + nt * 8 + 2 * t;
        ilo[nt] = 1.0f / rsum[q];
        ihi[nt] = 1.0f / rsum[q + 1];
    }
#pragma unroll
    for (int mt = 0; mt < 2; mt++) {
        const int d = wm_p + mt * 16 + g;
#pragma unroll
        for (int nt = 0; nt < 4; nt++) {
            const int q = wn_p + nt * 8 + 2 * t;
            g_Ctxh[base + (size_t)(q0 + q)     * HID + d]     = __float2half_rn(o[mt][nt][0] * ilo[nt]);
            g_Ctxh[base + (size_t)(q0 + q + 1) * HID + d]     = __float2half_rn(o[mt][nt][1] * ihi[nt]);
            g_Ctxh[base + (size_t)(q0 + q)     * HID + d + 8] = __float2half_rn(o[mt][nt][2] * ilo[nt]);
            g_Ctxh[base + (size_t)(q0 + q + 1) * HID + d + 8] = __float2half_rn(o[mt][nt][3] * ihi[nt]);
        }
    }
}

// ---------------------------------------------------------------------------
// Launch
// ---------------------------------------------------------------------------
extern "C" void kernel_launch(void* const* d_in, const int* in_sizes, int n_in,
                              void* d_out, int out_size)
{
    const float* x  = (const float*)d_in[0];
    const float* Wq = (const float*)d_in[1];
    const float* Wk = (const float*)d_in[2];
    const float* Wv = (const float*)d_in[3];
    const float* Wo = (const float*)d_in[4];
    float* out = (float*)d_out;

    float *pQ, *pK, *pV;
    __half *pXh, *pWh, *pCh;
    cudaGetSymbolAddress((void**)&pQ,  g_Q);
    cudaGetSymbolAddress((void**)&pK,  g_K);
    cudaGetSymbolAddress((void**)&pV,  g_V);
    cudaGetSymbolAddress((void**)&pXh, g_xh);
    cudaGetSymbolAddress((void**)&pWh, g_Wh);
    cudaGetSymbolAddress((void**)&pCh, g_Ctxh);

    const int WSZ = HID * HID;

    to_half_all<<<dim3(256, 6), 256>>>(
        (const float4*)x, (const float4*)Wq, (const float4*)Wk,
        (const float4*)Wv, (const float4*)Wo, (uint2*)pXh, (uint2*)pWh);

    cudaFuncSetAttribute(gemm_f16_pipe<true>,
                         cudaFuncAttributeMaxDynamicSharedMemorySize, GEMM_SMEM);
    cudaFuncSetAttribute(gemm_f16_pipe<false>,
                         cudaFuncAttributeMaxDynamicSharedMemorySize, GEMM_SMEM);

    gemm_f16_pipe<true><<<dim3(48, MROWS / 128), 256, GEMM_SMEM>>>(
        pXh, pWh, pQ, pK, pV, MROWS, HID, HID);

    rope_kernel<<<MROWS, 256>>>();
    vtrans_kernel<<<dim3(S_LEN / 64, 2 * NHEAD), 256>>>();

    cudaFuncSetAttribute(flash_f16,
                         cudaFuncAttributeMaxDynamicSharedMemorySize, FLASH_SMEM);
    flash_f16<<<dim3(S_LEN / 64, 2 * NHEAD), 256, FLASH_SMEM>>>();

    gemm_f16_pipe<false><<<dim3(16, MROWS / 128), 256, GEMM_SMEM>>>(
        pCh, pWh + 3 * WSZ, out, out, out, MROWS, HID, HID);
}

// round 11
// speedup vs baseline: 7.9358x; 1.0318x over previous
#include <cuda_runtime.h>
#include <cuda_fp16.h>
#include <math.h>

#define S_LEN 2048
#define HID   2048
#define NHEAD 16
#define HD    128
#define MROWS 4096
#define SCALE 0.08838834764831845f

// ---------------------------------------------------------------------------
// Global scratch
// ---------------------------------------------------------------------------
__device__ float  g_Q[MROWS * HID];
__device__ float  g_K[MROWS * HID];
__device__ float  g_V[MROWS * HID];
__device__ __half g_xh[MROWS * HID];
__device__ __half g_Wh[4 * HID * HID];    // Wq,Wk,Wv (6144x2048) + Wo
__device__ __half g_Qh[MROWS * HID];
__device__ __half g_Kh[MROWS * HID];
__device__ __half g_Vth[MROWS * HID];     // V^T per (b,h): [128 d][2048 s]
__device__ __half g_Ctxh[MROWS * HID];

// ---------------------------------------------------------------------------
// Helpers
// ---------------------------------------------------------------------------
__device__ __forceinline__ void mma_f16(float* c, const unsigned* a, const unsigned* b)
{
    asm volatile(
        "mma.sync.aligned.m16n8k16.row.col.f32.f16.f16.f32 "
        "{%0,%1,%2,%3}, {%4,%5,%6,%7}, {%8,%9}, {%0,%1,%2,%3};\n"
        : "+f"(c[0]), "+f"(c[1]), "+f"(c[2]), "+f"(c[3])
        : "r"(a[0]), "r"(a[1]), "r"(a[2]), "r"(a[3]),
          "r"(b[0]), "r"(b[1]));
}
__device__ __forceinline__ void ldsm_x4(unsigned* r, unsigned addr)
{
    asm volatile("ldmatrix.sync.aligned.m8n8.x4.shared.b16 {%0,%1,%2,%3}, [%4];"
                 : "=r"(r[0]), "=r"(r[1]), "=r"(r[2]), "=r"(r[3]) : "r"(addr));
}
__device__ __forceinline__ void cp_async16(unsigned saddr, const void* gaddr)
{
    asm volatile("cp.async.cg.shared.global [%0], [%1], 16;\n"
                 :: "r"(saddr), "l"(gaddr));
}
__device__ __forceinline__ void cp_commit()
{
    asm volatile("cp.async.commit_group;\n" ::: "memory");
}
__device__ __forceinline__ void cp_wait0()
{
    asm volatile("cp.async.wait_group 0;\n" ::: "memory");
}
__device__ __forceinline__ void cp_wait1()
{
    asm volatile("cp.async.wait_group 1;\n" ::: "memory");
}
__device__ __forceinline__ void cp_wait2()
{
    asm volatile("cp.async.wait_group 2;\n" ::: "memory");
}

// ---------------------------------------------------------------------------
// Fused fp32 -> fp16 convert: 6 regions x 1M float4
// ---------------------------------------------------------------------------
#define REG4 (1024 * 1024)

__global__ void to_half_all(const float4* __restrict__ x,
                            const float4* __restrict__ Wq,
                            const float4* __restrict__ Wk,
                            const float4* __restrict__ Wv,
                            const float4* __restrict__ Wo,
                            uint2* __restrict__ xh, uint2* __restrict__ Wh)
{
    const int region = blockIdx.y;
    const float4* src;
    uint2* dst;
    if (region == 0)      { src = x;        dst = xh; }
    else if (region == 1) { src = x + REG4; dst = xh + REG4; }
    else {
        src = (region == 2) ? Wq : (region == 3) ? Wk : (region == 4) ? Wv : Wo;
        dst = Wh + (size_t)(region - 2) * REG4;
    }
    for (int i = blockIdx.x * blockDim.x + threadIdx.x; i < REG4;
         i += gridDim.x * blockDim.x) {
        float4 v = src[i];
        __half2 h0 = __floats2half2_rn(v.x, v.y);
        __half2 h1 = __floats2half2_rn(v.z, v.w);
        uint2 u;
        u.x = *(unsigned*)&h0;
        u.y = *(unsigned*)&h1;
        dst[i] = u;
    }
}

// ---------------------------------------------------------------------------
// Pipelined FP16 GEMM with ldmatrix fragment loads.
// C(fp32) = A[M,K]*B[*,K]^T. CTA 128x128, K-tile 64, 3-stage cp.async,
// 256 threads, warp tile 64x32. Row stride 144 B (4 banks mod 32 ->
// conflict-free ldmatrix).
// ---------------------------------------------------------------------------
#define G3STG  3
#define G3MATW 4608
#define G3STGW 9216
#define GEMM_SMEM (G3STG * G3STGW * 4)   // 110592 B

#define ISSUE_STAGE(st, k0) do {                                              \
    const unsigned so_ = shb + (unsigned)(st) * (G3STGW * 4);                 \
    _Pragma("unroll")                                                         \
    for (int j_ = 0; j_ < 4; j_++) {                                          \
        const int c_ = tid + 256 * j_, r_ = c_ >> 3, kq_ = c_ & 7;            \
        cp_async16(so_ + r_ * 144 + kq_ * 16,                                 \
                   Abase + (size_t)r_ * K + (k0) + kq_ * 8);                  \
        cp_async16(so_ + G3MATW * 4 + r_ * 144 + kq_ * 16,                    \
                   Bbase + (size_t)r_ * K + (k0) + kq_ * 8);                  \
    } } while (0)

template<bool QKV>
__global__ __launch_bounds__(256, 2)
void gemm_f16_pipe(const __half* __restrict__ A, const __half* __restrict__ B,
                   float* __restrict__ C0, float* __restrict__ C1,
                   float* __restrict__ C2, int M, int Nout, int K)
{
    extern __shared__ unsigned sh[];

    const int tid  = threadIdx.x;
    const int lane = tid & 31;
    const int warp = tid >> 5;
    const int g    = lane >> 2;
    const int t    = lane & 3;
    const int wm   = (warp & 1) * 64;
    const int wn   = (warp >> 1) * 32;

    // ldmatrix lane address components
    const int aRow      = (lane & 7) + ((lane >> 3) & 1) * 8;
    const unsigned aCol = ((lane >> 4) & 1) * 16;
    const int bRow      = (lane & 7) + ((lane >> 4) & 1) * 8;
    const unsigned bCol = ((lane >> 3) & 1) * 16;

    const __half* Abase = A + (size_t)blockIdx.y * 128 * K;
    const __half* Bbase = B + (size_t)blockIdx.x * 128 * K;
    const unsigned shb = (unsigned)__cvta_generic_to_shared(sh);

    const int ntiles = K / 64;

    float c[4][4][4];
#pragma unroll
    for (int i = 0; i < 4; i++)
#pragma unroll
        for (int j = 0; j < 4; j++)
#pragma unroll
            for (int q = 0; q < 4; q++) c[i][j][q] = 0.f;

    ISSUE_STAGE(0, 0);  cp_commit();
    ISSUE_STAGE(1, 64); cp_commit();

    for (int i = 0; i < ntiles; i++) {
        cp_wait1();
        __syncthreads();

        const unsigned stA = shb + (unsigned)(i % 3) * (G3STGW * 4);
        const unsigned aBase = stA + (unsigned)(wm + aRow) * 144 + aCol;
        const unsigned bBase = stA + G3MATW * 4 + (unsigned)(wn + bRow) * 144 + bCol;

        unsigned af[2][4][4], bf[2][2][4];

        // sub0 fragments
#pragma unroll
        for (int mt = 0; mt < 4; mt++)
            ldsm_x4(af[0][mt], aBase + mt * (16 * 144));
#pragma unroll
        for (int pr = 0; pr < 2; pr++)
            ldsm_x4(bf[0][pr], bBase + pr * (16 * 144));

        if (i + 2 < ntiles) ISSUE_STAGE((i + 2) % 3, (i + 2) * 64);
        cp_commit();

#pragma unroll
        for (int sub = 0; sub < 4; sub++) {
            const int cur = sub & 1;
            if (sub < 3) {
                const int nxt = cur ^ 1;
                const unsigned ko = (sub + 1) * 32;
#pragma unroll
                for (int mt = 0; mt < 4; mt++)
                    ldsm_x4(af[nxt][mt], aBase + mt * (16 * 144) + ko);
#pragma unroll
                for (int pr = 0; pr < 2; pr++)
                    ldsm_x4(bf[nxt][pr], bBase + pr * (16 * 144) + ko);
            }
#pragma unroll
            for (int mt = 0; mt < 4; mt++)
#pragma unroll
                for (int nt = 0; nt < 4; nt++)
                    mma_f16(c[mt][nt], af[cur][mt], &bf[cur][nt >> 1][(nt & 1) * 2]);
        }
    }

    float* Cb;
    size_t colbase;
    if (QKV) {
        const int seg = blockIdx.x >> 4;
        Cb = (seg == 0) ? C0 : (seg == 1) ? C1 : C2;
        colbase = (size_t)(blockIdx.x & 15) * 128;
    } else {
        Cb = C0;
        colbase = (size_t)blockIdx.x * 128;
    }

#pragma unroll
    for (int mt = 0; mt < 4; mt++) {
        const size_t row = (size_t)blockIdx.y * 128 + wm + mt * 16 + g;
#pragma unroll
        for (int nt = 0; nt < 4; nt++) {
            const size_t col = colbase + wn + nt * 8 + 2 * t;
            *(float2*)(Cb + row * Nout + col) =
                make_float2(c[mt][nt][0], c[mt][nt][1]);
            *(float2*)(Cb + (row + 8) * Nout + col) =
                make_float2(c[mt][nt][2], c[mt][nt][3]);
        }
    }
}

// ---------------------------------------------------------------------------
// RoPE: reads fp32 Q/K, writes fp16 Q/K
// ---------------------------------------------------------------------------
__global__ void rope_kernel()
{
    const int row = blockIdx.x;
    const int s   = row & (S_LEN - 1);
    for (int t = threadIdx.x; t < NHEAD * 64; t += 256) {
        const int h = t >> 6;
        const int i = t & 63;
        float inv = powf(10000.0f, -((float)(2 * i)) / 128.0f);
        float ang = (float)s * inv;
        float sn, cs;
        sincosf(ang, &sn, &cs);
        const int idx = row * HID + h * HD + i;
        float q1 = g_Q[idx], q2 = g_Q[idx + 64];
        g_Qh[idx]      = __float2half_rn(q1 * cs - q2 * sn);
        g_Qh[idx + 64] = __float2half_rn(q1 * sn + q2 * cs);
        float k1 = g_K[idx], k2 = g_K[idx + 64];
        g_Kh[idx]      = __float2half_rn(k1 * cs - k2 * sn);
        g_Kh[idx + 64] = __float2half_rn(k1 * sn + k2 * cs);
    }
}

// ---------------------------------------------------------------------------
// V transpose: fp32 V[b,s,h,d] -> fp16 g_Vth[(b*16+h)*128+d][s]
// ---------------------------------------------------------------------------
__global__ void vtrans_kernel()
{
    __shared__ __half buf[128][65];
    const int s0 = blockIdx.x * 64;
    const int bh = blockIdx.y;
    const int b  = bh >> 4, h = bh & 15;
    const int tid = threadIdx.x;
#pragma unroll 4
    for (int j = 0; j < 32; j++) {
        const int idx = tid + 256 * j;
        const int s = idx >> 7, d = idx & 127;
        buf[d][s] = __float2half_rn(
            g_V[(size_t)(b * S_LEN + s0 + s) * HID + h * HD + d]);
    }
    __syncthreads();
#pragma unroll 4
    for (int j = 0; j < 32; j++) {
        const int idx = tid + 256 * j;
        const int d = idx >> 6, s = idx & 63;
        g_Vth[((size_t)bh * HD + d) * S_LEN + s0 + s] = buf[d][s];
    }
}

// ---------------------------------------------------------------------------
// FP16 flash attention with ldmatrix fragment loads, occupancy 2.
// Smem (words): Q 64x68 @0, K stages @4352/@8704, V 128x36 @13056,
//   Ss @17664, Ps @22016, rmax@24320 rsum@24384 alp@24448 -> 24512 w
// ---------------------------------------------------------------------------
#define QWS 68
#define KWS 68
#define VWS 36
#define PWS 36
#define SWS 68
#define WK0 4352
#define WV0 13056
#define WSS 17664
#define WPS 22016
#define FLASH_SMEM (24512 * 4)

__global__ __launch_bounds__(256, 2)
void flash_f16()
{
    extern __shared__ float sm[];
    unsigned* S32 = (unsigned*)sm;
    float* Ss   = sm + WSS;
    float* rmax = sm + 24320;
    float* rsum = sm + 24384;
    float* alp  = sm + 24448;

    const int tid  = threadIdx.x;
    const int lane = tid & 31;
    const int warp = tid >> 5;
    const int g    = lane >> 2;
    const int t    = lane & 3;
    const int q0   = blockIdx.x * 64;
    const int b    = blockIdx.y >> 4;
    const int h    = blockIdx.y & 15;
    const size_t base = (size_t)(b * S_LEN) * HID + (size_t)h * HD;
    const size_t vtb  = (size_t)blockIdx.y * HD * S_LEN;
    const unsigned shb = (unsigned)__cvta_generic_to_shared(sm);

    const int wm_s = (warp & 1) * 32;
    const int wn_s = (warp >> 1) * 16;
    const int wm_p = (warp & 3) * 32;
    const int wn_p = (warp >> 2) * 32;

    const int aRow      = (lane & 7) + ((lane >> 3) & 1) * 8;
    const unsigned aCol = ((lane >> 4) & 1) * 16;
    const int bRow      = (lane & 7) + ((lane >> 4) & 1) * 8;
    const unsigned bCol = ((lane >> 3) & 1) * 16;

    // prologue: P0 = {Q, K0, V0}, P1 = {K1}
#pragma unroll
    for (int j = 0; j < 4; j++) {
        const int c = tid + 256 * j;
        const int r = c >> 4, q = c & 15;
        cp_async16(shb + r * 272 + q * 16,
                   &g_Qh[base + (size_t)(q0 + r) * HID + q * 8]);
        cp_async16(shb + WK0 * 4 + r * 272 + q * 16,
                   &g_Kh[base + (size_t)r * HID + q * 8]);
        const int r2 = c >> 3, q2 = c & 7;
        cp_async16(shb + WV0 * 4 + r2 * 144 + q2 * 16,
                   &g_Vth[vtb + (size_t)r2 * S_LEN + q2 * 8]);
    }
    cp_commit();
#pragma unroll
    for (int j = 0; j < 4; j++) {
        const int c = tid + 256 * j;
        const int r = c >> 4, q = c & 15;
        cp_async16(shb + (WK0 + 4352) * 4 + r * 272 + q * 16,
                   &g_Kh[base + (size_t)(64 + r) * HID + q * 8]);
    }
    cp_commit();

    if (tid < 64) { rmax[tid] = -1e30f; rsum[tid] = 0.f; }

    float o[2][4][4];
#pragma unroll
    for (int mt = 0; mt < 2; mt++)
#pragma unroll
        for (int nt = 0; nt < 4; nt++)
#pragma unroll
            for (int j = 0; j < 4; j++) o[mt][nt][j] = 0.f;

    const unsigned qB = shb + (unsigned)(wm_s + aRow) * 272 + aCol;
    const unsigned vB = shb + WV0 * 4 + (unsigned)(wm_p + aRow) * 144 + aCol;
    const unsigned pB = shb + WPS * 4 + (unsigned)(wn_p + bRow) * 144 + bCol;

    const int NT = S_LEN / 64;
    for (int it = 0; it < NT; it++) {
        const int s = it & 1;
        if (it == 0) cp_wait1(); else cp_wait2();
        __syncthreads();

        const unsigned kB = shb + (WK0 + s * 4352) * 4
                          + (unsigned)(wn_s + bRow) * 272 + bCol;

        // ---- S = Q K^T (8 x k16, ldmatrix double-buffered) ----
        float sacc[2][2][4];
#pragma unroll
        for (int mt = 0; mt < 2; mt++)
#pragma unroll
            for (int nt = 0; nt < 2; nt++)
#pragma unroll
                for (int j = 0; j < 4; j++) sacc[mt][nt][j] = 0.f;

        unsigned afS[2][2][4], bfS[2][4];
        ldsm_x4(afS[0][0], qB);
        ldsm_x4(afS[0][1], qB + 16 * 272);
        ldsm_x4(bfS[0], kB);
#pragma unroll
        for (int kk = 0; kk < 8; kk++) {
            const int cur = kk & 1;
            if (kk < 7) {
                const int nxt = cur ^ 1;
                const unsigned ko = (kk + 1) * 32;
                ldsm_x4(afS[nxt][0], qB + ko);
                ldsm_x4(afS[nxt][1], qB + 16 * 272 + ko);
                ldsm_x4(bfS[nxt], kB + ko);
            }
#pragma unroll
            for (int mt = 0; mt < 2; mt++)
#pragma unroll
                for (int nt = 0; nt < 2; nt++)
                    mma_f16(sacc[mt][nt], afS[cur][mt], &bfS[cur][nt * 2]);
        }
#pragma unroll
        for (int mt = 0; mt < 2; mt++) {
            const int row = wm_s + mt * 16 + g;
#pragma unroll
            for (int nt = 0; nt < 2; nt++) {
                const int col = wn_s + nt * 8 + 2 * t;
                *(float2*)&Ss[row * SWS + col] =
                    make_float2(sacc[mt][nt][0] * SCALE, sacc[mt][nt][1] * SCALE);
                *(float2*)&Ss[(row + 8) * SWS + col] =
                    make_float2(sacc[mt][nt][2] * SCALE, sacc[mt][nt][3] * SCALE);
            }
        }
        __syncthreads();

        // ---- online softmax (4 threads/row), P written fp16 ----
        {
            const int row = tid >> 2;
            const int t4  = tid & 3;
            float* sr = Ss + row * SWS + t4 * 16;
            const float mold = rmax[row];
            float mx = mold;
#pragma unroll
            for (int j = 0; j < 16; j++) mx = fmaxf(mx, sr[j]);
            mx = fmaxf(mx, __shfl_xor_sync(0xffffffffu, mx, 1));
            mx = fmaxf(mx, __shfl_xor_sync(0xffffffffu, mx, 2));
            float p = 0.f;
            unsigned* pw = S32 + WPS + row * PWS + t4 * 8;
#pragma unroll
            for (int j = 0; j < 8; j++) {
                const float e0 = __expf(sr[2 * j]     - mx);
                const float e1 = __expf(sr[2 * j + 1] - mx);
                p += e0;
                p += e1;
                __half2 hp = __floats2half2_rn(e0, e1);
                pw[j] = *(unsigned*)&hp;
            }
            p += __shfl_xor_sync(0xffffffffu, p, 1);
            p += __shfl_xor_sync(0xffffffffu, p, 2);
            if (t4 == 0) {
                const float a = __expf(mold - mx);
                rsum[row] = rsum[row] * a + p;
                rmax[row] = mx;
                alp[row]  = a;
            }
        }
        cp_wait0();        // V(it) (and K(it+1)) arrived
        __syncthreads();

        // ---- alpha rescale + O^T += V^T P^T (4 x k16, ldmatrix) ----
        float alo[4], ahi[4];
#pragma unroll
        for (int nt = 0; nt < 4; nt++) {
            const int q = wn_p + nt * 8 + 2 * t;
            alo[nt] = alp[q];
            ahi[nt] = alp[q + 1];
        }
#pragma unroll
        for (int mt = 0; mt < 2; mt++)
#pragma unroll
            for (int nt = 0; nt < 4; nt++) {
                o[mt][nt][0] *= alo[nt];
                o[mt][nt][1] *= ahi[nt];
                o[mt][nt][2] *= alo[nt];
                o[mt][nt][3] *= ahi[nt];
            }

        unsigned afP[2][2][4], bfP[2][2][4];
        ldsm_x4(afP[0][0], vB);
        ldsm_x4(afP[0][1], vB + 16 * 144);
        ldsm_x4(bfP[0][0], pB);
        ldsm_x4(bfP[0][1], pB + 16 * 144);
#pragma unroll
        for (int kk = 0; kk < 4; kk++) {
            const int cur = kk & 1;
            if (kk < 3) {
                const int nxt = cur ^ 1;
                const unsigned ko = (kk + 1) * 32;
                ldsm_x4(afP[nxt][0], vB + ko);
                ldsm_x4(afP[nxt][1], vB + 16 * 144 + ko);
                ldsm_x4(bfP[nxt][0], pB + ko);
                ldsm_x4(bfP[nxt][1], pB + 16 * 144 + ko);
            }
#pragma unroll
            for (int mt = 0; mt < 2; mt++)
#pragma unroll
                for (int nt = 0; nt < 4; nt++)
                    mma_f16(o[mt][nt], afP[cur][mt], &bfP[cur][nt >> 1][(nt & 1) * 2]);
        }
        __syncthreads();   // all warps done with V(it) and K stage s

        // commit {K(it+2)} then {V(it+1)}
        if (it + 2 < NT) {
            const int kt2 = (it + 2) * 64;
#pragma unroll
            for (int j = 0; j < 4; j++) {
                const int c = tid + 256 * j;
                const int r = c >> 4, q = c & 15;
                cp_async16(shb + (WK0 + s * 4352) * 4 + r * 272 + q * 16,
                           &g_Kh[base + (size_t)(kt2 + r) * HID + q * 8]);
            }
        }
        cp_commit();
        if (it + 1 < NT) {
            const int kt1 = (it + 1) * 64;
#pragma unroll
            for (int j = 0; j < 4; j++) {
                const int c = tid + 256 * j;
                const int r2 = c >> 3, q2 = c & 7;
                cp_async16(shb + WV0 * 4 + r2 * 144 + q2 * 16,
                           &g_Vth[vtb + (size_t)r2 * S_LEN + kt1 + q2 * 8]);
            }
        }
        cp_commit();
    }
    __syncthreads();

    // ---- epilogue: Ctx (fp16) = O^T / rsum ----
    float ilo[4], ihi[4];
#pragma unroll
    for (int nt = 0; nt < 4; nt++) {
        const int q = wn_p + nt * 8 + 2 * t;
        ilo[nt] = 1.0f / rsum[q];
        ihi[nt] = 1.0f / rsum[q + 1];
    }
#pragma unroll
    for (int mt = 0; mt < 2; mt++) {
        const int d = wm_p + mt * 16 + g;
#pragma unroll
        for (int nt = 0; nt < 4; nt++) {
            const int q = wn_p + nt * 8 + 2 * t;
            g_Ctxh[base + (size_t)(q0 + q)     * HID + d]     = __float2half_rn(o[mt][nt][0] * ilo[nt]);
            g_Ctxh[base + (size_t)(q0 + q + 1) * HID + d]     = __float2half_rn(o[mt][nt][1] * ihi[nt]);
            g_Ctxh[base + (size_t)(q0 + q)     * HID + d + 8] = __float2half_rn(o[mt][nt][2] * ilo[nt]);
            g_Ctxh[base + (size_t)(q0 + q + 1) * HID + d + 8] = __float2half_rn(o[mt][nt][3] * ihi[nt]);
        }
    }
}

// ---------------------------------------------------------------------------
// Launch
// ---------------------------------------------------------------------------
extern "C" void kernel_launch(void* const* d_in, const int* in_sizes, int n_in,
                              void* d_out, int out_size)
{
    const float* x  = (const float*)d_in[0];
    const float* Wq = (const float*)d_in[1];
    const float* Wk = (const float*)d_in[2];
    const float* Wv = (const float*)d_in[3];
    const float* Wo = (const float*)d_in[4];
    float* out = (float*)d_out;

    float *pQ, *pK, *pV;
    __half *pXh, *pWh, *pCh;
    cudaGetSymbolAddress((void**)&pQ,  g_Q);
    cudaGetSymbolAddress((void**)&pK,  g_K);
    cudaGetSymbolAddress((void**)&pV,  g_V);
    cudaGetSymbolAddress((void**)&pXh, g_xh);
    cudaGetSymbolAddress((void**)&pWh, g_Wh);
    cudaGetSymbolAddress((void**)&pCh, g_Ctxh);

    const int WSZ = HID * HID;

    to_half_all<<<dim3(256, 6), 256>>>(
        (const float4*)x, (const float4*)Wq, (const float4*)Wk,
        (const float4*)Wv, (const float4*)Wo, (uint2*)pXh, (uint2*)pWh);

    cudaFuncSetAttribute(gemm_f16_pipe<true>,
                         cudaFuncAttributeMaxDynamicSharedMemorySize, GEMM_SMEM);
    cudaFuncSetAttribute(gemm_f16_pipe<false>,
                         cudaFuncAttributeMaxDynamicSharedMemorySize, GEMM_SMEM);

    gemm_f16_pipe<true><<<dim3(48, MROWS / 128), 256, GEMM_SMEM>>>(
        pXh, pWh, pQ, pK, pV, MROWS, HID, HID);

    rope_kernel<<<MROWS, 256>>>();
    vtrans_kernel<<<dim3(S_LEN / 64, 2 * NHEAD), 256>>>();

    cudaFuncSetAttribute(flash_f16,
                         cudaFuncAttributeMaxDynamicSharedMemorySize, FLASH_SMEM);
    flash_f16<<<dim3(S_LEN / 64, 2 * NHEAD), 256, FLASH_SMEM>>>();

    gemm_f16_pipe<false><<<dim3(16, MROWS / 128), 256, GEMM_SMEM>>>(
        pCh, pWh + 3 * WSZ, out, out, out, MROWS, HID, HID);
}